// round 3
// baseline (speedup 1.0000x reference)
#include <cuda_runtime.h>
#include <math.h>
#include <stdint.h>

// Problem constants (fixed by setup_inputs)
#define V_  100000
#define E_  256
#define H_  256
#define B_  256
#define S_  10
#define TC_ 20
#define TS_ 50
#define BC_ (B_ * S_)   // 2560
#define H3_ (3 * H_)    // 768

// ---------------- scratch (static device globals; no allocation) --------------
__device__ float g_gi_c[(size_t)BC_ * TC_ * H3_];
__device__ float g_gi_s[(size_t)B_ * TS_ * H3_];
__device__ float g_seq_cate[BC_ * H_];
__device__ float g_out_short[B_ * H_];
__device__ float g_sum_cate[B_ * H_];
__device__ float g_fc_out[B_ * H_];
__device__ int   g_order_c[BC_];
__device__ int   g_order_s[B_];

// ---------------- f32x2 packed-FMA helpers ------------------------------------
#define FMA2(acc, a, b) asm("fma.rn.f32x2 %0, %1, %2, %0;" : "+l"(acc) : "l"(a), "l"(b))

__device__ __forceinline__ unsigned long long splat2(float x) {
    unsigned long long r;
    asm("mov.b64 %0, {%1, %1};" : "=l"(r) : "f"(x));
    return r;
}
__device__ __forceinline__ float2 unpack2(unsigned long long v) {
    float2 f;
    asm("mov.b64 {%0, %1}, %2;" : "=f"(f.x), "=f"(f.y) : "l"(v));
    return f;
}
__device__ __forceinline__ float fast_sigmoid(float x) {
    return 1.f / (1.f + __expf(-x));
}
__device__ __forceinline__ float fast_tanh(float x) {
    float ax = fabsf(x);
    float e = __expf(-2.f * ax);
    float t = __fdividef(1.f - e, 1.f + e);
    return copysignf(t, x);
}

// ---------------- counting sort (desc by length) ------------------------------
__global__ void sort_kernel(const int* __restrict__ slen_c, int* __restrict__ order_c,
                            const int* __restrict__ slen_s, int* __restrict__ order_s)
{
    __shared__ int hist[64];
    __shared__ int base[64];
    const int tid = threadIdx.x;
    // --- category rows (2560 keys in [0,20)) ---
    if (tid < 64) hist[tid] = 0;
    __syncthreads();
    for (int i = tid; i < BC_; i += 256) atomicAdd(&hist[slen_c[i]], 1);
    __syncthreads();
    if (tid == 0) {
        int run = 0;
        for (int k = 63; k >= 0; k--) { base[k] = run; run += hist[k]; }
    }
    __syncthreads();
    for (int i = tid; i < BC_; i += 256) {
        int pos = atomicAdd(&base[slen_c[i]], 1);
        order_c[pos] = i;
    }
    __syncthreads();
    // --- short rows (256 keys in [0,50)) ---
    if (tid < 64) hist[tid] = 0;
    __syncthreads();
    for (int i = tid; i < B_; i += 256) atomicAdd(&hist[slen_s[i]], 1);
    __syncthreads();
    if (tid == 0) {
        int run = 0;
        for (int k = 63; k >= 0; k--) { base[k] = run; run += hist[k]; }
    }
    __syncthreads();
    for (int i = tid; i < B_; i += 256) {
        int pos = atomicAdd(&base[slen_s[i]], 1);
        order_s[pos] = i;
    }
}

// ---------------- NT GEMM (FFMA2): C[m,n]=sum_k Arow(m)[k]*Bm[n,k] (+bias) ----
// Arow(m) = A + (idx ? idx[m] : m) * K   (fused embedding gather)
// 128x128x8 tiles, 256 threads, 8x8 per thread. M must be a multiple of 128.
__global__ void __launch_bounds__(256) gemm_nt_128(
    const float* __restrict__ A, const int* __restrict__ idx,
    const float* __restrict__ Bm, const float* __restrict__ bias,
    float* __restrict__ C, int M, int N, int K)
{
    __shared__ __align__(16) float As[8][128];
    __shared__ __align__(16) float Bs[8][128];
    const int tid = threadIdx.x;
    const int bm = blockIdx.x * 128;
    const int bn = blockIdx.y * 128;
    const int lr = tid >> 1;
    const int lk = (tid & 1) * 4;
    const int tx = tid & 15;
    const int ty = tid >> 4;
    const int tm0 = ty * 8, tn0 = tx * 8;

    const int am = bm + lr;
    const float* arow = A + (size_t)(idx ? idx[am] : am) * K;
    const int brow = bn + lr;
    const float* brp = Bm + (size_t)brow * K;
    const bool bvalid = (brow < N);

    unsigned long long accP[8][4];
#pragma unroll
    for (int i = 0; i < 8; i++)
#pragma unroll
        for (int j = 0; j < 4; j++) accP[i][j] = 0ull;

    for (int k0 = 0; k0 < K; k0 += 8) {
        float4 av = *(const float4*)(arow + k0 + lk);
        float4 bv = bvalid ? *(const float4*)(brp + k0 + lk)
                           : make_float4(0.f, 0.f, 0.f, 0.f);
        As[lk + 0][lr] = av.x; As[lk + 1][lr] = av.y;
        As[lk + 2][lr] = av.z; As[lk + 3][lr] = av.w;
        Bs[lk + 0][lr] = bv.x; Bs[lk + 1][lr] = bv.y;
        Bs[lk + 2][lr] = bv.z; Bs[lk + 3][lr] = bv.w;
        __syncthreads();
#pragma unroll
        for (int k = 0; k < 8; k++) {
            float4 a0 = *(const float4*)&As[k][tm0];
            float4 a1 = *(const float4*)&As[k][tm0 + 4];
            const ulonglong2* bp2 = (const ulonglong2*)&Bs[k][tn0];
            ulonglong2 b01 = bp2[0];
            ulonglong2 b23 = bp2[1];
            unsigned long long bp[4] = {b01.x, b01.y, b23.x, b23.y};
            float am8[8] = {a0.x, a0.y, a0.z, a0.w, a1.x, a1.y, a1.z, a1.w};
#pragma unroll
            for (int i = 0; i < 8; i++) {
                unsigned long long as2 = splat2(am8[i]);
#pragma unroll
                for (int j = 0; j < 4; j++) FMA2(accP[i][j], as2, bp[j]);
            }
        }
        __syncthreads();
    }

#pragma unroll
    for (int i = 0; i < 8; i++) {
        const int m = bm + tm0 + i;
        float* crow = C + (size_t)m * N;
#pragma unroll
        for (int j = 0; j < 4; j++) {
            float2 v = unpack2(accP[i][j]);
            const int n0 = bn + tn0 + 2 * j;
            if (n0 < N)     crow[n0]     = v.x + (bias ? bias[n0]     : 0.f);
            if (n0 + 1 < N) crow[n0 + 1] = v.y + (bias ? bias[n0 + 1] : 0.f);
        }
    }
}

// ---------------- persistent row-parallel GRU ---------------------------------
// Block owns R rows (length-sorted desc, contiguous chunk of order[]). Whole
// t-loop runs in-kernel; h lives in smem (hs[j][r] layout). Each step: Whh is
// streamed through a smem k-tile (L2-resident), gh = h@Whh^T via FFMA2 with
// rows packed in pairs; epilogue does gate math for thread's column j = tid.
// Rows die after t > slen[row]; block exits after its max slen.
template<int R, int T>
__global__ void __launch_bounds__(256, 1) gru_persist(
    const float* __restrict__ Whh, const float* __restrict__ bhh,
    const float* __restrict__ gi,  const int* __restrict__ order,
    const int* __restrict__ slen,  const float* __restrict__ mask,
    float* __restrict__ gathered)
{
    constexpr int PAIRS = R / 2;
    constexpr int HS = R + 2;            // even stride: LDS.64-aligned
    __shared__ __align__(16) float Wt[8][H3_];     // 24 KB k-tile of Whh (transposed)
    __shared__ __align__(16) float hs[H_][HS];     // h state, hs[j][r] = h[r][j]
    __shared__ int rows_s[R];
    __shared__ int sl_s[R];

    const int tid = threadIdx.x;
    if (tid < R) {
        int rr = order[blockIdx.x * R + tid];
        rows_s[tid] = rr;
        sl_s[tid] = slen[rr];
    }
    for (int i = tid; i < H_ * HS; i += 256) ((float*)hs)[i] = 0.f;
    const float br = bhh[tid], bz = bhh[H_ + tid], bn = bhh[2 * H_ + tid];
    __syncthreads();
    const int tmax = sl_s[0];            // rows sorted desc -> max is first

    for (int t = 0; t <= tmax; t++) {
        int na = 0;
#pragma unroll
        for (int i = 0; i < R; i++) na += (sl_s[i] >= t) ? 1 : 0;
        const int pairs = (na + 1) >> 1;

        unsigned long long accR[PAIRS], accZ[PAIRS], accN[PAIRS];
#pragma unroll
        for (int p = 0; p < PAIRS; p++) { accR[p] = 0ull; accZ[p] = 0ull; accN[p] = 0ull; }

        if (t > 0) {
            for (int kt = 0; kt < 32; kt++) {     // 32 tiles x 8 k
                __syncthreads();
                // stage Whh[:, kt*8 : kt*8+8] transposed into Wt[kk][gate_row]
#pragma unroll
                for (int g = 0; g < 3; g++) {
                    const int gr = g * H_ + tid;
                    const float4* wp = (const float4*)(Whh + (size_t)gr * H_ + kt * 8);
                    float4 v0 = wp[0];
                    float4 v1 = wp[1];
                    Wt[0][gr] = v0.x; Wt[1][gr] = v0.y;
                    Wt[2][gr] = v0.z; Wt[3][gr] = v0.w;
                    Wt[4][gr] = v1.x; Wt[5][gr] = v1.y;
                    Wt[6][gr] = v1.z; Wt[7][gr] = v1.w;
                }
                __syncthreads();
#pragma unroll
                for (int kk = 0; kk < 8; kk++) {
                    const int k = kt * 8 + kk;
                    unsigned long long wr2 = splat2(Wt[kk][tid]);
                    unsigned long long wz2 = splat2(Wt[kk][H_ + tid]);
                    unsigned long long wn2 = splat2(Wt[kk][2 * H_ + tid]);
                    const float* hk = &hs[k][0];
#pragma unroll
                    for (int p = 0; p < PAIRS; p++) {
                        if (p < pairs) {
                            unsigned long long h2 = *(const unsigned long long*)(hk + 2 * p);
                            FMA2(accR[p], h2, wr2);
                            FMA2(accZ[p], h2, wz2);
                            FMA2(accN[p], h2, wn2);
                        }
                    }
                }
            }
        }
        __syncthreads();   // all reads of hs complete before epilogue rewrites it

        // epilogue: gates + h update + length-gather (thread owns column j=tid)
#pragma unroll
        for (int p = 0; p < PAIRS; p++) {
            float2 fr = unpack2(accR[p]);
            float2 fz = unpack2(accZ[p]);
            float2 fn = unpack2(accN[p]);
#pragma unroll
            for (int hh = 0; hh < 2; hh++) {
                const int i = 2 * p + hh;
                if (i < na) {
                    const int row = rows_s[i];
                    const size_t gbase = ((size_t)row * T + t) * H3_ + tid;
                    const float g_r = gi[gbase];
                    const float g_z = gi[gbase + H_];
                    const float g_n = gi[gbase + 2 * H_];
                    const float ar = hh ? fr.y : fr.x;
                    const float az = hh ? fz.y : fz.x;
                    const float an = hh ? fn.y : fn.x;
                    const float hold = hs[tid][i];
                    const float r = fast_sigmoid(g_r + ar + br);
                    const float z = fast_sigmoid(g_z + az + bz);
                    const float n = fast_tanh(g_n + r * (an + bn));
                    const float hnew = (1.f - z) * n + z * hold;
                    hs[tid][i] = hnew;
                    if (sl_s[i] == t)
                        gathered[(size_t)row * H_ + tid] =
                            hnew * mask[(size_t)row * T + t];
                }
            }
        }
        __syncthreads();   // new hs visible before next step's k-loop
    }
}

// ---------------- attention: masked softmax of out_short over seq_cate -------
__global__ void attention_kernel(const float* __restrict__ seq_cate,
                                 const float* __restrict__ out_short,
                                 const float* __restrict__ mask_seq,
                                 float* __restrict__ sum_cate)
{
    const int b = blockIdx.x;
    const int j = threadIdx.x;  // 256 = H
    __shared__ float red[8];
    __shared__ float w[S_];
    const float os = out_short[(size_t)b * H_ + j];
    float sc[S_];
#pragma unroll
    for (int s = 0; s < S_; s++)
        sc[s] = seq_cate[(size_t)(b * S_ + s) * H_ + j];

    for (int s = 0; s < S_; s++) {
        float v = sc[s] * os;
#pragma unroll
        for (int off = 16; off; off >>= 1) v += __shfl_xor_sync(0xffffffffu, v, off);
        if ((j & 31) == 0) red[j >> 5] = v;
        __syncthreads();
        if (j == 0) {
            float x = 0.f;
#pragma unroll
            for (int q = 0; q < 8; q++) x += red[q];
            w[s] = x;
        }
        __syncthreads();
    }
    if (j == 0) {
        float mx = w[0];
        for (int s = 1; s < S_; s++) mx = fmaxf(mx, w[s]);
        float e[S_];
        float sum = 0.f;
        for (int s = 0; s < S_; s++) { e[s] = expf(w[s] - mx); sum += e[s]; }
        float s2 = 0.f;
        for (int s = 0; s < S_; s++) {
            e[s] = (e[s] / sum) * mask_seq[(size_t)b * S_ + s];
            s2 += e[s];
        }
        for (int s = 0; s < S_; s++) w[s] = e[s] / s2;
    }
    __syncthreads();
    float acc = 0.f;
#pragma unroll
    for (int s = 0; s < S_; s++) acc += w[s] * sc[s];
    sum_cate[(size_t)b * H_ + j] = acc;
}

// ---------------- FC: fc_out[b,i] = [sum_cate|out_short][b,:] . fc_W[i,:] ----
__global__ void fc_kernel(const float* __restrict__ sum_cate,
                          const float* __restrict__ out_short,
                          const float* __restrict__ fcW,
                          const float* __restrict__ fcb,
                          float* __restrict__ fc_out)
{
    __shared__ float mix[16][2 * H_];
    const int b0 = blockIdx.x * 16;
    for (int idx = threadIdx.x; idx < 16 * 2 * H_; idx += 256) {
        const int bb = idx >> 9, k = idx & 511;
        mix[bb][k] = (k < H_) ? sum_cate[(size_t)(b0 + bb) * H_ + k]
                              : out_short[(size_t)(b0 + bb) * H_ + (k - H_)];
    }
    __syncthreads();
    const int i = threadIdx.x;
    const float* wrow = fcW + (size_t)i * (2 * H_);
    float acc[16];
#pragma unroll
    for (int bb = 0; bb < 16; bb++) acc[bb] = 0.f;
    for (int k = 0; k < 2 * H_; k++) {
        const float wv = wrow[k];
#pragma unroll
        for (int bb = 0; bb < 16; bb++) acc[bb] += wv * mix[bb][k];
    }
    const float bias = fcb[i];
#pragma unroll
    for (int bb = 0; bb < 16; bb++)
        fc_out[(size_t)(b0 + bb) * H_ + i] = acc[bb] + bias;
}

__global__ void write_targets(const int* __restrict__ tgt, float* __restrict__ out)
{
    out[threadIdx.x] = (float)tgt[threadIdx.x];
}

// ---------------- launcher ----------------------------------------------------
extern "C" void kernel_launch(void* const* d_in, const int* in_sizes, int n_in,
                              void* d_out, int out_size)
{
    const int*   in_cate       = (const int*)d_in[0];
    const float* mask_cate     = (const float*)d_in[1];
    const float* mask_cate_seq = (const float*)d_in[2];
    const int*   subseqLen     = (const int*)d_in[5];
    const int*   in_batch      = (const int*)d_in[7];
    const float* mask_b        = (const float*)d_in[8];
    const int*   seqLen        = (const int*)d_in[9];
    const int*   target        = (const int*)d_in[10];
    const float* emb           = (const float*)d_in[12];
    const float* Wih_c         = (const float*)d_in[13];
    const float* Whh_c         = (const float*)d_in[14];
    const float* bih_c         = (const float*)d_in[15];
    const float* bhh_c         = (const float*)d_in[16];
    const float* Wih_s         = (const float*)d_in[17];
    const float* Whh_s         = (const float*)d_in[18];
    const float* bih_s         = (const float*)d_in[19];
    const float* bhh_s         = (const float*)d_in[20];
    const float* fc_W          = (const float*)d_in[21];
    const float* fc_b          = (const float*)d_in[22];
    float* out = (float*)d_out;

    float *gi_c, *gi_s, *seqc, *osht, *sumc, *fco;
    int *ord_c, *ord_s;
    cudaGetSymbolAddress((void**)&gi_c, g_gi_c);
    cudaGetSymbolAddress((void**)&gi_s, g_gi_s);
    cudaGetSymbolAddress((void**)&seqc, g_seq_cate);
    cudaGetSymbolAddress((void**)&osht, g_out_short);
    cudaGetSymbolAddress((void**)&sumc, g_sum_cate);
    cudaGetSymbolAddress((void**)&fco,  g_fc_out);
    cudaGetSymbolAddress((void**)&ord_c, g_order_c);
    cudaGetSymbolAddress((void**)&ord_s, g_order_s);

    // 0) sort rows by length (desc) for block-level early exit
    sort_kernel<<<1, 256>>>(subseqLen, ord_c, seqLen, ord_s);

    // 1) input-gate GEMMs (fused embedding gather)
    gemm_nt_128<<<dim3(BC_ * TC_ / 128, H3_ / 128), 256>>>(
        emb, in_cate, Wih_c, bih_c, gi_c, BC_ * TC_, H3_, E_);
    gemm_nt_128<<<dim3(B_ * TS_ / 128, H3_ / 128), 256>>>(
        emb, in_batch, Wih_s, bih_s, gi_s, B_ * TS_, H3_, E_);

    // 2) category GRU: one persistent kernel, 160 blocks x 16 rows
    gru_persist<16, TC_><<<BC_ / 16, 256>>>(
        Whh_c, bhh_c, gi_c, ord_c, subseqLen, mask_cate, seqc);

    // 3) short GRU: one persistent kernel, 64 blocks x 4 rows
    gru_persist<4, TS_><<<B_ / 4, 256>>>(
        Whh_s, bhh_s, gi_s, ord_s, seqLen, mask_b, osht);

    // 4) attention + 5) FC
    attention_kernel<<<B_, 256>>>(seqc, osht, mask_cate_seq, sumc);
    fc_kernel<<<B_ / 16, 256>>>(sumc, osht, fc_W, fc_b, fco);

    // 6) logits = fc_out @ emb^T
    gemm_nt_128<<<dim3(B_ / 128, (V_ + 127) / 128), 256>>>(
        fco, nullptr, emb, nullptr, out, B_, V_, H_);

    // 7) targets appended as float, if the output carries them
    if (out_size >= B_ * V_ + B_)
        write_targets<<<1, B_>>>(target, out + (size_t)B_ * V_);
}

// round 4
// speedup vs baseline: 1.6883x; 1.6883x over previous
#include <cuda_runtime.h>
#include <math.h>
#include <stdint.h>

// Problem constants (fixed by setup_inputs)
#define V_  100000
#define E_  256
#define H_  256
#define B_  256
#define S_  10
#define TC_ 20
#define TS_ 50
#define BC_ (B_ * S_)   // 2560
#define H3_ (3 * H_)    // 768

// ---------------- scratch (static device globals; no allocation) --------------
__device__ float g_gi_c[(size_t)BC_ * TC_ * H3_];
__device__ float g_gi_s[(size_t)B_ * TS_ * H3_];
__device__ float g_hA[BC_ * H_];
__device__ float g_hB[BC_ * H_];
__device__ float g_hsA[B_ * H_];
__device__ float g_hsB[B_ * H_];
__device__ float g_seq_cate[BC_ * H_];
__device__ float g_out_short[B_ * H_];
__device__ float g_sum_cate[B_ * H_];
__device__ float g_fc_out[B_ * H_];
__device__ int   g_order_c[BC_];
__device__ int   g_order_s[B_];
__device__ int   g_off_c[BC_ + 1];
__device__ int   g_off_s[B_ + 1];
__device__ int   g_tok_c[BC_ * TC_];
__device__ int   g_tok_s[B_ * TS_];
__device__ int   g_cnt_c[TS_ + 1];   // active-row count per step (0 beyond TC_)
__device__ int   g_cnt_s[TS_ + 1];
__device__ int   g_Mc[1];
__device__ int   g_Ms[1];

// ---------------- prep: counting sort desc, prefix offsets, token compaction --
__global__ void prep_kernel(const int* __restrict__ slen_c, const int* __restrict__ tokens_c,
                            const int* __restrict__ slen_s, const int* __restrict__ tokens_s)
{
    __shared__ int hist[64];
    __shared__ int base[64];
    __shared__ int ssum[256];
    const int tid = threadIdx.x;

    // ======== category rows (2560 keys in [0,TC_)) ========
    if (tid < 64) hist[tid] = 0;
    __syncthreads();
    for (int i = tid; i < BC_; i += 256) atomicAdd(&hist[slen_c[i]], 1);
    __syncthreads();
    // cnt_c[t] = #rows with slen >= t
    if (tid <= TS_) {
        int c = 0;
        if (tid < 64) for (int k = tid; k < 64; k++) c += hist[k];
        g_cnt_c[tid] = (tid < TC_) ? c : 0;
    }
    if (tid == 0) {
        int run = 0;
        for (int k = 63; k >= 0; k--) { base[k] = run; run += hist[k]; }
    }
    __syncthreads();
    for (int i = tid; i < BC_; i += 256) {
        int pos = atomicAdd(&base[slen_c[i]], 1);
        g_order_c[pos] = i;
    }
    // prefix sum of (slen+1) in ORIGINAL row order -> off_c
    {
        const int chunk = BC_ / 256;   // 10
        int s = 0;
        for (int i = 0; i < chunk; i++) s += slen_c[tid * chunk + i] + 1;
        ssum[tid] = s;
        __syncthreads();
        for (int d = 1; d < 256; d <<= 1) {
            int v = (tid >= d) ? ssum[tid - d] : 0;
            __syncthreads();
            ssum[tid] += v;
            __syncthreads();
        }
        int run = (tid > 0) ? ssum[tid - 1] : 0;
        for (int i = 0; i < chunk; i++) {
            int b = tid * chunk + i;
            g_off_c[b] = run;
            run += slen_c[b] + 1;
        }
        if (tid == 255) { g_off_c[BC_] = ssum[255]; g_Mc[0] = ssum[255]; }
    }
    __syncthreads();
    for (int i = tid; i < BC_ * TC_; i += 256) {
        int b = i / TC_, t = i % TC_;
        if (t <= slen_c[b]) g_tok_c[g_off_c[b] + t] = tokens_c[i];
    }
    __syncthreads();

    // ======== short rows (256 keys in [0,TS_)) ========
    if (tid < 64) hist[tid] = 0;
    __syncthreads();
    for (int i = tid; i < B_; i += 256) atomicAdd(&hist[slen_s[i]], 1);
    __syncthreads();
    if (tid <= TS_) {
        int c = 0;
        if (tid < 64) for (int k = tid; k < 64; k++) c += hist[k];
        g_cnt_s[tid] = (tid < TS_) ? c : 0;
    }
    if (tid == 0) {
        int run = 0;
        for (int k = 63; k >= 0; k--) { base[k] = run; run += hist[k]; }
    }
    __syncthreads();
    for (int i = tid; i < B_; i += 256) {
        int pos = atomicAdd(&base[slen_s[i]], 1);
        g_order_s[pos] = i;
    }
    {
        int s = (tid < B_) ? slen_s[tid] + 1 : 0;
        ssum[tid] = s;
        __syncthreads();
        for (int d = 1; d < 256; d <<= 1) {
            int v = (tid >= d) ? ssum[tid - d] : 0;
            __syncthreads();
            ssum[tid] += v;
            __syncthreads();
        }
        if (tid < B_) g_off_s[tid] = ssum[tid] - (slen_s[tid] + 1);
        if (tid == 255) { g_off_s[B_] = ssum[255]; g_Ms[0] = ssum[255]; }
    }
    __syncthreads();
    for (int i = tid; i < B_ * TS_; i += 256) {
        int b = i / TS_, t = i % TS_;
        if (t <= slen_s[b]) g_tok_s[g_off_s[b] + t] = tokens_s[i];
    }
}

// ---------------- NT GEMM (scalar, proven): C[m,n]=sum_k Arow(m)[k]*Bm[n,k] --
// Arow(m) = A + (idx ? idx[m] : m) * K  (fused embedding gather over compact
// token list). Mdev (optional): device row count -> blocks beyond it exit.
__global__ void __launch_bounds__(256) gemm_nt_128(
    const float* __restrict__ A, const int* __restrict__ idx,
    const int* __restrict__ Mdev,
    const float* __restrict__ Bm, const float* __restrict__ bias,
    float* __restrict__ C, int M, int N, int K)
{
    const int Mq = Mdev ? *Mdev : M;
    const int bm = blockIdx.x * 128;
    if (bm >= Mq) return;
    __shared__ float As[8][128];
    __shared__ float Bs[8][128];
    const int tid = threadIdx.x;
    const int bn = blockIdx.y * 128;
    const int lr = tid >> 1;
    const int lk = (tid & 1) * 4;
    const int tx = tid & 15;
    const int ty = tid >> 4;
    const int tm0 = ty * 8, tn0 = tx * 8;

    const int am = bm + lr;
    const int amc = (am < Mq) ? am : (Mq - 1);
    const float* arow = A + (size_t)(idx ? idx[amc] : amc) * K;
    const int brow = bn + lr;
    const float* brp = Bm + (size_t)brow * K;
    const bool bvalid = (brow < N);

    float acc[8][8];
#pragma unroll
    for (int i = 0; i < 8; i++)
#pragma unroll
        for (int j = 0; j < 8; j++) acc[i][j] = 0.f;

    for (int k0 = 0; k0 < K; k0 += 8) {
        float4 av = *(const float4*)(arow + k0 + lk);
        float4 bv = bvalid ? *(const float4*)(brp + k0 + lk)
                           : make_float4(0.f, 0.f, 0.f, 0.f);
        As[lk + 0][lr] = av.x; As[lk + 1][lr] = av.y;
        As[lk + 2][lr] = av.z; As[lk + 3][lr] = av.w;
        Bs[lk + 0][lr] = bv.x; Bs[lk + 1][lr] = bv.y;
        Bs[lk + 2][lr] = bv.z; Bs[lk + 3][lr] = bv.w;
        __syncthreads();
#pragma unroll
        for (int k = 0; k < 8; k++) {
            float4 a0 = *(const float4*)&As[k][tm0];
            float4 a1 = *(const float4*)&As[k][tm0 + 4];
            float4 b0 = *(const float4*)&Bs[k][tn0];
            float4 b1 = *(const float4*)&Bs[k][tn0 + 4];
            float am8[8] = {a0.x, a0.y, a0.z, a0.w, a1.x, a1.y, a1.z, a1.w};
            float bn8[8] = {b0.x, b0.y, b0.z, b0.w, b1.x, b1.y, b1.z, b1.w};
#pragma unroll
            for (int i = 0; i < 8; i++)
#pragma unroll
                for (int j = 0; j < 8; j++) acc[i][j] += am8[i] * bn8[j];
        }
        __syncthreads();
    }

#pragma unroll
    for (int i = 0; i < 8; i++) {
        const int m = bm + tm0 + i;
        if (m >= Mq) continue;
        float* crow = C + (size_t)m * N;
#pragma unroll
        for (int j = 0; j < 8; j++) {
            const int n = bn + tn0 + j;
            if (n < N) crow[n] = acc[i][j] + (bias ? bias[n] : 0.f);
        }
    }
}

// ---------------- fused dual GRU step (cat + short in one launch) -------------
// blockIdx.x < CATBX: category rows, row-block = blockIdx.x.
// blockIdx.x >= CATBX: short rows,   row-block = blockIdx.x - CATBX.
// Each side processes the active prefix [0, cnt[t]) of its length-sorted order.
// 64 sorted-slots x 64 j per block; gh = h@Whh^T + gates + update + gather.
#define CATBX 40
__device__ __forceinline__ void gru_tile(
    const float* __restrict__ Whh, const float* __restrict__ bhh,
    const float* __restrict__ gi,  const int* __restrict__ off,
    const int* __restrict__ order, const int* __restrict__ slen,
    const float* __restrict__ mask, int maskT,
    const float* __restrict__ h_in, float* __restrict__ h_out,
    float* __restrict__ gathered, int t, int active, int bx)
{
    __shared__ float Hs[16][64];
    __shared__ float Ws[3][16][64];
    const int tid = threadIdx.x;
    const int bm = bx * 64;
    const int bj = blockIdx.y * 64;
    const int lr = tid >> 2;           // 0..63
    const int lk = (tid & 3) * 4;      // 0,4,8,12
    const int tx = tid & 15, ty = tid >> 4;
    const int tm0 = ty * 4, tn0 = tx * 4;

    float ar[4][4] = {}, az[4][4] = {}, an[4][4] = {};

    const int slot_l = bm + lr;
    const int row_l = order[(slot_l < active) ? slot_l : (active - 1)];

    if (t > 0) {
        const float* hrow = h_in + (size_t)row_l * H_;
        const float* w0 = Whh + (size_t)(0 * H_ + bj + lr) * H_;
        const float* w1 = Whh + (size_t)(1 * H_ + bj + lr) * H_;
        const float* w2 = Whh + (size_t)(2 * H_ + bj + lr) * H_;
        for (int k0 = 0; k0 < H_; k0 += 16) {
            float4 hv = *(const float4*)(hrow + k0 + lk);
            float4 v0 = *(const float4*)(w0 + k0 + lk);
            float4 v1 = *(const float4*)(w1 + k0 + lk);
            float4 v2 = *(const float4*)(w2 + k0 + lk);
            Hs[lk + 0][lr] = hv.x; Hs[lk + 1][lr] = hv.y;
            Hs[lk + 2][lr] = hv.z; Hs[lk + 3][lr] = hv.w;
            Ws[0][lk + 0][lr] = v0.x; Ws[0][lk + 1][lr] = v0.y;
            Ws[0][lk + 2][lr] = v0.z; Ws[0][lk + 3][lr] = v0.w;
            Ws[1][lk + 0][lr] = v1.x; Ws[1][lk + 1][lr] = v1.y;
            Ws[1][lk + 2][lr] = v1.z; Ws[1][lk + 3][lr] = v1.w;
            Ws[2][lk + 0][lr] = v2.x; Ws[2][lk + 1][lr] = v2.y;
            Ws[2][lk + 2][lr] = v2.z; Ws[2][lk + 3][lr] = v2.w;
            __syncthreads();
#pragma unroll
            for (int k = 0; k < 16; k++) {
                float4 h4 = *(const float4*)&Hs[k][tm0];
                float4 r4 = *(const float4*)&Ws[0][k][tn0];
                float4 z4 = *(const float4*)&Ws[1][k][tn0];
                float4 n4 = *(const float4*)&Ws[2][k][tn0];
                float hm[4] = {h4.x, h4.y, h4.z, h4.w};
                float rr[4] = {r4.x, r4.y, r4.z, r4.w};
                float zz[4] = {z4.x, z4.y, z4.z, z4.w};
                float nn[4] = {n4.x, n4.y, n4.z, n4.w};
#pragma unroll
                for (int i = 0; i < 4; i++)
#pragma unroll
                    for (int j = 0; j < 4; j++) {
                        ar[i][j] += hm[i] * rr[j];
                        az[i][j] += hm[i] * zz[j];
                        an[i][j] += hm[i] * nn[j];
                    }
            }
            __syncthreads();
        }
    }

#pragma unroll
    for (int i = 0; i < 4; i++) {
        const int slot = bm + tm0 + i;
        if (slot >= active) continue;
        const int b = order[slot];
        const float* girow = gi + ((size_t)(off[b] + t)) * H3_;
        const bool take = (slen[b] == t);
        const float mval = mask[(size_t)b * maskT + t];
#pragma unroll
        for (int j = 0; j < 4; j++) {
            const int jj = bj + tn0 + j;
            const float gr = girow[jj];
            const float gz = girow[H_ + jj];
            const float gn = girow[2 * H_ + jj];
            const float hr = ar[i][j] + bhh[jj];
            const float hz = az[i][j] + bhh[H_ + jj];
            const float hn = an[i][j] + bhh[2 * H_ + jj];
            const float hold = (t > 0) ? h_in[(size_t)b * H_ + jj] : 0.f;
            const float r = 1.f / (1.f + __expf(-(gr + hr)));
            const float z = 1.f / (1.f + __expf(-(gz + hz)));
            const float n = tanhf(gn + r * hn);
            const float hnew = (1.f - z) * n + z * hold;
            h_out[(size_t)b * H_ + jj] = hnew;
            if (take) gathered[(size_t)b * H_ + jj] = hnew * mval;
        }
    }
}

__global__ void __launch_bounds__(256) gru_dual_step(
    const float* Whh_c, const float* bhh_c, const float* gi_c,
    const float* h_in_c, float* h_out_c, const float* mask_c, float* gath_c,
    const int* slen_c,
    const float* Whh_s, const float* bhh_s, const float* gi_s,
    const float* h_in_s, float* h_out_s, const float* mask_s, float* gath_s,
    const int* slen_s, int t)
{
    if ((int)blockIdx.x < CATBX) {
        const int active = g_cnt_c[t];
        if (blockIdx.x * 64 >= (unsigned)active) return;
        gru_tile(Whh_c, bhh_c, gi_c, g_off_c, g_order_c, slen_c, mask_c, TC_,
                 h_in_c, h_out_c, gath_c, t, active, blockIdx.x);
    } else {
        const int bx = blockIdx.x - CATBX;
        const int active = g_cnt_s[t];
        if (bx * 64 >= active) return;
        gru_tile(Whh_s, bhh_s, gi_s, g_off_s, g_order_s, slen_s, mask_s, TS_,
                 h_in_s, h_out_s, gath_s, t, active, bx);
    }
}

// ---------------- attention: masked softmax of out_short over seq_cate -------
__global__ void attention_kernel(const float* __restrict__ seq_cate,
                                 const float* __restrict__ out_short,
                                 const float* __restrict__ mask_seq,
                                 float* __restrict__ sum_cate)
{
    const int b = blockIdx.x;
    const int j = threadIdx.x;  // 256 = H
    __shared__ float red[8];
    __shared__ float w[S_];
    const float os = out_short[(size_t)b * H_ + j];
    float sc[S_];
#pragma unroll
    for (int s = 0; s < S_; s++)
        sc[s] = seq_cate[(size_t)(b * S_ + s) * H_ + j];

    for (int s = 0; s < S_; s++) {
        float v = sc[s] * os;
#pragma unroll
        for (int off = 16; off; off >>= 1) v += __shfl_xor_sync(0xffffffffu, v, off);
        if ((j & 31) == 0) red[j >> 5] = v;
        __syncthreads();
        if (j == 0) {
            float x = 0.f;
#pragma unroll
            for (int q = 0; q < 8; q++) x += red[q];
            w[s] = x;
        }
        __syncthreads();
    }
    if (j == 0) {
        float mx = w[0];
        for (int s = 1; s < S_; s++) mx = fmaxf(mx, w[s]);
        float e[S_];
        float sum = 0.f;
        for (int s = 0; s < S_; s++) { e[s] = expf(w[s] - mx); sum += e[s]; }
        float s2 = 0.f;
        for (int s = 0; s < S_; s++) {
            e[s] = (e[s] / sum) * mask_seq[(size_t)b * S_ + s];
            s2 += e[s];
        }
        for (int s = 0; s < S_; s++) w[s] = e[s] / s2;
    }
    __syncthreads();
    float acc = 0.f;
#pragma unroll
    for (int s = 0; s < S_; s++) acc += w[s] * sc[s];
    sum_cate[(size_t)b * H_ + j] = acc;
}

// ---------------- FC: fc_out[b,i] = [sum_cate|out_short][b,:] . fc_W[i,:] ----
__global__ void fc_kernel(const float* __restrict__ sum_cate,
                          const float* __restrict__ out_short,
                          const float* __restrict__ fcW,
                          const float* __restrict__ fcb,
                          float* __restrict__ fc_out)
{
    __shared__ float mix[16][2 * H_];
    const int b0 = blockIdx.x * 16;
    for (int idx = threadIdx.x; idx < 16 * 2 * H_; idx += 256) {
        const int bb = idx >> 9, k = idx & 511;
        mix[bb][k] = (k < H_) ? sum_cate[(size_t)(b0 + bb) * H_ + k]
                              : out_short[(size_t)(b0 + bb) * H_ + (k - H_)];
    }
    __syncthreads();
    const int i = threadIdx.x;
    const float* wrow = fcW + (size_t)i * (2 * H_);
    float acc[16];
#pragma unroll
    for (int bb = 0; bb < 16; bb++) acc[bb] = 0.f;
    for (int k = 0; k < 2 * H_; k++) {
        const float wv = wrow[k];
#pragma unroll
        for (int bb = 0; bb < 16; bb++) acc[bb] += wv * mix[bb][k];
    }
    const float bias = fcb[i];
#pragma unroll
    for (int bb = 0; bb < 16; bb++)
        fc_out[(size_t)(b0 + bb) * H_ + i] = acc[bb] + bias;
}

__global__ void write_targets(const int* __restrict__ tgt, float* __restrict__ out)
{
    out[threadIdx.x] = (float)tgt[threadIdx.x];
}

// ---------------- launcher ----------------------------------------------------
extern "C" void kernel_launch(void* const* d_in, const int* in_sizes, int n_in,
                              void* d_out, int out_size)
{
    const int*   in_cate       = (const int*)d_in[0];
    const float* mask_cate     = (const float*)d_in[1];
    const float* mask_cate_seq = (const float*)d_in[2];
    const int*   subseqLen     = (const int*)d_in[5];
    const int*   in_batch      = (const int*)d_in[7];
    const float* mask_b        = (const float*)d_in[8];
    const int*   seqLen        = (const int*)d_in[9];
    const int*   target        = (const int*)d_in[10];
    const float* emb           = (const float*)d_in[12];
    const float* Wih_c         = (const float*)d_in[13];
    const float* Whh_c         = (const float*)d_in[14];
    const float* bih_c         = (const float*)d_in[15];
    const float* bhh_c         = (const float*)d_in[16];
    const float* Wih_s         = (const float*)d_in[17];
    const float* Whh_s         = (const float*)d_in[18];
    const float* bih_s         = (const float*)d_in[19];
    const float* bhh_s         = (const float*)d_in[20];
    const float* fc_W          = (const float*)d_in[21];
    const float* fc_b          = (const float*)d_in[22];
    float* out = (float*)d_out;

    float *gi_c, *gi_s, *hA, *hB, *hsA, *hsB, *seqc, *osht, *sumc, *fco;
    int *tok_c, *tok_s, *Mc, *Ms;
    cudaGetSymbolAddress((void**)&gi_c, g_gi_c);
    cudaGetSymbolAddress((void**)&gi_s, g_gi_s);
    cudaGetSymbolAddress((void**)&hA,  g_hA);
    cudaGetSymbolAddress((void**)&hB,  g_hB);
    cudaGetSymbolAddress((void**)&hsA, g_hsA);
    cudaGetSymbolAddress((void**)&hsB, g_hsB);
    cudaGetSymbolAddress((void**)&seqc, g_seq_cate);
    cudaGetSymbolAddress((void**)&osht, g_out_short);
    cudaGetSymbolAddress((void**)&sumc, g_sum_cate);
    cudaGetSymbolAddress((void**)&fco,  g_fc_out);
    cudaGetSymbolAddress((void**)&tok_c, g_tok_c);
    cudaGetSymbolAddress((void**)&tok_s, g_tok_s);
    cudaGetSymbolAddress((void**)&Mc, g_Mc);
    cudaGetSymbolAddress((void**)&Ms, g_Ms);

    // 0) prep: sort by length desc, offsets, compact token lists, cnt tables
    prep_kernel<<<1, 256>>>(subseqLen, in_cate, seqLen, in_batch);

    // 1) input-gate GEMMs over COMPACTED tokens (fused embedding gather)
    gemm_nt_128<<<dim3((BC_ * TC_ + 127) / 128, H3_ / 128), 256>>>(
        emb, tok_c, Mc, Wih_c, bih_c, gi_c, BC_ * TC_, H3_, E_);
    gemm_nt_128<<<dim3((B_ * TS_ + 127) / 128, H3_ / 128), 256>>>(
        emb, tok_s, Ms, Wih_s, bih_s, gi_s, B_ * TS_, H3_, E_);

    // 2+3) fused GRU scans: 50 dual-step launches (cat active for t<20)
    {
        float *hc_in = hA, *hc_out = hB, *hs_in = hsA, *hs_out = hsB;
        for (int t = 0; t < TS_; t++) {
            gru_dual_step<<<dim3(CATBX + B_ / 64, H_ / 64), 256>>>(
                Whh_c, bhh_c, gi_c, hc_in, hc_out, mask_cate, seqc, subseqLen,
                Whh_s, bhh_s, gi_s, hs_in, hs_out, mask_b, osht, seqLen, t);
            float* tmp;
            tmp = hc_in; hc_in = hc_out; hc_out = tmp;
            tmp = hs_in; hs_in = hs_out; hs_out = tmp;
        }
    }

    // 4) attention + 5) FC
    attention_kernel<<<B_, 256>>>(seqc, osht, mask_cate_seq, sumc);
    fc_kernel<<<B_ / 16, 256>>>(sumc, osht, fc_W, fc_b, fco);

    // 6) logits = fc_out @ emb^T
    gemm_nt_128<<<dim3(B_ / 128, (V_ + 127) / 128), 256>>>(
        fco, nullptr, nullptr, emb, nullptr, out, B_, V_, H_);

    // 7) targets appended as float, if the output carries them
    if (out_size >= B_ * V_ + B_)
        write_targets<<<1, B_>>>(target, out + (size_t)B_ * V_);
}

// round 5
// speedup vs baseline: 1.7149x; 1.0157x over previous
#include <cuda_runtime.h>
#include <math.h>
#include <stdint.h>

// Problem constants (fixed by setup_inputs)
#define V_  100000
#define E_  256
#define H_  256
#define B_  256
#define S_  10
#define TC_ 20
#define TS_ 50
#define BC_ (B_ * S_)   // 2560
#define H3_ (3 * H_)    // 768

// ---------------- scratch (static device globals; no allocation) --------------
__device__ float g_gi_c[(size_t)BC_ * TC_ * H3_];
__device__ float g_gi_s[(size_t)B_ * TS_ * H3_];
__device__ float g_hA[BC_ * H_];
__device__ float g_hB[BC_ * H_];
__device__ float g_hsA[B_ * H_];
__device__ float g_hsB[B_ * H_];
__device__ float g_seq_cate[BC_ * H_];
__device__ float g_out_short[B_ * H_];
__device__ float g_sum_cate[B_ * H_];
__device__ float g_fc_out[B_ * H_];
__device__ int   g_order_c[BC_];
__device__ int   g_order_s[B_];
__device__ int   g_off_c[BC_ + 1];
__device__ int   g_off_s[B_ + 1];
__device__ int   g_tok_c[BC_ * TC_];
__device__ int   g_tok_s[B_ * TS_];
__device__ int   g_cnt_c[TS_ + 1];   // active-row count per step (0 beyond TC_)
__device__ int   g_cnt_s[TS_ + 1];
__device__ int   g_Mc[1];
__device__ int   g_Ms[1];

// ---------------- f32x2 packed-FMA helpers ------------------------------------
#define FMA2(acc, a, b) asm("fma.rn.f32x2 %0, %1, %2, %0;" : "+l"(acc) : "l"(a), "l"(b))

__device__ __forceinline__ unsigned long long splat2(float x) {
    unsigned long long r;
    asm("mov.b64 %0, {%1, %1};" : "=l"(r) : "f"(x));
    return r;
}
__device__ __forceinline__ float2 unpack2(unsigned long long v) {
    float2 f;
    asm("mov.b64 {%0, %1}, %2;" : "=f"(f.x), "=f"(f.y) : "l"(v));
    return f;
}
__device__ __forceinline__ float fast_sigmoid(float x) {
    return 1.f / (1.f + __expf(-x));
}
__device__ __forceinline__ float fast_tanh(float x) {
    float ax = fabsf(x);
    float e = __expf(-2.f * ax);
    float t = __fdividef(1.f - e, 1.f + e);
    return copysignf(t, x);
}

// ---------------- prep: counting sort desc, prefix offsets, token compaction --
__global__ void prep_kernel(const int* __restrict__ slen_c, const int* __restrict__ tokens_c,
                            const int* __restrict__ slen_s, const int* __restrict__ tokens_s)
{
    __shared__ int hist[64];
    __shared__ int base[64];
    __shared__ int ssum[256];
    const int tid = threadIdx.x;

    // ======== category rows (2560 keys in [0,TC_)) ========
    if (tid < 64) hist[tid] = 0;
    __syncthreads();
    for (int i = tid; i < BC_; i += 256) atomicAdd(&hist[slen_c[i]], 1);
    __syncthreads();
    if (tid <= TS_) {
        int c = 0;
        if (tid < 64) for (int k = tid; k < 64; k++) c += hist[k];
        g_cnt_c[tid] = (tid < TC_) ? c : 0;
    }
    if (tid == 0) {
        int run = 0;
        for (int k = 63; k >= 0; k--) { base[k] = run; run += hist[k]; }
    }
    __syncthreads();
    for (int i = tid; i < BC_; i += 256) {
        int pos = atomicAdd(&base[slen_c[i]], 1);
        g_order_c[pos] = i;
    }
    {
        const int chunk = BC_ / 256;   // 10
        int s = 0;
        for (int i = 0; i < chunk; i++) s += slen_c[tid * chunk + i] + 1;
        ssum[tid] = s;
        __syncthreads();
        for (int d = 1; d < 256; d <<= 1) {
            int v = (tid >= d) ? ssum[tid - d] : 0;
            __syncthreads();
            ssum[tid] += v;
            __syncthreads();
        }
        int run = (tid > 0) ? ssum[tid - 1] : 0;
        for (int i = 0; i < chunk; i++) {
            int b = tid * chunk + i;
            g_off_c[b] = run;
            run += slen_c[b] + 1;
        }
        if (tid == 255) { g_off_c[BC_] = ssum[255]; g_Mc[0] = ssum[255]; }
    }
    __syncthreads();
    for (int i = tid; i < BC_ * TC_; i += 256) {
        int b = i / TC_, t = i % TC_;
        if (t <= slen_c[b]) g_tok_c[g_off_c[b] + t] = tokens_c[i];
    }
    __syncthreads();

    // ======== short rows (256 keys in [0,TS_)) ========
    if (tid < 64) hist[tid] = 0;
    __syncthreads();
    for (int i = tid; i < B_; i += 256) atomicAdd(&hist[slen_s[i]], 1);
    __syncthreads();
    if (tid <= TS_) {
        int c = 0;
        if (tid < 64) for (int k = tid; k < 64; k++) c += hist[k];
        g_cnt_s[tid] = (tid < TS_) ? c : 0;
    }
    if (tid == 0) {
        int run = 0;
        for (int k = 63; k >= 0; k--) { base[k] = run; run += hist[k]; }
    }
    __syncthreads();
    for (int i = tid; i < B_; i += 256) {
        int pos = atomicAdd(&base[slen_s[i]], 1);
        g_order_s[pos] = i;
    }
    {
        int s = (tid < B_) ? slen_s[tid] + 1 : 0;
        ssum[tid] = s;
        __syncthreads();
        for (int d = 1; d < 256; d <<= 1) {
            int v = (tid >= d) ? ssum[tid - d] : 0;
            __syncthreads();
            ssum[tid] += v;
            __syncthreads();
        }
        if (tid < B_) g_off_s[tid] = ssum[tid] - (slen_s[tid] + 1);
        if (tid == 255) { g_off_s[B_] = ssum[255]; g_Ms[0] = ssum[255]; }
    }
    __syncthreads();
    for (int i = tid; i < B_ * TS_; i += 256) {
        int b = i / TS_, t = i % TS_;
        if (t <= slen_s[b]) g_tok_s[g_off_s[b] + t] = tokens_s[i];
    }
}

// ---------------- NT GEMM (FFMA2): C[m,n]=sum_k Arow(m)[k]*Bm[n,k] (+bias) ----
// Arow(m) = A + (idx ? idx[m] : m) * K  (fused embedding gather over compact
// token list). Mdev (optional): device row count -> blocks beyond it exit.
__global__ void __launch_bounds__(256) gemm_nt_128(
    const float* __restrict__ A, const int* __restrict__ idx,
    const int* __restrict__ Mdev,
    const float* __restrict__ Bm, const float* __restrict__ bias,
    float* __restrict__ C, int M, int N, int K)
{
    const int Mq = Mdev ? *Mdev : M;
    const int bm = blockIdx.x * 128;
    if (bm >= Mq) return;
    __shared__ __align__(16) float As[8][128];
    __shared__ __align__(16) float Bs[8][128];
    const int tid = threadIdx.x;
    const int bn = blockIdx.y * 128;
    const int lr = tid >> 1;
    const int lk = (tid & 1) * 4;
    const int tx = tid & 15;
    const int ty = tid >> 4;
    const int tm0 = ty * 8, tn0 = tx * 8;

    const int am = bm + lr;
    const int amc = (am < Mq) ? am : (Mq - 1);
    const float* arow = A + (size_t)(idx ? idx[amc] : amc) * K;
    const int brow = bn + lr;
    const float* brp = Bm + (size_t)brow * K;
    const bool bvalid = (brow < N);

    unsigned long long accP[8][4];
#pragma unroll
    for (int i = 0; i < 8; i++)
#pragma unroll
        for (int j = 0; j < 4; j++) accP[i][j] = 0ull;

    for (int k0 = 0; k0 < K; k0 += 8) {
        float4 av = *(const float4*)(arow + k0 + lk);
        float4 bv = bvalid ? *(const float4*)(brp + k0 + lk)
                           : make_float4(0.f, 0.f, 0.f, 0.f);
        As[lk + 0][lr] = av.x; As[lk + 1][lr] = av.y;
        As[lk + 2][lr] = av.z; As[lk + 3][lr] = av.w;
        Bs[lk + 0][lr] = bv.x; Bs[lk + 1][lr] = bv.y;
        Bs[lk + 2][lr] = bv.z; Bs[lk + 3][lr] = bv.w;
        __syncthreads();
#pragma unroll
        for (int k = 0; k < 8; k++) {
            float4 a0 = *(const float4*)&As[k][tm0];
            float4 a1 = *(const float4*)&As[k][tm0 + 4];
            const ulonglong2* bp2 = (const ulonglong2*)&Bs[k][tn0];
            ulonglong2 b01 = bp2[0];
            ulonglong2 b23 = bp2[1];
            unsigned long long bp[4] = {b01.x, b01.y, b23.x, b23.y};
            float am8[8] = {a0.x, a0.y, a0.z, a0.w, a1.x, a1.y, a1.z, a1.w};
#pragma unroll
            for (int i = 0; i < 8; i++) {
                unsigned long long as2 = splat2(am8[i]);
#pragma unroll
                for (int j = 0; j < 4; j++) FMA2(accP[i][j], as2, bp[j]);
            }
        }
        __syncthreads();
    }

#pragma unroll
    for (int i = 0; i < 8; i++) {
        const int m = bm + tm0 + i;
        if (m >= Mq) continue;
        float* crow = C + (size_t)m * N;
#pragma unroll
        for (int j = 0; j < 4; j++) {
            float2 v = unpack2(accP[i][j]);
            const int n0 = bn + tn0 + 2 * j;
            if (n0 < N)     crow[n0]     = v.x + (bias ? bias[n0]     : 0.f);
            if (n0 + 1 < N) crow[n0 + 1] = v.y + (bias ? bias[n0 + 1] : 0.f);
        }
    }
}

// ---------------- fused dual GRU step (cat + short in one launch) -------------
#define CATBX 40
__device__ __forceinline__ void gru_tile(
    const float* __restrict__ Whh, const float* __restrict__ bhh,
    const float* __restrict__ gi,  const int* __restrict__ off,
    const int* __restrict__ order, const int* __restrict__ slen,
    const float* __restrict__ mask, int maskT,
    const float* __restrict__ h_in, float* __restrict__ h_out,
    float* __restrict__ gathered, int t, int active, int bx)
{
    __shared__ float Hs[16][64];
    __shared__ float Ws[3][16][64];
    const int tid = threadIdx.x;
    const int bm = bx * 64;
    const int bj = blockIdx.y * 64;
    const int lr = tid >> 2;           // 0..63
    const int lk = (tid & 3) * 4;      // 0,4,8,12
    const int tx = tid & 15, ty = tid >> 4;
    const int tm0 = ty * 4, tn0 = tx * 4;

    float ar[4][4] = {}, az[4][4] = {}, an[4][4] = {};

    const int slot_l = bm + lr;
    const int row_l = order[(slot_l < active) ? slot_l : (active - 1)];

    if (t > 0) {
        const float* hrow = h_in + (size_t)row_l * H_;
        const float* w0 = Whh + (size_t)(0 * H_ + bj + lr) * H_;
        const float* w1 = Whh + (size_t)(1 * H_ + bj + lr) * H_;
        const float* w2 = Whh + (size_t)(2 * H_ + bj + lr) * H_;
        for (int k0 = 0; k0 < H_; k0 += 16) {
            float4 hv = *(const float4*)(hrow + k0 + lk);
            float4 v0 = *(const float4*)(w0 + k0 + lk);
            float4 v1 = *(const float4*)(w1 + k0 + lk);
            float4 v2 = *(const float4*)(w2 + k0 + lk);
            Hs[lk + 0][lr] = hv.x; Hs[lk + 1][lr] = hv.y;
            Hs[lk + 2][lr] = hv.z; Hs[lk + 3][lr] = hv.w;
            Ws[0][lk + 0][lr] = v0.x; Ws[0][lk + 1][lr] = v0.y;
            Ws[0][lk + 2][lr] = v0.z; Ws[0][lk + 3][lr] = v0.w;
            Ws[1][lk + 0][lr] = v1.x; Ws[1][lk + 1][lr] = v1.y;
            Ws[1][lk + 2][lr] = v1.z; Ws[1][lk + 3][lr] = v1.w;
            Ws[2][lk + 0][lr] = v2.x; Ws[2][lk + 1][lr] = v2.y;
            Ws[2][lk + 2][lr] = v2.z; Ws[2][lk + 3][lr] = v2.w;
            __syncthreads();
#pragma unroll
            for (int k = 0; k < 16; k++) {
                float4 h4 = *(const float4*)&Hs[k][tm0];
                float4 r4 = *(const float4*)&Ws[0][k][tn0];
                float4 z4 = *(const float4*)&Ws[1][k][tn0];
                float4 n4 = *(const float4*)&Ws[2][k][tn0];
                float hm[4] = {h4.x, h4.y, h4.z, h4.w};
                float rr[4] = {r4.x, r4.y, r4.z, r4.w};
                float zz[4] = {z4.x, z4.y, z4.z, z4.w};
                float nn[4] = {n4.x, n4.y, n4.z, n4.w};
#pragma unroll
                for (int i = 0; i < 4; i++)
#pragma unroll
                    for (int j = 0; j < 4; j++) {
                        ar[i][j] += hm[i] * rr[j];
                        az[i][j] += hm[i] * zz[j];
                        an[i][j] += hm[i] * nn[j];
                    }
            }
            __syncthreads();
        }
    }

#pragma unroll
    for (int i = 0; i < 4; i++) {
        const int slot = bm + tm0 + i;
        if (slot >= active) continue;
        const int b = order[slot];
        const float* girow = gi + ((size_t)(off[b] + t)) * H3_;
        const bool take = (slen[b] == t);
        const float mval = mask[(size_t)b * maskT + t];
#pragma unroll
        for (int j = 0; j < 4; j++) {
            const int jj = bj + tn0 + j;
            const float gr = girow[jj];
            const float gz = girow[H_ + jj];
            const float gn = girow[2 * H_ + jj];
            const float hr = ar[i][j] + bhh[jj];
            const float hz = az[i][j] + bhh[H_ + jj];
            const float hn = an[i][j] + bhh[2 * H_ + jj];
            const float hold = (t > 0) ? h_in[(size_t)b * H_ + jj] : 0.f;
            const float r = fast_sigmoid(gr + hr);
            const float z = fast_sigmoid(gz + hz);
            const float n = fast_tanh(gn + r * hn);
            const float hnew = (1.f - z) * n + z * hold;
            h_out[(size_t)b * H_ + jj] = hnew;
            if (take) gathered[(size_t)b * H_ + jj] = hnew * mval;
        }
    }
}

__global__ void __launch_bounds__(256) gru_dual_step(
    const float* Whh_c, const float* bhh_c, const float* gi_c,
    const float* h_in_c, float* h_out_c, const float* mask_c, float* gath_c,
    const int* slen_c,
    const float* Whh_s, const float* bhh_s, const float* gi_s,
    const float* h_in_s, float* h_out_s, const float* mask_s, float* gath_s,
    const int* slen_s, int t)
{
    if ((int)blockIdx.x < CATBX) {
        const int active = g_cnt_c[t];
        if (blockIdx.x * 64 >= (unsigned)active) return;
        gru_tile(Whh_c, bhh_c, gi_c, g_off_c, g_order_c, slen_c, mask_c, TC_,
                 h_in_c, h_out_c, gath_c, t, active, blockIdx.x);
    } else {
        const int bx = blockIdx.x - CATBX;
        const int active = g_cnt_s[t];
        if (bx * 64 >= active) return;
        gru_tile(Whh_s, bhh_s, gi_s, g_off_s, g_order_s, slen_s, mask_s, TS_,
                 h_in_s, h_out_s, gath_s, t, active, bx);
    }
}

// ---------------- attention: masked softmax of out_short over seq_cate -------
__global__ void attention_kernel(const float* __restrict__ seq_cate,
                                 const float* __restrict__ out_short,
                                 const float* __restrict__ mask_seq,
                                 float* __restrict__ sum_cate)
{
    const int b = blockIdx.x;
    const int j = threadIdx.x;  // 256 = H
    __shared__ float red[8];
    __shared__ float w[S_];
    const float os = out_short[(size_t)b * H_ + j];
    float sc[S_];
#pragma unroll
    for (int s = 0; s < S_; s++)
        sc[s] = seq_cate[(size_t)(b * S_ + s) * H_ + j];

    for (int s = 0; s < S_; s++) {
        float v = sc[s] * os;
#pragma unroll
        for (int off = 16; off; off >>= 1) v += __shfl_xor_sync(0xffffffffu, v, off);
        if ((j & 31) == 0) red[j >> 5] = v;
        __syncthreads();
        if (j == 0) {
            float x = 0.f;
#pragma unroll
            for (int q = 0; q < 8; q++) x += red[q];
            w[s] = x;
        }
        __syncthreads();
    }
    if (j == 0) {
        float mx = w[0];
        for (int s = 1; s < S_; s++) mx = fmaxf(mx, w[s]);
        float e[S_];
        float sum = 0.f;
        for (int s = 0; s < S_; s++) { e[s] = expf(w[s] - mx); sum += e[s]; }
        float s2 = 0.f;
        for (int s = 0; s < S_; s++) {
            e[s] = (e[s] / sum) * mask_seq[(size_t)b * S_ + s];
            s2 += e[s];
        }
        for (int s = 0; s < S_; s++) w[s] = e[s] / s2;
    }
    __syncthreads();
    float acc = 0.f;
#pragma unroll
    for (int s = 0; s < S_; s++) acc += w[s] * sc[s];
    sum_cate[(size_t)b * H_ + j] = acc;
}

// ---------------- FC: fc_out[b,i] = [sum_cate|out_short][b,:] . fc_W[i,:] ----
__global__ void fc_kernel(const float* __restrict__ sum_cate,
                          const float* __restrict__ out_short,
                          const float* __restrict__ fcW,
                          const float* __restrict__ fcb,
                          float* __restrict__ fc_out)
{
    __shared__ float mix[16][2 * H_];
    const int b0 = blockIdx.x * 16;
    for (int idx = threadIdx.x; idx < 16 * 2 * H_; idx += 256) {
        const int bb = idx >> 9, k = idx & 511;
        mix[bb][k] = (k < H_) ? sum_cate[(size_t)(b0 + bb) * H_ + k]
                              : out_short[(size_t)(b0 + bb) * H_ + (k - H_)];
    }
    __syncthreads();
    const int i = threadIdx.x;
    const float* wrow = fcW + (size_t)i * (2 * H_);
    float acc[16];
#pragma unroll
    for (int bb = 0; bb < 16; bb++) acc[bb] = 0.f;
    for (int k = 0; k < 2 * H_; k++) {
        const float wv = wrow[k];
#pragma unroll
        for (int bb = 0; bb < 16; bb++) acc[bb] += wv * mix[bb][k];
    }
    const float bias = fcb[i];
#pragma unroll
    for (int bb = 0; bb < 16; bb++)
        fc_out[(size_t)(b0 + bb) * H_ + i] = acc[bb] + bias;
}

__global__ void write_targets(const int* __restrict__ tgt, float* __restrict__ out)
{
    out[threadIdx.x] = (float)tgt[threadIdx.x];
}

// ---------------- launcher ----------------------------------------------------
extern "C" void kernel_launch(void* const* d_in, const int* in_sizes, int n_in,
                              void* d_out, int out_size)
{
    const int*   in_cate       = (const int*)d_in[0];
    const float* mask_cate     = (const float*)d_in[1];
    const float* mask_cate_seq = (const float*)d_in[2];
    const int*   subseqLen     = (const int*)d_in[5];
    const int*   in_batch      = (const int*)d_in[7];
    const float* mask_b        = (const float*)d_in[8];
    const int*   seqLen        = (const int*)d_in[9];
    const int*   target        = (const int*)d_in[10];
    const float* emb           = (const float*)d_in[12];
    const float* Wih_c         = (const float*)d_in[13];
    const float* Whh_c         = (const float*)d_in[14];
    const float* bih_c         = (const float*)d_in[15];
    const float* bhh_c         = (const float*)d_in[16];
    const float* Wih_s         = (const float*)d_in[17];
    const float* Whh_s         = (const float*)d_in[18];
    const float* bih_s         = (const float*)d_in[19];
    const float* bhh_s         = (const float*)d_in[20];
    const float* fc_W          = (const float*)d_in[21];
    const float* fc_b          = (const float*)d_in[22];
    float* out = (float*)d_out;

    float *gi_c, *gi_s, *hA, *hB, *hsA, *hsB, *seqc, *osht, *sumc, *fco;
    int *tok_c, *tok_s, *Mc, *Ms;
    cudaGetSymbolAddress((void**)&gi_c, g_gi_c);
    cudaGetSymbolAddress((void**)&gi_s, g_gi_s);
    cudaGetSymbolAddress((void**)&hA,  g_hA);
    cudaGetSymbolAddress((void**)&hB,  g_hB);
    cudaGetSymbolAddress((void**)&hsA, g_hsA);
    cudaGetSymbolAddress((void**)&hsB, g_hsB);
    cudaGetSymbolAddress((void**)&seqc, g_seq_cate);
    cudaGetSymbolAddress((void**)&osht, g_out_short);
    cudaGetSymbolAddress((void**)&sumc, g_sum_cate);
    cudaGetSymbolAddress((void**)&fco,  g_fc_out);
    cudaGetSymbolAddress((void**)&tok_c, g_tok_c);
    cudaGetSymbolAddress((void**)&tok_s, g_tok_s);
    cudaGetSymbolAddress((void**)&Mc, g_Mc);
    cudaGetSymbolAddress((void**)&Ms, g_Ms);

    // 0) prep: sort by length desc, offsets, compact token lists, cnt tables
    prep_kernel<<<1, 256>>>(subseqLen, in_cate, seqLen, in_batch);

    // 1) input-gate GEMMs over COMPACTED tokens (fused embedding gather)
    gemm_nt_128<<<dim3((BC_ * TC_ + 127) / 128, H3_ / 128), 256>>>(
        emb, tok_c, Mc, Wih_c, bih_c, gi_c, BC_ * TC_, H3_, E_);
    gemm_nt_128<<<dim3((B_ * TS_ + 127) / 128, H3_ / 128), 256>>>(
        emb, tok_s, Ms, Wih_s, bih_s, gi_s, B_ * TS_, H3_, E_);

    // 2+3) fused GRU scans: 50 dual-step launches (cat active for t<20)
    {
        float *hc_in = hA, *hc_out = hB, *hs_in = hsA, *hs_out = hsB;
        for (int t = 0; t < TS_; t++) {
            gru_dual_step<<<dim3(CATBX + B_ / 64, H_ / 64), 256>>>(
                Whh_c, bhh_c, gi_c, hc_in, hc_out, mask_cate, seqc, subseqLen,
                Whh_s, bhh_s, gi_s, hs_in, hs_out, mask_b, osht, seqLen, t);
            float* tmp;
            tmp = hc_in; hc_in = hc_out; hc_out = tmp;
            tmp = hs_in; hs_in = hs_out; hs_out = tmp;
        }
    }

    // 4) attention + 5) FC
    attention_kernel<<<B_, 256>>>(seqc, osht, mask_cate_seq, sumc);
    fc_kernel<<<B_ / 16, 256>>>(sumc, osht, fc_W, fc_b, fco);

    // 6) logits = fc_out @ emb^T
    gemm_nt_128<<<dim3(B_ / 128, (V_ + 127) / 128), 256>>>(
        fco, nullptr, nullptr, emb, nullptr, out, B_, V_, H_);

    // 7) targets appended as float, if the output carries them
    if (out_size >= B_ * V_ + B_)
        write_targets<<<1, B_>>>(target, out + (size_t)B_ * V_);
}

// round 7
// speedup vs baseline: 2.0108x; 1.1726x over previous
#include <cuda_runtime.h>
#include <cuda_bf16.h>
#include <math.h>
#include <stdint.h>

// Problem constants (fixed by setup_inputs)
#define V_  100000
#define E_  256
#define H_  256
#define B_  256
#define S_  10
#define TC_ 20
#define TS_ 50
#define BC_ (B_ * S_)   // 2560
#define H3_ (3 * H_)    // 768

// ---------------- scratch (static device globals; no allocation) --------------
__device__ float g_gi_c[(size_t)BC_ * TC_ * H3_];
__device__ float g_gi_s[(size_t)B_ * TS_ * H3_];
__device__ float g_hA[BC_ * H_];
__device__ float g_hB[BC_ * H_];
__device__ float g_hsA[B_ * H_];
__device__ float g_hsB[B_ * H_];
__device__ float g_seq_cate[BC_ * H_];
__device__ float g_out_short[B_ * H_];
__device__ float g_sum_cate[B_ * H_];
__device__ float g_fc_out[B_ * H_];
__device__ int   g_order_c[BC_];
__device__ int   g_order_s[B_];
__device__ int   g_off_c[BC_ + 1];
__device__ int   g_off_s[B_ + 1];
__device__ int   g_tok_c[BC_ * TC_];
__device__ int   g_tok_s[B_ * TS_];
__device__ int   g_cnt_c[TS_ + 1];
__device__ int   g_cnt_s[TS_ + 1];
__device__ int   g_Mc[1];
__device__ int   g_Ms[1];
// bf16 hi/lo splits for tensor-core GEMMs
__device__ __nv_bfloat16 g_emb_hi[(size_t)V_ * E_];
__device__ __nv_bfloat16 g_emb_lo[(size_t)V_ * E_];
__device__ __nv_bfloat16 g_wc_hi[H3_ * E_];
__device__ __nv_bfloat16 g_wc_lo[H3_ * E_];
__device__ __nv_bfloat16 g_ws_hi[H3_ * E_];
__device__ __nv_bfloat16 g_ws_lo[H3_ * E_];
__device__ __nv_bfloat16 g_fc_hi[B_ * H_];
__device__ __nv_bfloat16 g_fc_lo[B_ * H_];

// ---------------- helpers ------------------------------------------------------
__device__ __forceinline__ float fast_sigmoid(float x) {
    return 1.f / (1.f + __expf(-x));
}
__device__ __forceinline__ float fast_tanh(float x) {
    float ax = fabsf(x);
    float e = __expf(-2.f * ax);
    float t = __fdividef(1.f - e, 1.f + e);
    return copysignf(t, x);
}
__device__ __forceinline__ uint32_t smem_u32(const void* p) {
    uint32_t a;
    asm("{ .reg .u64 t; cvta.to.shared.u64 t, %1; cvt.u32.u64 %0, t; }"
        : "=r"(a) : "l"(p));
    return a;
}
__device__ __forceinline__ void ldsm4(uint32_t& r0, uint32_t& r1, uint32_t& r2,
                                      uint32_t& r3, uint32_t addr) {
    asm volatile("ldmatrix.sync.aligned.m8n8.x4.shared.b16 {%0,%1,%2,%3}, [%4];"
                 : "=r"(r0), "=r"(r1), "=r"(r2), "=r"(r3) : "r"(addr));
}
__device__ __forceinline__ void mma16816(float* d, const uint32_t* a,
                                         uint32_t b0, uint32_t b1) {
    asm volatile(
        "mma.sync.aligned.m16n8k16.row.col.f32.bf16.bf16.f32 "
        "{%0,%1,%2,%3}, {%4,%5,%6,%7}, {%8,%9}, {%0,%1,%2,%3};"
        : "+f"(d[0]), "+f"(d[1]), "+f"(d[2]), "+f"(d[3])
        : "r"(a[0]), "r"(a[1]), "r"(a[2]), "r"(a[3]), "r"(b0), "r"(b1));
}

// ---------------- fp32 -> bf16 hi/lo split ------------------------------------
__global__ void split_kernel(const float* __restrict__ src,
                             __nv_bfloat16* __restrict__ hi,
                             __nv_bfloat16* __restrict__ lo, int n)
{
    int i = (blockIdx.x * 256 + threadIdx.x) * 4;
    const int stride = gridDim.x * 256 * 4;
    for (; i < n; i += stride) {
        float4 v = *(const float4*)(src + i);
        __nv_bfloat16 h0 = __float2bfloat16(v.x);
        __nv_bfloat16 h1 = __float2bfloat16(v.y);
        __nv_bfloat16 h2 = __float2bfloat16(v.z);
        __nv_bfloat16 h3 = __float2bfloat16(v.w);
        __nv_bfloat16 l0 = __float2bfloat16(v.x - __bfloat162float(h0));
        __nv_bfloat16 l1 = __float2bfloat16(v.y - __bfloat162float(h1));
        __nv_bfloat16 l2 = __float2bfloat16(v.z - __bfloat162float(h2));
        __nv_bfloat16 l3 = __float2bfloat16(v.w - __bfloat162float(h3));
        ((__nv_bfloat162*)(hi + i))[0] = __nv_bfloat162(h0, h1);
        ((__nv_bfloat162*)(hi + i))[1] = __nv_bfloat162(h2, h3);
        ((__nv_bfloat162*)(lo + i))[0] = __nv_bfloat162(l0, l1);
        ((__nv_bfloat162*)(lo + i))[1] = __nv_bfloat162(l2, l3);
    }
}

// ---------------- prep: counting sort desc, prefix offsets, token compaction --
__global__ void prep_kernel(const int* __restrict__ slen_c, const int* __restrict__ tokens_c,
                            const int* __restrict__ slen_s, const int* __restrict__ tokens_s)
{
    __shared__ int hist[64];
    __shared__ int base[64];
    __shared__ int ssum[256];
    const int tid = threadIdx.x;

    if (tid < 64) hist[tid] = 0;
    __syncthreads();
    for (int i = tid; i < BC_; i += 256) atomicAdd(&hist[slen_c[i]], 1);
    __syncthreads();
    if (tid <= TS_) {
        int c = 0;
        if (tid < 64) for (int k = tid; k < 64; k++) c += hist[k];
        g_cnt_c[tid] = (tid < TC_) ? c : 0;
    }
    if (tid == 0) {
        int run = 0;
        for (int k = 63; k >= 0; k--) { base[k] = run; run += hist[k]; }
    }
    __syncthreads();
    for (int i = tid; i < BC_; i += 256) {
        int pos = atomicAdd(&base[slen_c[i]], 1);
        g_order_c[pos] = i;
    }
    {
        const int chunk = BC_ / 256;
        int s = 0;
        for (int i = 0; i < chunk; i++) s += slen_c[tid * chunk + i] + 1;
        ssum[tid] = s;
        __syncthreads();
        for (int d = 1; d < 256; d <<= 1) {
            int v = (tid >= d) ? ssum[tid - d] : 0;
            __syncthreads();
            ssum[tid] += v;
            __syncthreads();
        }
        int run = (tid > 0) ? ssum[tid - 1] : 0;
        for (int i = 0; i < chunk; i++) {
            int b = tid * chunk + i;
            g_off_c[b] = run;
            run += slen_c[b] + 1;
        }
        if (tid == 255) { g_off_c[BC_] = ssum[255]; g_Mc[0] = ssum[255]; }
    }
    __syncthreads();
    for (int i = tid; i < BC_ * TC_; i += 256) {
        int b = i / TC_, t = i % TC_;
        if (t <= slen_c[b]) g_tok_c[g_off_c[b] + t] = tokens_c[i];
    }
    __syncthreads();

    if (tid < 64) hist[tid] = 0;
    __syncthreads();
    for (int i = tid; i < B_; i += 256) atomicAdd(&hist[slen_s[i]], 1);
    __syncthreads();
    if (tid <= TS_) {
        int c = 0;
        if (tid < 64) for (int k = tid; k < 64; k++) c += hist[k];
        g_cnt_s[tid] = (tid < TS_) ? c : 0;
    }
    if (tid == 0) {
        int run = 0;
        for (int k = 63; k >= 0; k--) { base[k] = run; run += hist[k]; }
    }
    __syncthreads();
    for (int i = tid; i < B_; i += 256) {
        int pos = atomicAdd(&base[slen_s[i]], 1);
        g_order_s[pos] = i;
    }
    {
        int s = (tid < B_) ? slen_s[tid] + 1 : 0;
        ssum[tid] = s;
        __syncthreads();
        for (int d = 1; d < 256; d <<= 1) {
            int v = (tid >= d) ? ssum[tid - d] : 0;
            __syncthreads();
            ssum[tid] += v;
            __syncthreads();
        }
        if (tid < B_) g_off_s[tid] = ssum[tid] - (slen_s[tid] + 1);
        if (tid == 255) { g_off_s[B_] = ssum[255]; g_Ms[0] = ssum[255]; }
    }
    __syncthreads();
    for (int i = tid; i < B_ * TS_; i += 256) {
        int b = i / TS_, t = i % TS_;
        if (t <= slen_s[b]) g_tok_s[g_off_s[b] + t] = tokens_s[i];
    }
}

// ---------------- bf16-split HMMA GEMM (mma.sync, arch-neutral) ---------------
// C[m,n] = sum_k A(m)[k]*B(n)[k] + bias[n] via Ah*Bh + Ah*Bl + Al*Bh.
// NT layout (both K-contiguous). K=256 fixed. 128x128 CTA tile, BK=64,
// 8 warps (2m x 4n), each 64x32 via m16n8k16. A rows gathered through idx.
#define STRIDE_ 72              // padded bf16 row stride: conflict-free ldmatrix
#define GTILE_  (128 * STRIDE_) // elements per smem tile
#define GEMM_SMEM (4 * GTILE_ * 2)

__global__ void __launch_bounds__(256, 2) gemm_mma(
    const __nv_bfloat16* __restrict__ Ah, const __nv_bfloat16* __restrict__ Al,
    const int* __restrict__ idx, const int* __restrict__ Mdev,
    const __nv_bfloat16* __restrict__ Bh, const __nv_bfloat16* __restrict__ Bl,
    const float* __restrict__ bias, float* __restrict__ C, int M, int N)
{
    extern __shared__ __align__(16) __nv_bfloat16 smem[];
    const int Mq = Mdev ? *Mdev : M;
    const int bm = blockIdx.x * 128, bn = blockIdx.y * 128;
    if (bm >= Mq) return;
    const int tid = threadIdx.x, wid = tid >> 5, lane = tid & 31;
    const int warp_m = wid & 1, warp_n = wid >> 1;

    __nv_bfloat16* sAh = smem;
    __nv_bfloat16* sAl = smem + GTILE_;
    __nv_bfloat16* sBh = smem + 2 * GTILE_;
    __nv_bfloat16* sBl = smem + 3 * GTILE_;
    const uint32_t uAh = smem_u32(sAh), uAl = smem_u32(sAl);
    const uint32_t uBh = smem_u32(sBh), uBl = smem_u32(sBl);

    // load lane geometry
    const int lrow = tid >> 3;         // 0..31 (x4 rows per pass of 256 thr? no: id>>3)
    (void)lrow;

    // fragment lane geometry
    const int fr = lane & 15;          // ldmatrix row within 16
    const int fc = (lane >> 4) * 8;    // 8-elem col half
    const int arow_f = warp_m * 64 + fr;
    const int brow_f = warp_n * 32 + fr;

    float acc[4][4][4];
#pragma unroll
    for (int i = 0; i < 4; i++)
#pragma unroll
        for (int j = 0; j < 4; j++)
#pragma unroll
            for (int e = 0; e < 4; e++) acc[i][j][e] = 0.f;

    for (int kt = 0; kt < 4; kt++) {
        if (kt) __syncthreads();
        // stage 128x64 of each operand tile
#pragma unroll
        for (int i = 0; i < 4; i++) {
            const int id = i * 256 + tid;
            const int row = id >> 3, ch = id & 7;
            const int col = kt * 64 + ch * 8;
            int am = bm + row; if (am > Mq - 1) am = Mq - 1;
            const int ar = idx ? idx[am] : am;
            int br = bn + row; if (br > N - 1) br = N - 1;
            const int so = row * STRIDE_ + ch * 8;
            *(uint4*)(sAh + so) = *(const uint4*)(Ah + (size_t)ar * 256 + col);
            *(uint4*)(sAl + so) = *(const uint4*)(Al + (size_t)ar * 256 + col);
            *(uint4*)(sBh + so) = *(const uint4*)(Bh + (size_t)br * 256 + col);
            *(uint4*)(sBl + so) = *(const uint4*)(Bl + (size_t)br * 256 + col);
        }
        __syncthreads();

#pragma unroll
        for (int kk = 0; kk < 4; kk++) {
            const int col = kk * 16 + fc;
            uint32_t bh[2][4], bl[2][4], av[4][4];
#pragma unroll
            for (int p = 0; p < 2; p++) {
                const uint32_t off = 2u * ((brow_f + p * 16) * STRIDE_ + col);
                ldsm4(bh[p][0], bh[p][1], bh[p][2], bh[p][3], uBh + off);
                ldsm4(bl[p][0], bl[p][1], bl[p][2], bl[p][3], uBl + off);
            }
#pragma unroll
            for (int tm = 0; tm < 4; tm++) {
                const uint32_t off = 2u * ((arow_f + tm * 16) * STRIDE_ + col);
                ldsm4(av[tm][0], av[tm][1], av[tm][2], av[tm][3], uAh + off);
            }
#pragma unroll
            for (int tm = 0; tm < 4; tm++)
#pragma unroll
                for (int tn = 0; tn < 4; tn++) {
                    const int p = tn >> 1, o = tn & 1;
                    mma16816(acc[tm][tn], av[tm], bh[p][o], bh[p][o + 2]);
                    mma16816(acc[tm][tn], av[tm], bl[p][o], bl[p][o + 2]);
                }
#pragma unroll
            for (int tm = 0; tm < 4; tm++) {
                const uint32_t off = 2u * ((arow_f + tm * 16) * STRIDE_ + col);
                ldsm4(av[tm][0], av[tm][1], av[tm][2], av[tm][3], uAl + off);
            }
#pragma unroll
            for (int tm = 0; tm < 4; tm++)
#pragma unroll
                for (int tn = 0; tn < 4; tn++) {
                    const int p = tn >> 1, o = tn & 1;
                    mma16816(acc[tm][tn], av[tm], bh[p][o], bh[p][o + 2]);
                }
        }
    }

    // epilogue
    const int mrow = bm + warp_m * 64 + (lane >> 2);
    const int ncol = bn + warp_n * 32 + (lane & 3) * 2;
#pragma unroll
    for (int tm = 0; tm < 4; tm++) {
#pragma unroll
        for (int half = 0; half < 2; half++) {
            const int m = mrow + tm * 16 + half * 8;
            if (m >= Mq) continue;
            float* crow = C + (size_t)m * N;
#pragma unroll
            for (int tn = 0; tn < 4; tn++) {
                const int n0 = ncol + tn * 8;
                const float v0 = acc[tm][tn][half * 2 + 0]
                               + (bias ? bias[n0] : 0.f);
                if (n0 + 1 < N) {
                    const float v1 = acc[tm][tn][half * 2 + 1]
                                   + (bias ? bias[n0 + 1] : 0.f);
                    *(float2*)(crow + n0) = make_float2(v0, v1);
                } else if (n0 < N) {
                    crow[n0] = v0;
                }
            }
        }
    }
}

// ---------------- fused dual GRU step (cat + short in one launch) -------------
#define CATBX 40
__device__ __forceinline__ void gru_tile(
    const float* __restrict__ Whh, const float* __restrict__ bhh,
    const float* __restrict__ gi,  const int* __restrict__ off,
    const int* __restrict__ order, const int* __restrict__ slen,
    const float* __restrict__ mask, int maskT,
    const float* __restrict__ h_in, float* __restrict__ h_out,
    float* __restrict__ gathered, int t, int active, int bx)
{
    __shared__ float Hs[16][64];
    __shared__ float Ws[3][16][64];
    const int tid = threadIdx.x;
    const int bm = bx * 64;
    const int bj = blockIdx.y * 64;
    const int lr = tid >> 2;
    const int lk = (tid & 3) * 4;
    const int tx = tid & 15, ty = tid >> 4;
    const int tm0 = ty * 4, tn0 = tx * 4;

    float ar[4][4] = {}, az[4][4] = {}, an[4][4] = {};

    const int slot_l = bm + lr;
    const int row_l = order[(slot_l < active) ? slot_l : (active - 1)];

    if (t > 0) {
        const float* hrow = h_in + (size_t)row_l * H_;
        const float* w0 = Whh + (size_t)(0 * H_ + bj + lr) * H_;
        const float* w1 = Whh + (size_t)(1 * H_ + bj + lr) * H_;
        const float* w2 = Whh + (size_t)(2 * H_ + bj + lr) * H_;
        for (int k0 = 0; k0 < H_; k0 += 16) {
            float4 hv = *(const float4*)(hrow + k0 + lk);
            float4 v0 = *(const float4*)(w0 + k0 + lk);
            float4 v1 = *(const float4*)(w1 + k0 + lk);
            float4 v2 = *(const float4*)(w2 + k0 + lk);
            Hs[lk + 0][lr] = hv.x; Hs[lk + 1][lr] = hv.y;
            Hs[lk + 2][lr] = hv.z; Hs[lk + 3][lr] = hv.w;
            Ws[0][lk + 0][lr] = v0.x; Ws[0][lk + 1][lr] = v0.y;
            Ws[0][lk + 2][lr] = v0.z; Ws[0][lk + 3][lr] = v0.w;
            Ws[1][lk + 0][lr] = v1.x; Ws[1][lk + 1][lr] = v1.y;
            Ws[1][lk + 2][lr] = v1.z; Ws[1][lk + 3][lr] = v1.w;
            Ws[2][lk + 0][lr] = v2.x; Ws[2][lk + 1][lr] = v2.y;
            Ws[2][lk + 2][lr] = v2.z; Ws[2][lk + 3][lr] = v2.w;
            __syncthreads();
#pragma unroll
            for (int k = 0; k < 16; k++) {
                float4 h4 = *(const float4*)&Hs[k][tm0];
                float4 r4 = *(const float4*)&Ws[0][k][tn0];
                float4 z4 = *(const float4*)&Ws[1][k][tn0];
                float4 n4 = *(const float4*)&Ws[2][k][tn0];
                float hm[4] = {h4.x, h4.y, h4.z, h4.w};
                float rr[4] = {r4.x, r4.y, r4.z, r4.w};
                float zz[4] = {z4.x, z4.y, z4.z, z4.w};
                float nn[4] = {n4.x, n4.y, n4.z, n4.w};
#pragma unroll
                for (int i = 0; i < 4; i++)
#pragma unroll
                    for (int j = 0; j < 4; j++) {
                        ar[i][j] += hm[i] * rr[j];
                        az[i][j] += hm[i] * zz[j];
                        an[i][j] += hm[i] * nn[j];
                    }
            }
            __syncthreads();
        }
    }

#pragma unroll
    for (int i = 0; i < 4; i++) {
        const int slot = bm + tm0 + i;
        if (slot >= active) continue;
        const int b = order[slot];
        const float* girow = gi + ((size_t)(off[b] + t)) * H3_;
        const bool take = (slen[b] == t);
        const float mval = mask[(size_t)b * maskT + t];
#pragma unroll
        for (int j = 0; j < 4; j++) {
            const int jj = bj + tn0 + j;
            const float gr = girow[jj];
            const float gz = girow[H_ + jj];
            const float gn = girow[2 * H_ + jj];
            const float hr = ar[i][j] + bhh[jj];
            const float hz = az[i][j] + bhh[H_ + jj];
            const float hn = an[i][j] + bhh[2 * H_ + jj];
            const float hold = (t > 0) ? h_in[(size_t)b * H_ + jj] : 0.f;
            const float r = fast_sigmoid(gr + hr);
            const float z = fast_sigmoid(gz + hz);
            const float n = fast_tanh(gn + r * hn);
            const float hnew = (1.f - z) * n + z * hold;
            h_out[(size_t)b * H_ + jj] = hnew;
            if (take) gathered[(size_t)b * H_ + jj] = hnew * mval;
        }
    }
}

__global__ void __launch_bounds__(256) gru_dual_step(
    const float* Whh_c, const float* bhh_c, const float* gi_c,
    const float* h_in_c, float* h_out_c, const float* mask_c, float* gath_c,
    const int* slen_c,
    const float* Whh_s, const float* bhh_s, const float* gi_s,
    const float* h_in_s, float* h_out_s, const float* mask_s, float* gath_s,
    const int* slen_s, int t)
{
    if ((int)blockIdx.x < CATBX) {
        const int active = g_cnt_c[t];
        if (blockIdx.x * 64 >= (unsigned)active) return;
        gru_tile(Whh_c, bhh_c, gi_c, g_off_c, g_order_c, slen_c, mask_c, TC_,
                 h_in_c, h_out_c, gath_c, t, active, blockIdx.x);
    } else {
        const int bx = blockIdx.x - CATBX;
        const int active = g_cnt_s[t];
        if (bx * 64 >= active) return;
        gru_tile(Whh_s, bhh_s, gi_s, g_off_s, g_order_s, slen_s, mask_s, TS_,
                 h_in_s, h_out_s, gath_s, t, active, bx);
    }
}

// ---------------- attention ----------------------------------------------------
__global__ void attention_kernel(const float* __restrict__ seq_cate,
                                 const float* __restrict__ out_short,
                                 const float* __restrict__ mask_seq,
                                 float* __restrict__ sum_cate)
{
    const int b = blockIdx.x;
    const int j = threadIdx.x;
    __shared__ float red[8];
    __shared__ float w[S_];
    const float os = out_short[(size_t)b * H_ + j];
    float sc[S_];
#pragma unroll
    for (int s = 0; s < S_; s++)
        sc[s] = seq_cate[(size_t)(b * S_ + s) * H_ + j];

    for (int s = 0; s < S_; s++) {
        float v = sc[s] * os;
#pragma unroll
        for (int off = 16; off; off >>= 1) v += __shfl_xor_sync(0xffffffffu, v, off);
        if ((j & 31) == 0) red[j >> 5] = v;
        __syncthreads();
        if (j == 0) {
            float x = 0.f;
#pragma unroll
            for (int q = 0; q < 8; q++) x += red[q];
            w[s] = x;
        }
        __syncthreads();
    }
    if (j == 0) {
        float mx = w[0];
        for (int s = 1; s < S_; s++) mx = fmaxf(mx, w[s]);
        float e[S_];
        float sum = 0.f;
        for (int s = 0; s < S_; s++) { e[s] = expf(w[s] - mx); sum += e[s]; }
        float s2 = 0.f;
        for (int s = 0; s < S_; s++) {
            e[s] = (e[s] / sum) * mask_seq[(size_t)b * S_ + s];
            s2 += e[s];
        }
        for (int s = 0; s < S_; s++) w[s] = e[s] / s2;
    }
    __syncthreads();
    float acc = 0.f;
#pragma unroll
    for (int s = 0; s < S_; s++) acc += w[s] * sc[s];
    sum_cate[(size_t)b * H_ + j] = acc;
}

// ---------------- FC -----------------------------------------------------------
__global__ void fc_kernel(const float* __restrict__ sum_cate,
                          const float* __restrict__ out_short,
                          const float* __restrict__ fcW,
                          const float* __restrict__ fcb,
                          float* __restrict__ fc_out)
{
    __shared__ float mix[16][2 * H_];
    const int b0 = blockIdx.x * 16;
    for (int idx = threadIdx.x; idx < 16 * 2 * H_; idx += 256) {
        const int bb = idx >> 9, k = idx & 511;
        mix[bb][k] = (k < H_) ? sum_cate[(size_t)(b0 + bb) * H_ + k]
                              : out_short[(size_t)(b0 + bb) * H_ + (k - H_)];
    }
    __syncthreads();
    const int i = threadIdx.x;
    const float* wrow = fcW + (size_t)i * (2 * H_);
    float acc[16];
#pragma unroll
    for (int bb = 0; bb < 16; bb++) acc[bb] = 0.f;
    for (int k = 0; k < 2 * H_; k++) {
        const float wv = wrow[k];
#pragma unroll
        for (int bb = 0; bb < 16; bb++) acc[bb] += wv * mix[bb][k];
    }
    const float bias = fcb[i];
#pragma unroll
    for (int bb = 0; bb < 16; bb++)
        fc_out[(size_t)(b0 + bb) * H_ + i] = acc[bb] + bias;
}

__global__ void write_targets(const int* __restrict__ tgt, float* __restrict__ out)
{
    out[threadIdx.x] = (float)tgt[threadIdx.x];
}

// ---------------- launcher ----------------------------------------------------
extern "C" void kernel_launch(void* const* d_in, const int* in_sizes, int n_in,
                              void* d_out, int out_size)
{
    const int*   in_cate       = (const int*)d_in[0];
    const float* mask_cate     = (const float*)d_in[1];
    const float* mask_cate_seq = (const float*)d_in[2];
    const int*   subseqLen     = (const int*)d_in[5];
    const int*   in_batch      = (const int*)d_in[7];
    const float* mask_b        = (const float*)d_in[8];
    const int*   seqLen        = (const int*)d_in[9];
    const int*   target        = (const int*)d_in[10];
    const float* emb           = (const float*)d_in[12];
    const float* Wih_c         = (const float*)d_in[13];
    const float* Whh_c         = (const float*)d_in[14];
    const float* bih_c         = (const float*)d_in[15];
    const float* bhh_c         = (const float*)d_in[16];
    const float* Wih_s         = (const float*)d_in[17];
    const float* Whh_s         = (const float*)d_in[18];
    const float* bih_s         = (const float*)d_in[19];
    const float* bhh_s         = (const float*)d_in[20];
    const float* fc_W          = (const float*)d_in[21];
    const float* fc_b          = (const float*)d_in[22];
    float* out = (float*)d_out;

    float *gi_c, *gi_s, *hA, *hB, *hsA, *hsB, *seqc, *osht, *sumc, *fco;
    int *tok_c, *tok_s, *Mc, *Ms;
    __nv_bfloat16 *emb_hi, *emb_lo, *wc_hi, *wc_lo, *ws_hi, *ws_lo, *fc_hi, *fc_lo;
    cudaGetSymbolAddress((void**)&gi_c, g_gi_c);
    cudaGetSymbolAddress((void**)&gi_s, g_gi_s);
    cudaGetSymbolAddress((void**)&hA,  g_hA);
    cudaGetSymbolAddress((void**)&hB,  g_hB);
    cudaGetSymbolAddress((void**)&hsA, g_hsA);
    cudaGetSymbolAddress((void**)&hsB, g_hsB);
    cudaGetSymbolAddress((void**)&seqc, g_seq_cate);
    cudaGetSymbolAddress((void**)&osht, g_out_short);
    cudaGetSymbolAddress((void**)&sumc, g_sum_cate);
    cudaGetSymbolAddress((void**)&fco,  g_fc_out);
    cudaGetSymbolAddress((void**)&tok_c, g_tok_c);
    cudaGetSymbolAddress((void**)&tok_s, g_tok_s);
    cudaGetSymbolAddress((void**)&Mc, g_Mc);
    cudaGetSymbolAddress((void**)&Ms, g_Ms);
    cudaGetSymbolAddress((void**)&emb_hi, g_emb_hi);
    cudaGetSymbolAddress((void**)&emb_lo, g_emb_lo);
    cudaGetSymbolAddress((void**)&wc_hi, g_wc_hi);
    cudaGetSymbolAddress((void**)&wc_lo, g_wc_lo);
    cudaGetSymbolAddress((void**)&ws_hi, g_ws_hi);
    cudaGetSymbolAddress((void**)&ws_lo, g_ws_lo);
    cudaGetSymbolAddress((void**)&fc_hi, g_fc_hi);
    cudaGetSymbolAddress((void**)&fc_lo, g_fc_lo);

    cudaFuncSetAttribute(gemm_mma, cudaFuncAttributeMaxDynamicSharedMemorySize,
                         GEMM_SMEM);

    // 0) prep + bf16 splits
    prep_kernel<<<1, 256>>>(subseqLen, in_cate, seqLen, in_batch);
    split_kernel<<<8192, 256>>>(emb, emb_hi, emb_lo, V_ * E_);
    split_kernel<<<192, 256>>>(Wih_c, wc_hi, wc_lo, H3_ * E_);
    split_kernel<<<192, 256>>>(Wih_s, ws_hi, ws_lo, H3_ * E_);

    // 1) input-gate GEMMs over compacted tokens (HMMA tensor cores)
    gemm_mma<<<dim3((BC_ * TC_ + 127) / 128, H3_ / 128), 256, GEMM_SMEM>>>(
        emb_hi, emb_lo, tok_c, Mc, wc_hi, wc_lo, bih_c, gi_c, BC_ * TC_, H3_);
    gemm_mma<<<dim3((B_ * TS_ + 127) / 128, H3_ / 128), 256, GEMM_SMEM>>>(
        emb_hi, emb_lo, tok_s, Ms, ws_hi, ws_lo, bih_s, gi_s, B_ * TS_, H3_);

    // 2+3) fused GRU scans: 50 dual-step launches (cat active for t<20)
    {
        float *hc_in = hA, *hc_out = hB, *hs_in = hsA, *hs_out = hsB;
        for (int t = 0; t < TS_; t++) {
            gru_dual_step<<<dim3(CATBX + B_ / 64, H_ / 64), 256>>>(
                Whh_c, bhh_c, gi_c, hc_in, hc_out, mask_cate, seqc, subseqLen,
                Whh_s, bhh_s, gi_s, hs_in, hs_out, mask_b, osht, seqLen, t);
            float* tmp;
            tmp = hc_in; hc_in = hc_out; hc_out = tmp;
            tmp = hs_in; hs_in = hs_out; hs_out = tmp;
        }
    }

    // 4) attention + 5) FC (+ split fc_out for tensor-core logits)
    attention_kernel<<<B_, 256>>>(seqc, osht, mask_cate_seq, sumc);
    fc_kernel<<<B_ / 16, 256>>>(sumc, osht, fc_W, fc_b, fco);
    split_kernel<<<64, 256>>>(fco, fc_hi, fc_lo, B_ * H_);

    // 6) logits = fc_out @ emb^T (HMMA tensor cores)
    gemm_mma<<<dim3(B_ / 128, (V_ + 127) / 128), 256, GEMM_SMEM>>>(
        fc_hi, fc_lo, nullptr, nullptr, emb_hi, emb_lo, nullptr, out, B_, V_);

    // 7) targets appended as float, if the output carries them
    if (out_size >= B_ * V_ + B_)
        write_targets<<<1, B_>>>(target, out + (size_t)B_ * V_);
}

// round 8
// speedup vs baseline: 2.7990x; 1.3920x over previous
#include <cuda_runtime.h>
#include <cuda_bf16.h>
#include <math.h>
#include <stdint.h>

// Problem constants (fixed by setup_inputs)
#define V_  100000
#define E_  256
#define H_  256
#define B_  256
#define S_  10
#define TC_ 20
#define TS_ 50
#define BC_ (B_ * S_)   // 2560
#define H3_ (3 * H_)    // 768

// ---------------- scratch (static device globals; no allocation) --------------
__device__ float g_gi_c[(size_t)BC_ * TC_ * H3_];
__device__ float g_gi_s[(size_t)B_ * TS_ * H3_];
__device__ float g_hA[BC_ * H_];
__device__ float g_hB[BC_ * H_];
__device__ float g_hsA[B_ * H_];
__device__ float g_hsB[B_ * H_];
__device__ float g_seq_cate[BC_ * H_];
__device__ float g_out_short[B_ * H_];
__device__ float g_sum_cate[B_ * H_];
__device__ float g_fc_out[B_ * H_];
__device__ int   g_order_c[BC_];
__device__ int   g_order_s[B_];
__device__ int   g_off_c[BC_ + 1];
__device__ int   g_off_s[B_ + 1];
__device__ int   g_tok_c[BC_ * TC_];
__device__ int   g_tok_s[B_ * TS_];
__device__ int   g_cnt_c[TS_ + 1];
__device__ int   g_cnt_s[TS_ + 1];
__device__ int   g_Mc[1];
__device__ int   g_Ms[1];
// bf16 hi/lo splits for tensor-core GEMMs
__device__ __nv_bfloat16 g_emb_hi[(size_t)V_ * E_];
__device__ __nv_bfloat16 g_emb_lo[(size_t)V_ * E_];
__device__ __nv_bfloat16 g_wc_hi[H3_ * E_];
__device__ __nv_bfloat16 g_wc_lo[H3_ * E_];
__device__ __nv_bfloat16 g_ws_hi[H3_ * E_];
__device__ __nv_bfloat16 g_ws_lo[H3_ * E_];
__device__ __nv_bfloat16 g_fc_hi[B_ * H_];
__device__ __nv_bfloat16 g_fc_lo[B_ * H_];
__device__ __nv_bfloat16 g_whc_hi[H3_ * H_];
__device__ __nv_bfloat16 g_whc_lo[H3_ * H_];
__device__ __nv_bfloat16 g_whs_hi[H3_ * H_];
__device__ __nv_bfloat16 g_whs_lo[H3_ * H_];

// ---------------- helpers ------------------------------------------------------
__device__ __forceinline__ float fast_sigmoid(float x) {
    return 1.f / (1.f + __expf(-x));
}
__device__ __forceinline__ float fast_tanh(float x) {
    float ax = fabsf(x);
    float e = __expf(-2.f * ax);
    float t = __fdividef(1.f - e, 1.f + e);
    return copysignf(t, x);
}
__device__ __forceinline__ uint32_t smem_u32(const void* p) {
    uint32_t a;
    asm("{ .reg .u64 t; cvta.to.shared.u64 t, %1; cvt.u32.u64 %0, t; }"
        : "=r"(a) : "l"(p));
    return a;
}
__device__ __forceinline__ void ldsm4(uint32_t& r0, uint32_t& r1, uint32_t& r2,
                                      uint32_t& r3, uint32_t addr) {
    asm volatile("ldmatrix.sync.aligned.m8n8.x4.shared.b16 {%0,%1,%2,%3}, [%4];"
                 : "=r"(r0), "=r"(r1), "=r"(r2), "=r"(r3) : "r"(addr));
}
__device__ __forceinline__ void mma16816(float* d, const uint32_t* a,
                                         uint32_t b0, uint32_t b1) {
    asm volatile(
        "mma.sync.aligned.m16n8k16.row.col.f32.bf16.bf16.f32 "
        "{%0,%1,%2,%3}, {%4,%5,%6,%7}, {%8,%9}, {%0,%1,%2,%3};"
        : "+f"(d[0]), "+f"(d[1]), "+f"(d[2]), "+f"(d[3])
        : "r"(a[0]), "r"(a[1]), "r"(a[2]), "r"(a[3]), "r"(b0), "r"(b1));
}

// ---------------- fp32 -> bf16 hi/lo split ------------------------------------
__global__ void split_kernel(const float* __restrict__ src,
                             __nv_bfloat16* __restrict__ hi,
                             __nv_bfloat16* __restrict__ lo, int n)
{
    int i = (blockIdx.x * 256 + threadIdx.x) * 4;
    const int stride = gridDim.x * 256 * 4;
    for (; i < n; i += stride) {
        float4 v = *(const float4*)(src + i);
        __nv_bfloat16 h0 = __float2bfloat16(v.x);
        __nv_bfloat16 h1 = __float2bfloat16(v.y);
        __nv_bfloat16 h2 = __float2bfloat16(v.z);
        __nv_bfloat16 h3 = __float2bfloat16(v.w);
        __nv_bfloat16 l0 = __float2bfloat16(v.x - __bfloat162float(h0));
        __nv_bfloat16 l1 = __float2bfloat16(v.y - __bfloat162float(h1));
        __nv_bfloat16 l2 = __float2bfloat16(v.z - __bfloat162float(h2));
        __nv_bfloat16 l3 = __float2bfloat16(v.w - __bfloat162float(h3));
        ((__nv_bfloat162*)(hi + i))[0] = __nv_bfloat162(h0, h1);
        ((__nv_bfloat162*)(hi + i))[1] = __nv_bfloat162(h2, h3);
        ((__nv_bfloat162*)(lo + i))[0] = __nv_bfloat162(l0, l1);
        ((__nv_bfloat162*)(lo + i))[1] = __nv_bfloat162(l2, l3);
    }
}

// ---------------- prep: counting sort desc, prefix offsets, token compaction --
__global__ void prep_kernel(const int* __restrict__ slen_c, const int* __restrict__ tokens_c,
                            const int* __restrict__ slen_s, const int* __restrict__ tokens_s)
{
    __shared__ int hist[64];
    __shared__ int base[64];
    __shared__ int ssum[256];
    const int tid = threadIdx.x;

    if (tid < 64) hist[tid] = 0;
    __syncthreads();
    for (int i = tid; i < BC_; i += 256) atomicAdd(&hist[slen_c[i]], 1);
    __syncthreads();
    if (tid <= TS_) {
        int c = 0;
        if (tid < 64) for (int k = tid; k < 64; k++) c += hist[k];
        g_cnt_c[tid] = (tid < TC_) ? c : 0;
    }
    if (tid == 0) {
        int run = 0;
        for (int k = 63; k >= 0; k--) { base[k] = run; run += hist[k]; }
    }
    __syncthreads();
    for (int i = tid; i < BC_; i += 256) {
        int pos = atomicAdd(&base[slen_c[i]], 1);
        g_order_c[pos] = i;
    }
    {
        const int chunk = BC_ / 256;
        int s = 0;
        for (int i = 0; i < chunk; i++) s += slen_c[tid * chunk + i] + 1;
        ssum[tid] = s;
        __syncthreads();
        for (int d = 1; d < 256; d <<= 1) {
            int v = (tid >= d) ? ssum[tid - d] : 0;
            __syncthreads();
            ssum[tid] += v;
            __syncthreads();
        }
        int run = (tid > 0) ? ssum[tid - 1] : 0;
        for (int i = 0; i < chunk; i++) {
            int b = tid * chunk + i;
            g_off_c[b] = run;
            run += slen_c[b] + 1;
        }
        if (tid == 255) { g_off_c[BC_] = ssum[255]; g_Mc[0] = ssum[255]; }
    }
    __syncthreads();
    for (int i = tid; i < BC_ * TC_; i += 256) {
        int b = i / TC_, t = i % TC_;
        if (t <= slen_c[b]) g_tok_c[g_off_c[b] + t] = tokens_c[i];
    }
    __syncthreads();

    if (tid < 64) hist[tid] = 0;
    __syncthreads();
    for (int i = tid; i < B_; i += 256) atomicAdd(&hist[slen_s[i]], 1);
    __syncthreads();
    if (tid <= TS_) {
        int c = 0;
        if (tid < 64) for (int k = tid; k < 64; k++) c += hist[k];
        g_cnt_s[tid] = (tid < TS_) ? c : 0;
    }
    if (tid == 0) {
        int run = 0;
        for (int k = 63; k >= 0; k--) { base[k] = run; run += hist[k]; }
    }
    __syncthreads();
    for (int i = tid; i < B_; i += 256) {
        int pos = atomicAdd(&base[slen_s[i]], 1);
        g_order_s[pos] = i;
    }
    {
        int s = (tid < B_) ? slen_s[tid] + 1 : 0;
        ssum[tid] = s;
        __syncthreads();
        for (int d = 1; d < 256; d <<= 1) {
            int v = (tid >= d) ? ssum[tid - d] : 0;
            __syncthreads();
            ssum[tid] += v;
            __syncthreads();
        }
        if (tid < B_) g_off_s[tid] = ssum[tid] - (slen_s[tid] + 1);
        if (tid == 255) { g_off_s[B_] = ssum[255]; g_Ms[0] = ssum[255]; }
    }
    __syncthreads();
    for (int i = tid; i < B_ * TS_; i += 256) {
        int b = i / TS_, t = i % TS_;
        if (t <= slen_s[b]) g_tok_s[g_off_s[b] + t] = tokens_s[i];
    }
}

// ---------------- bf16-split HMMA GEMM (mma.sync, arch-neutral) ---------------
#define STRIDE_ 72
#define GTILE_  (128 * STRIDE_)
#define GEMM_SMEM (4 * GTILE_ * 2)

__global__ void __launch_bounds__(256, 2) gemm_mma(
    const __nv_bfloat16* __restrict__ Ah, const __nv_bfloat16* __restrict__ Al,
    const int* __restrict__ idx, const int* __restrict__ Mdev,
    const __nv_bfloat16* __restrict__ Bh, const __nv_bfloat16* __restrict__ Bl,
    const float* __restrict__ bias, float* __restrict__ C, int M, int N)
{
    extern __shared__ __align__(16) __nv_bfloat16 smem[];
    const int Mq = Mdev ? *Mdev : M;
    const int bm = blockIdx.x * 128, bn = blockIdx.y * 128;
    if (bm >= Mq) return;
    const int tid = threadIdx.x, wid = tid >> 5, lane = tid & 31;
    const int warp_m = wid & 1, warp_n = wid >> 1;

    __nv_bfloat16* sAh = smem;
    __nv_bfloat16* sAl = smem + GTILE_;
    __nv_bfloat16* sBh = smem + 2 * GTILE_;
    __nv_bfloat16* sBl = smem + 3 * GTILE_;
    const uint32_t uAh = smem_u32(sAh), uAl = smem_u32(sAl);
    const uint32_t uBh = smem_u32(sBh), uBl = smem_u32(sBl);

    const int fr = lane & 15;
    const int fc = (lane >> 4) * 8;
    const int arow_f = warp_m * 64 + fr;
    const int brow_f = warp_n * 32 + fr;

    float acc[4][4][4];
#pragma unroll
    for (int i = 0; i < 4; i++)
#pragma unroll
        for (int j = 0; j < 4; j++)
#pragma unroll
            for (int e = 0; e < 4; e++) acc[i][j][e] = 0.f;

    for (int kt = 0; kt < 4; kt++) {
        if (kt) __syncthreads();
#pragma unroll
        for (int i = 0; i < 4; i++) {
            const int id = i * 256 + tid;
            const int row = id >> 3, ch = id & 7;
            const int col = kt * 64 + ch * 8;
            int am = bm + row; if (am > Mq - 1) am = Mq - 1;
            const int ar = idx ? idx[am] : am;
            int br = bn + row; if (br > N - 1) br = N - 1;
            const int so = row * STRIDE_ + ch * 8;
            *(uint4*)(sAh + so) = *(const uint4*)(Ah + (size_t)ar * 256 + col);
            *(uint4*)(sAl + so) = *(const uint4*)(Al + (size_t)ar * 256 + col);
            *(uint4*)(sBh + so) = *(const uint4*)(Bh + (size_t)br * 256 + col);
            *(uint4*)(sBl + so) = *(const uint4*)(Bl + (size_t)br * 256 + col);
        }
        __syncthreads();

#pragma unroll
        for (int kk = 0; kk < 4; kk++) {
            const int col = kk * 16 + fc;
            uint32_t bh[2][4], bl[2][4], av[4][4];
#pragma unroll
            for (int p = 0; p < 2; p++) {
                const uint32_t off = 2u * ((brow_f + p * 16) * STRIDE_ + col);
                ldsm4(bh[p][0], bh[p][1], bh[p][2], bh[p][3], uBh + off);
                ldsm4(bl[p][0], bl[p][1], bl[p][2], bl[p][3], uBl + off);
            }
#pragma unroll
            for (int tm = 0; tm < 4; tm++) {
                const uint32_t off = 2u * ((arow_f + tm * 16) * STRIDE_ + col);
                ldsm4(av[tm][0], av[tm][1], av[tm][2], av[tm][3], uAh + off);
            }
#pragma unroll
            for (int tm = 0; tm < 4; tm++)
#pragma unroll
                for (int tn = 0; tn < 4; tn++) {
                    const int p = tn >> 1, o = tn & 1;
                    mma16816(acc[tm][tn], av[tm], bh[p][o], bh[p][o + 2]);
                    mma16816(acc[tm][tn], av[tm], bl[p][o], bl[p][o + 2]);
                }
#pragma unroll
            for (int tm = 0; tm < 4; tm++) {
                const uint32_t off = 2u * ((arow_f + tm * 16) * STRIDE_ + col);
                ldsm4(av[tm][0], av[tm][1], av[tm][2], av[tm][3], uAl + off);
            }
#pragma unroll
            for (int tm = 0; tm < 4; tm++)
#pragma unroll
                for (int tn = 0; tn < 4; tn++) {
                    const int p = tn >> 1, o = tn & 1;
                    mma16816(acc[tm][tn], av[tm], bh[p][o], bh[p][o + 2]);
                }
        }
    }

    const int mrow = bm + warp_m * 64 + (lane >> 2);
    const int ncol = bn + warp_n * 32 + (lane & 3) * 2;
#pragma unroll
    for (int tm = 0; tm < 4; tm++) {
#pragma unroll
        for (int half = 0; half < 2; half++) {
            const int m = mrow + tm * 16 + half * 8;
            if (m >= Mq) continue;
            float* crow = C + (size_t)m * N;
#pragma unroll
            for (int tn = 0; tn < 4; tn++) {
                const int n0 = ncol + tn * 8;
                const float v0 = acc[tm][tn][half * 2 + 0]
                               + (bias ? bias[n0] : 0.f);
                if (n0 + 1 < N) {
                    const float v1 = acc[tm][tn][half * 2 + 1]
                                   + (bias ? bias[n0 + 1] : 0.f);
                    *(float2*)(crow + n0) = make_float2(v0, v1);
                } else if (n0 < N) {
                    crow[n0] = v0;
                }
            }
        }
    }
}

// ---------------- HMMA fused dual GRU step ------------------------------------
// Block: 64 sorted slots x 64 j (grid.y = H/64). gh[64 x 192] (3 gates) via
// mma.sync 3-pass bf16 split: h staged+split on the fly, Whh pre-split.
// smem: sAh[64][72], sAl, sBh[192][72], sBl (bf16); sgh[64][192] f32 aliased.
#define CATBX 40
#define GRU_SA 4608             // 64*72
#define GRU_SB 13824            // 192*72
#define GRU_SMEM ((2 * GRU_SA + 2 * GRU_SB) * 2)   // 73728 bytes

__device__ __forceinline__ void gru_tile_mma(
    const __nv_bfloat16* __restrict__ Whi, const __nv_bfloat16* __restrict__ Wlo,
    const float* __restrict__ bhh,
    const float* __restrict__ gi,  const int* __restrict__ off,
    const int* __restrict__ order, const int* __restrict__ slen,
    const float* __restrict__ mask, int maskT,
    const float* __restrict__ h_in, float* __restrict__ h_out,
    float* __restrict__ gathered, int t, int active, int bx)
{
    extern __shared__ __align__(16) char gsm[];
    __nv_bfloat16* sAh = (__nv_bfloat16*)gsm;
    __nv_bfloat16* sAl = sAh + GRU_SA;
    __nv_bfloat16* sBh = sAl + GRU_SA;
    __nv_bfloat16* sBl = sBh + GRU_SB;
    float* sgh = (float*)gsm;          // aliased after MMA completes
    const uint32_t uAh = smem_u32(sAh), uAl = smem_u32(sAl);
    const uint32_t uBh = smem_u32(sBh), uBl = smem_u32(sBl);

    const int tid = threadIdx.x, wid = tid >> 5, lane = tid & 31;
    const int warp_m = wid & 1, warp_n = wid >> 1;   // 2 x 4
    const int bm = bx * 64;
    const int bj = blockIdx.y * 64;
    const int fr = lane & 15;
    const int fc = (lane >> 4) * 8;

    float acc[2][6][4];
#pragma unroll
    for (int i = 0; i < 2; i++)
#pragma unroll
        for (int j = 0; j < 6; j++)
#pragma unroll
            for (int e = 0; e < 4; e++) acc[i][j][e] = 0.f;

    if (t > 0) {
        for (int kt = 0; kt < 4; kt++) {
            if (kt) __syncthreads();
            // stage A: h rows, fp32 -> bf16 hi/lo split
#pragma unroll
            for (int i = 0; i < 4; i++) {
                const int id = i * 256 + tid;
                const int sl = id >> 4, c4 = id & 15;
                int gs = bm + sl; if (gs > active - 1) gs = active - 1;
                const int row = order[gs];
                float4 v = *(const float4*)(h_in + (size_t)row * 256 + kt * 64 + c4 * 4);
                __nv_bfloat16 h0 = __float2bfloat16(v.x);
                __nv_bfloat16 h1 = __float2bfloat16(v.y);
                __nv_bfloat16 h2 = __float2bfloat16(v.z);
                __nv_bfloat16 h3 = __float2bfloat16(v.w);
                const int so = sl * STRIDE_ + c4 * 4;
                *(__nv_bfloat162*)(sAh + so)     = __nv_bfloat162(h0, h1);
                *(__nv_bfloat162*)(sAh + so + 2) = __nv_bfloat162(h2, h3);
                *(__nv_bfloat162*)(sAl + so) =
                    __nv_bfloat162(__float2bfloat16(v.x - __bfloat162float(h0)),
                                   __float2bfloat16(v.y - __bfloat162float(h1)));
                *(__nv_bfloat162*)(sAl + so + 2) =
                    __nv_bfloat162(__float2bfloat16(v.z - __bfloat162float(h2)),
                                   __float2bfloat16(v.w - __bfloat162float(h3)));
            }
            // stage B: Whh gate rows (pre-split bf16)
#pragma unroll
            for (int i = 0; i < 6; i++) {
                const int id = i * 256 + tid;
                const int row = id >> 3, ch = id & 7;       // row 0..191
                const int g = row >> 6, j = row & 63;
                const int grow = g * 256 + bj + j;
                const int col = kt * 64 + ch * 8;
                const int so = row * STRIDE_ + ch * 8;
                *(uint4*)(sBh + so) = *(const uint4*)(Whi + (size_t)grow * 256 + col);
                *(uint4*)(sBl + so) = *(const uint4*)(Wlo + (size_t)grow * 256 + col);
            }
            __syncthreads();

#pragma unroll
            for (int kk = 0; kk < 4; kk++) {
                const int col = kk * 16 + fc;
                uint32_t bh[3][4], bl[3][4], avh[2][4], avl[2][4];
#pragma unroll
                for (int p = 0; p < 3; p++) {
                    const uint32_t o = 2u * ((warp_n * 48 + p * 16 + fr) * STRIDE_ + col);
                    ldsm4(bh[p][0], bh[p][1], bh[p][2], bh[p][3], uBh + o);
                    ldsm4(bl[p][0], bl[p][1], bl[p][2], bl[p][3], uBl + o);
                }
#pragma unroll
                for (int tm = 0; tm < 2; tm++) {
                    const uint32_t o = 2u * ((warp_m * 32 + tm * 16 + fr) * STRIDE_ + col);
                    ldsm4(avh[tm][0], avh[tm][1], avh[tm][2], avh[tm][3], uAh + o);
                    ldsm4(avl[tm][0], avl[tm][1], avl[tm][2], avl[tm][3], uAl + o);
                }
#pragma unroll
                for (int tm = 0; tm < 2; tm++)
#pragma unroll
                    for (int tn = 0; tn < 6; tn++) {
                        const int p = tn >> 1, o = tn & 1;
                        mma16816(acc[tm][tn], avh[tm], bh[p][o], bh[p][o + 2]);
                        mma16816(acc[tm][tn], avh[tm], bl[p][o], bl[p][o + 2]);
                        mma16816(acc[tm][tn], avl[tm], bh[p][o], bh[p][o + 2]);
                    }
            }
        }
        __syncthreads();
        // park fragments: sgh[slot][n], n in [0,192)
#pragma unroll
        for (int tm = 0; tm < 2; tm++)
#pragma unroll
            for (int tn = 0; tn < 6; tn++)
#pragma unroll
                for (int e = 0; e < 4; e++) {
                    const int m = warp_m * 32 + tm * 16 + (lane >> 2) + (e >> 1) * 8;
                    const int n = warp_n * 48 + tn * 8 + (lane & 3) * 2 + (e & 1);
                    sgh[m * 192 + n] = acc[tm][tn][e];
                }
        __syncthreads();
    }

    // epilogue: 64 slots x 64 j, 16 elements/thread
#pragma unroll
    for (int i = 0; i < 16; i++) {
        const int idx = i * 256 + tid;
        const int sl = idx >> 6, j = idx & 63;
        const int slot = bm + sl;
        if (slot >= active) continue;
        const int b = order[slot];
        const int jj = bj + j;
        const size_t gbase = ((size_t)(off[b] + t)) * H3_ + jj;
        const float gr = gi[gbase];
        const float gz = gi[gbase + H_];
        const float gn = gi[gbase + 2 * H_];
        const float ar = (t > 0) ? sgh[sl * 192 + j] : 0.f;
        const float az = (t > 0) ? sgh[sl * 192 + 64 + j] : 0.f;
        const float an = (t > 0) ? sgh[sl * 192 + 128 + j] : 0.f;
        const float hold = (t > 0) ? h_in[(size_t)b * H_ + jj] : 0.f;
        const float r = fast_sigmoid(gr + ar + bhh[jj]);
        const float z = fast_sigmoid(gz + az + bhh[H_ + jj]);
        const float n = fast_tanh(gn + r * (an + bhh[2 * H_ + jj]));
        const float hnew = (1.f - z) * n + z * hold;
        h_out[(size_t)b * H_ + jj] = hnew;
        if (slen[b] == t)
            gathered[(size_t)b * H_ + jj] = hnew * mask[(size_t)b * maskT + t];
    }
}

__global__ void __launch_bounds__(256) gru_dual_step(
    const __nv_bfloat16* Whi_c, const __nv_bfloat16* Wlo_c, const float* bhh_c,
    const float* gi_c, const float* h_in_c, float* h_out_c,
    const float* mask_c, float* gath_c, const int* slen_c,
    const __nv_bfloat16* Whi_s, const __nv_bfloat16* Wlo_s, const float* bhh_s,
    const float* gi_s, const float* h_in_s, float* h_out_s,
    const float* mask_s, float* gath_s, const int* slen_s, int t)
{
    if ((int)blockIdx.x < CATBX) {
        const int active = g_cnt_c[t];
        if (blockIdx.x * 64 >= (unsigned)active) return;
        gru_tile_mma(Whi_c, Wlo_c, bhh_c, gi_c, g_off_c, g_order_c, slen_c,
                     mask_c, TC_, h_in_c, h_out_c, gath_c, t, active, blockIdx.x);
    } else {
        const int bx = blockIdx.x - CATBX;
        const int active = g_cnt_s[t];
        if (bx * 64 >= active) return;
        gru_tile_mma(Whi_s, Wlo_s, bhh_s, gi_s, g_off_s, g_order_s, slen_s,
                     mask_s, TS_, h_in_s, h_out_s, gath_s, t, active, bx);
    }
}

// ---------------- attention ----------------------------------------------------
__global__ void attention_kernel(const float* __restrict__ seq_cate,
                                 const float* __restrict__ out_short,
                                 const float* __restrict__ mask_seq,
                                 float* __restrict__ sum_cate)
{
    const int b = blockIdx.x;
    const int j = threadIdx.x;
    __shared__ float red[8];
    __shared__ float w[S_];
    const float os = out_short[(size_t)b * H_ + j];
    float sc[S_];
#pragma unroll
    for (int s = 0; s < S_; s++)
        sc[s] = seq_cate[(size_t)(b * S_ + s) * H_ + j];

    for (int s = 0; s < S_; s++) {
        float v = sc[s] * os;
#pragma unroll
        for (int off = 16; off; off >>= 1) v += __shfl_xor_sync(0xffffffffu, v, off);
        if ((j & 31) == 0) red[j >> 5] = v;
        __syncthreads();
        if (j == 0) {
            float x = 0.f;
#pragma unroll
            for (int q = 0; q < 8; q++) x += red[q];
            w[s] = x;
        }
        __syncthreads();
    }
    if (j == 0) {
        float mx = w[0];
        for (int s = 1; s < S_; s++) mx = fmaxf(mx, w[s]);
        float e[S_];
        float sum = 0.f;
        for (int s = 0; s < S_; s++) { e[s] = expf(w[s] - mx); sum += e[s]; }
        float s2 = 0.f;
        for (int s = 0; s < S_; s++) {
            e[s] = (e[s] / sum) * mask_seq[(size_t)b * S_ + s];
            s2 += e[s];
        }
        for (int s = 0; s < S_; s++) w[s] = e[s] / s2;
    }
    __syncthreads();
    float acc = 0.f;
#pragma unroll
    for (int s = 0; s < S_; s++) acc += w[s] * sc[s];
    sum_cate[(size_t)b * H_ + j] = acc;
}

// ---------------- FC -----------------------------------------------------------
__global__ void fc_kernel(const float* __restrict__ sum_cate,
                          const float* __restrict__ out_short,
                          const float* __restrict__ fcW,
                          const float* __restrict__ fcb,
                          float* __restrict__ fc_out)
{
    __shared__ float mix[16][2 * H_];
    const int b0 = blockIdx.x * 16;
    for (int idx = threadIdx.x; idx < 16 * 2 * H_; idx += 256) {
        const int bb = idx >> 9, k = idx & 511;
        mix[bb][k] = (k < H_) ? sum_cate[(size_t)(b0 + bb) * H_ + k]
                              : out_short[(size_t)(b0 + bb) * H_ + (k - H_)];
    }
    __syncthreads();
    const int i = threadIdx.x;
    const float* wrow = fcW + (size_t)i * (2 * H_);
    float acc[16];
#pragma unroll
    for (int bb = 0; bb < 16; bb++) acc[bb] = 0.f;
    for (int k = 0; k < 2 * H_; k++) {
        const float wv = wrow[k];
#pragma unroll
        for (int bb = 0; bb < 16; bb++) acc[bb] += wv * mix[bb][k];
    }
    const float bias = fcb[i];
#pragma unroll
    for (int bb = 0; bb < 16; bb++)
        fc_out[(size_t)(b0 + bb) * H_ + i] = acc[bb] + bias;
}

__global__ void write_targets(const int* __restrict__ tgt, float* __restrict__ out)
{
    out[threadIdx.x] = (float)tgt[threadIdx.x];
}

// ---------------- launcher ----------------------------------------------------
extern "C" void kernel_launch(void* const* d_in, const int* in_sizes, int n_in,
                              void* d_out, int out_size)
{
    const int*   in_cate       = (const int*)d_in[0];
    const float* mask_cate     = (const float*)d_in[1];
    const float* mask_cate_seq = (const float*)d_in[2];
    const int*   subseqLen     = (const int*)d_in[5];
    const int*   in_batch      = (const int*)d_in[7];
    const float* mask_b        = (const float*)d_in[8];
    const int*   seqLen        = (const int*)d_in[9];
    const int*   target        = (const int*)d_in[10];
    const float* emb           = (const float*)d_in[12];
    const float* Wih_c         = (const float*)d_in[13];
    const float* Whh_c         = (const float*)d_in[14];
    const float* bih_c         = (const float*)d_in[15];
    const float* bhh_c         = (const float*)d_in[16];
    const float* Wih_s         = (const float*)d_in[17];
    const float* Whh_s         = (const float*)d_in[18];
    const float* bih_s         = (const float*)d_in[19];
    const float* bhh_s         = (const float*)d_in[20];
    const float* fc_W          = (const float*)d_in[21];
    const float* fc_b          = (const float*)d_in[22];
    float* out = (float*)d_out;

    float *gi_c, *gi_s, *hA, *hB, *hsA, *hsB, *seqc, *osht, *sumc, *fco;
    int *tok_c, *tok_s, *Mc, *Ms;
    __nv_bfloat16 *emb_hi, *emb_lo, *wc_hi, *wc_lo, *ws_hi, *ws_lo, *fc_hi, *fc_lo;
    __nv_bfloat16 *whc_hi, *whc_lo, *whs_hi, *whs_lo;
    cudaGetSymbolAddress((void**)&gi_c, g_gi_c);
    cudaGetSymbolAddress((void**)&gi_s, g_gi_s);
    cudaGetSymbolAddress((void**)&hA,  g_hA);
    cudaGetSymbolAddress((void**)&hB,  g_hB);
    cudaGetSymbolAddress((void**)&hsA, g_hsA);
    cudaGetSymbolAddress((void**)&hsB, g_hsB);
    cudaGetSymbolAddress((void**)&seqc, g_seq_cate);
    cudaGetSymbolAddress((void**)&osht, g_out_short);
    cudaGetSymbolAddress((void**)&sumc, g_sum_cate);
    cudaGetSymbolAddress((void**)&fco,  g_fc_out);
    cudaGetSymbolAddress((void**)&tok_c, g_tok_c);
    cudaGetSymbolAddress((void**)&tok_s, g_tok_s);
    cudaGetSymbolAddress((void**)&Mc, g_Mc);
    cudaGetSymbolAddress((void**)&Ms, g_Ms);
    cudaGetSymbolAddress((void**)&emb_hi, g_emb_hi);
    cudaGetSymbolAddress((void**)&emb_lo, g_emb_lo);
    cudaGetSymbolAddress((void**)&wc_hi, g_wc_hi);
    cudaGetSymbolAddress((void**)&wc_lo, g_wc_lo);
    cudaGetSymbolAddress((void**)&ws_hi, g_ws_hi);
    cudaGetSymbolAddress((void**)&ws_lo, g_ws_lo);
    cudaGetSymbolAddress((void**)&fc_hi, g_fc_hi);
    cudaGetSymbolAddress((void**)&fc_lo, g_fc_lo);
    cudaGetSymbolAddress((void**)&whc_hi, g_whc_hi);
    cudaGetSymbolAddress((void**)&whc_lo, g_whc_lo);
    cudaGetSymbolAddress((void**)&whs_hi, g_whs_hi);
    cudaGetSymbolAddress((void**)&whs_lo, g_whs_lo);

    cudaFuncSetAttribute(gemm_mma, cudaFuncAttributeMaxDynamicSharedMemorySize,
                         GEMM_SMEM);
    cudaFuncSetAttribute(gru_dual_step,
                         cudaFuncAttributeMaxDynamicSharedMemorySize, GRU_SMEM);

    // 0) prep + bf16 splits
    prep_kernel<<<1, 256>>>(subseqLen, in_cate, seqLen, in_batch);
    split_kernel<<<8192, 256>>>(emb, emb_hi, emb_lo, V_ * E_);
    split_kernel<<<192, 256>>>(Wih_c, wc_hi, wc_lo, H3_ * E_);
    split_kernel<<<192, 256>>>(Wih_s, ws_hi, ws_lo, H3_ * E_);
    split_kernel<<<192, 256>>>(Whh_c, whc_hi, whc_lo, H3_ * H_);
    split_kernel<<<192, 256>>>(Whh_s, whs_hi, whs_lo, H3_ * H_);

    // 1) input-gate GEMMs over compacted tokens (HMMA tensor cores)
    gemm_mma<<<dim3((BC_ * TC_ + 127) / 128, H3_ / 128), 256, GEMM_SMEM>>>(
        emb_hi, emb_lo, tok_c, Mc, wc_hi, wc_lo, bih_c, gi_c, BC_ * TC_, H3_);
    gemm_mma<<<dim3((B_ * TS_ + 127) / 128, H3_ / 128), 256, GEMM_SMEM>>>(
        emb_hi, emb_lo, tok_s, Ms, ws_hi, ws_lo, bih_s, gi_s, B_ * TS_, H3_);

    // 2+3) fused HMMA GRU scans: 50 dual-step launches (cat active for t<20)
    {
        float *hc_in = hA, *hc_out = hB, *hs_in = hsA, *hs_out = hsB;
        for (int t = 0; t < TS_; t++) {
            gru_dual_step<<<dim3(CATBX + B_ / 64, H_ / 64), 256, GRU_SMEM>>>(
                whc_hi, whc_lo, bhh_c, gi_c, hc_in, hc_out, mask_cate, seqc,
                subseqLen,
                whs_hi, whs_lo, bhh_s, gi_s, hs_in, hs_out, mask_b, osht,
                seqLen, t);
            float* tmp;
            tmp = hc_in; hc_in = hc_out; hc_out = tmp;
            tmp = hs_in; hs_in = hs_out; hs_out = tmp;
        }
    }

    // 4) attention + 5) FC (+ split fc_out for tensor-core logits)
    attention_kernel<<<B_, 256>>>(seqc, osht, mask_cate_seq, sumc);
    fc_kernel<<<B_ / 16, 256>>>(sumc, osht, fc_W, fc_b, fco);
    split_kernel<<<64, 256>>>(fco, fc_hi, fc_lo, B_ * H_);

    // 6) logits = fc_out @ emb^T (HMMA tensor cores)
    gemm_mma<<<dim3(B_ / 128, (V_ + 127) / 128), 256, GEMM_SMEM>>>(
        fc_hi, fc_lo, nullptr, nullptr, emb_hi, emb_lo, nullptr, out, B_, V_);

    // 7) targets appended as float, if the output carries them
    if (out_size >= B_ * V_ + B_)
        write_targets<<<1, B_>>>(target, out + (size_t)B_ * V_);
}

// round 9
// speedup vs baseline: 3.1248x; 1.1164x over previous
#include <cuda_runtime.h>
#include <cuda_bf16.h>
#include <math.h>
#include <stdint.h>

// Problem constants (fixed by setup_inputs)
#define V_  100000
#define E_  256
#define H_  256
#define B_  256
#define S_  10
#define TC_ 20
#define TS_ 50
#define BC_ (B_ * S_)   // 2560
#define H3_ (3 * H_)    // 768

// ---------------- scratch (static device globals; no allocation) --------------
__device__ float g_gi_c[(size_t)BC_ * TC_ * H3_];
__device__ float g_gi_s[(size_t)B_ * TS_ * H3_];
__device__ float g_hA[BC_ * H_];
__device__ float g_hB[BC_ * H_];
__device__ float g_hsA[B_ * H_];
__device__ float g_hsB[B_ * H_];
__device__ float g_seq_cate[BC_ * H_];
__device__ float g_out_short[B_ * H_];
__device__ float g_sum_cate[B_ * H_];
__device__ float g_fc_out[B_ * H_];
__device__ int   g_order_c[BC_];
__device__ int   g_order_s[B_];
__device__ int   g_off_c[BC_ + 1];
__device__ int   g_off_s[B_ + 1];
__device__ int   g_tok_c[BC_ * TC_];
__device__ int   g_tok_s[B_ * TS_];
__device__ int   g_cnt_c[TS_ + 1];
__device__ int   g_cnt_s[TS_ + 1];
__device__ int   g_Mc[1];
__device__ int   g_Ms[1];
// pre-split Whh (read by many blocks every GRU step -> worth materializing)
__device__ __nv_bfloat16 g_whc_hi[H3_ * H_];
__device__ __nv_bfloat16 g_whc_lo[H3_ * H_];
__device__ __nv_bfloat16 g_whs_hi[H3_ * H_];
__device__ __nv_bfloat16 g_whs_lo[H3_ * H_];

// ---------------- helpers ------------------------------------------------------
__device__ __forceinline__ float fast_sigmoid(float x) {
    return 1.f / (1.f + __expf(-x));
}
__device__ __forceinline__ float fast_tanh(float x) {
    float ax = fabsf(x);
    float e = __expf(-2.f * ax);
    float t = __fdividef(1.f - e, 1.f + e);
    return copysignf(t, x);
}
__device__ __forceinline__ uint32_t smem_u32(const void* p) {
    uint32_t a;
    asm("{ .reg .u64 t; cvta.to.shared.u64 t, %1; cvt.u32.u64 %0, t; }"
        : "=r"(a) : "l"(p));
    return a;
}
__device__ __forceinline__ void ldsm4(uint32_t& r0, uint32_t& r1, uint32_t& r2,
                                      uint32_t& r3, uint32_t addr) {
    asm volatile("ldmatrix.sync.aligned.m8n8.x4.shared.b16 {%0,%1,%2,%3}, [%4];"
                 : "=r"(r0), "=r"(r1), "=r"(r2), "=r"(r3) : "r"(addr));
}
__device__ __forceinline__ void mma16816(float* d, const uint32_t* a,
                                         uint32_t b0, uint32_t b1) {
    asm volatile(
        "mma.sync.aligned.m16n8k16.row.col.f32.bf16.bf16.f32 "
        "{%0,%1,%2,%3}, {%4,%5,%6,%7}, {%8,%9}, {%0,%1,%2,%3};"
        : "+f"(d[0]), "+f"(d[1]), "+f"(d[2]), "+f"(d[3])
        : "r"(a[0]), "r"(a[1]), "r"(a[2]), "r"(a[3]), "r"(b0), "r"(b1));
}
// split 8 fp32 -> 8 bf16 hi + 8 bf16 lo, packed stores
__device__ __forceinline__ void split_store8(float4 a0, float4 a1,
                                             __nv_bfloat16* hi,
                                             __nv_bfloat16* lo) {
    float f[8] = {a0.x, a0.y, a0.z, a0.w, a1.x, a1.y, a1.z, a1.w};
    __nv_bfloat16 h[8], l[8];
#pragma unroll
    for (int e = 0; e < 8; e++) h[e] = __float2bfloat16(f[e]);
#pragma unroll
    for (int e = 0; e < 8; e++)
        l[e] = __float2bfloat16(f[e] - __bfloat162float(h[e]));
    __nv_bfloat162 hp[4] = {{h[0], h[1]}, {h[2], h[3]}, {h[4], h[5]}, {h[6], h[7]}};
    __nv_bfloat162 lp[4] = {{l[0], l[1]}, {l[2], l[3]}, {l[4], l[5]}, {l[6], l[7]}};
    *(uint4*)hi = *(uint4*)hp;
    *(uint4*)lo = *(uint4*)lp;
}

// ---------------- fp32 -> bf16 hi/lo split (Whh only) -------------------------
__global__ void split_kernel(const float* __restrict__ src,
                             __nv_bfloat16* __restrict__ hi,
                             __nv_bfloat16* __restrict__ lo, int n)
{
    int i = (blockIdx.x * 256 + threadIdx.x) * 4;
    const int stride = gridDim.x * 256 * 4;
    for (; i < n; i += stride) {
        float4 v = *(const float4*)(src + i);
        __nv_bfloat16 h0 = __float2bfloat16(v.x);
        __nv_bfloat16 h1 = __float2bfloat16(v.y);
        __nv_bfloat16 h2 = __float2bfloat16(v.z);
        __nv_bfloat16 h3 = __float2bfloat16(v.w);
        __nv_bfloat16 l0 = __float2bfloat16(v.x - __bfloat162float(h0));
        __nv_bfloat16 l1 = __float2bfloat16(v.y - __bfloat162float(h1));
        __nv_bfloat16 l2 = __float2bfloat16(v.z - __bfloat162float(h2));
        __nv_bfloat16 l3 = __float2bfloat16(v.w - __bfloat162float(h3));
        ((__nv_bfloat162*)(hi + i))[0] = __nv_bfloat162(h0, h1);
        ((__nv_bfloat162*)(hi + i))[1] = __nv_bfloat162(h2, h3);
        ((__nv_bfloat162*)(lo + i))[0] = __nv_bfloat162(l0, l1);
        ((__nv_bfloat162*)(lo + i))[1] = __nv_bfloat162(l2, l3);
    }
}

// ---------------- prep: counting sort desc, prefix offsets, token compaction --
__global__ void prep_kernel(const int* __restrict__ slen_c, const int* __restrict__ tokens_c,
                            const int* __restrict__ slen_s, const int* __restrict__ tokens_s)
{
    __shared__ int hist[64];
    __shared__ int base[64];
    __shared__ int ssum[256];
    const int tid = threadIdx.x;

    if (tid < 64) hist[tid] = 0;
    __syncthreads();
    for (int i = tid; i < BC_; i += 256) atomicAdd(&hist[slen_c[i]], 1);
    __syncthreads();
    if (tid <= TS_) {
        int c = 0;
        if (tid < 64) for (int k = tid; k < 64; k++) c += hist[k];
        g_cnt_c[tid] = (tid < TC_) ? c : 0;
    }
    if (tid == 0) {
        int run = 0;
        for (int k = 63; k >= 0; k--) { base[k] = run; run += hist[k]; }
    }
    __syncthreads();
    for (int i = tid; i < BC_; i += 256) {
        int pos = atomicAdd(&base[slen_c[i]], 1);
        g_order_c[pos] = i;
    }
    {
        const int chunk = BC_ / 256;
        int s = 0;
        for (int i = 0; i < chunk; i++) s += slen_c[tid * chunk + i] + 1;
        ssum[tid] = s;
        __syncthreads();
        for (int d = 1; d < 256; d <<= 1) {
            int v = (tid >= d) ? ssum[tid - d] : 0;
            __syncthreads();
            ssum[tid] += v;
            __syncthreads();
        }
        int run = (tid > 0) ? ssum[tid - 1] : 0;
        for (int i = 0; i < chunk; i++) {
            int b = tid * chunk + i;
            g_off_c[b] = run;
            run += slen_c[b] + 1;
        }
        if (tid == 255) { g_off_c[BC_] = ssum[255]; g_Mc[0] = ssum[255]; }
    }
    __syncthreads();
    for (int i = tid; i < BC_ * TC_; i += 256) {
        int b = i / TC_, t = i % TC_;
        if (t <= slen_c[b]) g_tok_c[g_off_c[b] + t] = tokens_c[i];
    }
    __syncthreads();

    if (tid < 64) hist[tid] = 0;
    __syncthreads();
    for (int i = tid; i < B_; i += 256) atomicAdd(&hist[slen_s[i]], 1);
    __syncthreads();
    if (tid <= TS_) {
        int c = 0;
        if (tid < 64) for (int k = tid; k < 64; k++) c += hist[k];
        g_cnt_s[tid] = (tid < TS_) ? c : 0;
    }
    if (tid == 0) {
        int run = 0;
        for (int k = 63; k >= 0; k--) { base[k] = run; run += hist[k]; }
    }
    __syncthreads();
    for (int i = tid; i < B_; i += 256) {
        int pos = atomicAdd(&base[slen_s[i]], 1);
        g_order_s[pos] = i;
    }
    {
        int s = (tid < B_) ? slen_s[tid] + 1 : 0;
        ssum[tid] = s;
        __syncthreads();
        for (int d = 1; d < 256; d <<= 1) {
            int v = (tid >= d) ? ssum[tid - d] : 0;
            __syncthreads();
            ssum[tid] += v;
            __syncthreads();
        }
        if (tid < B_) g_off_s[tid] = ssum[tid] - (slen_s[tid] + 1);
        if (tid == 255) { g_off_s[B_] = ssum[255]; g_Ms[0] = ssum[255]; }
    }
    __syncthreads();
    for (int i = tid; i < B_ * TS_; i += 256) {
        int b = i / TS_, t = i % TS_;
        if (t <= slen_s[b]) g_tok_s[g_off_s[b] + t] = tokens_s[i];
    }
}

// ---------------- bf16-split HMMA GEMM, fp32 in, split-on-stage ---------------
// C[m,n] = sum_k A(m)[k]*B(n)[k] + bias[n] via Ah*Bh + Ah*Bl + Al*Bh.
// A, B fp32; hi/lo bf16 split happens while staging to smem.
#define STRIDE_ 72
#define GTILE_  (128 * STRIDE_)
#define GEMM_SMEM (4 * GTILE_ * 2)

__global__ void __launch_bounds__(256, 2) gemm_mma(
    const float* __restrict__ A, const int* __restrict__ idx,
    const int* __restrict__ Mdev,
    const float* __restrict__ B, const float* __restrict__ bias,
    float* __restrict__ C, int M, int N)
{
    extern __shared__ __align__(16) __nv_bfloat16 smem[];
    const int Mq = Mdev ? *Mdev : M;
    const int bm = blockIdx.x * 128, bn = blockIdx.y * 128;
    if (bm >= Mq) return;
    const int tid = threadIdx.x, wid = tid >> 5, lane = tid & 31;
    const int warp_m = wid & 1, warp_n = wid >> 1;

    __nv_bfloat16* sAh = smem;
    __nv_bfloat16* sAl = smem + GTILE_;
    __nv_bfloat16* sBh = smem + 2 * GTILE_;
    __nv_bfloat16* sBl = smem + 3 * GTILE_;
    const uint32_t uAh = smem_u32(sAh), uAl = smem_u32(sAl);
    const uint32_t uBh = smem_u32(sBh), uBl = smem_u32(sBl);

    const int fr = lane & 15;
    const int fc = (lane >> 4) * 8;
    const int arow_f = warp_m * 64 + fr;
    const int brow_f = warp_n * 32 + fr;

    float acc[4][4][4];
#pragma unroll
    for (int i = 0; i < 4; i++)
#pragma unroll
        for (int j = 0; j < 4; j++)
#pragma unroll
            for (int e = 0; e < 4; e++) acc[i][j][e] = 0.f;

    for (int kt = 0; kt < 4; kt++) {
        if (kt) __syncthreads();
#pragma unroll
        for (int i = 0; i < 4; i++) {
            const int id = i * 256 + tid;
            const int row = id >> 3, ch = id & 7;
            const int col = kt * 64 + ch * 8;
            int am = bm + row; if (am > Mq - 1) am = Mq - 1;
            const int ar = idx ? idx[am] : am;
            int br = bn + row; if (br > N - 1) br = N - 1;
            const int so = row * STRIDE_ + ch * 8;
            const float* ap = A + (size_t)ar * 256 + col;
            const float* bp = B + (size_t)br * 256 + col;
            split_store8(*(const float4*)ap, *(const float4*)(ap + 4),
                         sAh + so, sAl + so);
            split_store8(*(const float4*)bp, *(const float4*)(bp + 4),
                         sBh + so, sBl + so);
        }
        __syncthreads();

#pragma unroll
        for (int kk = 0; kk < 4; kk++) {
            const int col = kk * 16 + fc;
            uint32_t bh[2][4], bl[2][4], av[4][4];
#pragma unroll
            for (int p = 0; p < 2; p++) {
                const uint32_t off = 2u * ((brow_f + p * 16) * STRIDE_ + col);
                ldsm4(bh[p][0], bh[p][1], bh[p][2], bh[p][3], uBh + off);
                ldsm4(bl[p][0], bl[p][1], bl[p][2], bl[p][3], uBl + off);
            }
#pragma unroll
            for (int tm = 0; tm < 4; tm++) {
                const uint32_t off = 2u * ((arow_f + tm * 16) * STRIDE_ + col);
                ldsm4(av[tm][0], av[tm][1], av[tm][2], av[tm][3], uAh + off);
            }
#pragma unroll
            for (int tm = 0; tm < 4; tm++)
#pragma unroll
                for (int tn = 0; tn < 4; tn++) {
                    const int p = tn >> 1, o = tn & 1;
                    mma16816(acc[tm][tn], av[tm], bh[p][o], bh[p][o + 2]);
                    mma16816(acc[tm][tn], av[tm], bl[p][o], bl[p][o + 2]);
                }
#pragma unroll
            for (int tm = 0; tm < 4; tm++) {
                const uint32_t off = 2u * ((arow_f + tm * 16) * STRIDE_ + col);
                ldsm4(av[tm][0], av[tm][1], av[tm][2], av[tm][3], uAl + off);
            }
#pragma unroll
            for (int tm = 0; tm < 4; tm++)
#pragma unroll
                for (int tn = 0; tn < 4; tn++) {
                    const int p = tn >> 1, o = tn & 1;
                    mma16816(acc[tm][tn], av[tm], bh[p][o], bh[p][o + 2]);
                }
        }
    }

    const int mrow = bm + warp_m * 64 + (lane >> 2);
    const int ncol = bn + warp_n * 32 + (lane & 3) * 2;
#pragma unroll
    for (int tm = 0; tm < 4; tm++) {
#pragma unroll
        for (int half = 0; half < 2; half++) {
            const int m = mrow + tm * 16 + half * 8;
            if (m >= Mq) continue;
            float* crow = C + (size_t)m * N;
#pragma unroll
            for (int tn = 0; tn < 4; tn++) {
                const int n0 = ncol + tn * 8;
                const float v0 = acc[tm][tn][half * 2 + 0]
                               + (bias ? bias[n0] : 0.f);
                if (n0 + 1 < N) {
                    const float v1 = acc[tm][tn][half * 2 + 1]
                                   + (bias ? bias[n0 + 1] : 0.f);
                    *(float2*)(crow + n0) = make_float2(v0, v1);
                } else if (n0 < N) {
                    crow[n0] = v0;
                }
            }
        }
    }
}

// ---------------- HMMA fused dual GRU step (no-park warp mapping) -------------
// Block: 64 sorted slots x 64 j. Warp w: warp_m=w&1 (32 rows), warp_n=w>>1
// (16 j). Each warp computes all 3 gates for its j-slice -> r,z,n land in the
// SAME thread's accumulators; epilogue runs from registers, no smem park.
#define CATBX 40
#define GRU_SA 4608             // 64*72
#define GRU_SB 13824            // 192*72
#define GRU_SMEM ((2 * GRU_SA + 2 * GRU_SB) * 2)   // 73728 bytes

__device__ __forceinline__ void gru_tile_mma(
    const __nv_bfloat16* __restrict__ Whi, const __nv_bfloat16* __restrict__ Wlo,
    const float* __restrict__ bhh,
    const float* __restrict__ gi,  const int* __restrict__ off,
    const int* __restrict__ order, const int* __restrict__ slen,
    const float* __restrict__ mask, int maskT,
    const float* __restrict__ h_in, float* __restrict__ h_out,
    float* __restrict__ gathered, int t, int active, int bx)
{
    extern __shared__ __align__(16) char gsm[];
    __nv_bfloat16* sAh = (__nv_bfloat16*)gsm;
    __nv_bfloat16* sAl = sAh + GRU_SA;
    __nv_bfloat16* sBh = sAl + GRU_SA;
    __nv_bfloat16* sBl = sBh + GRU_SB;
    const uint32_t uAh = smem_u32(sAh), uAl = smem_u32(sAl);
    const uint32_t uBh = smem_u32(sBh), uBl = smem_u32(sBl);
    __shared__ int rows_s[64];
    __shared__ int sl_s[64];

    const int tid = threadIdx.x, wid = tid >> 5, lane = tid & 31;
    const int warp_m = wid & 1, warp_n = wid >> 1;   // 2 x 4
    const int bm = bx * 64;
    const int bj = blockIdx.y * 64;
    const int fr = lane & 15;
    const int fc = (lane >> 4) * 8;

    if (tid < 64) {
        int gs = bm + tid; if (gs > active - 1) gs = active - 1;
        const int r = order[gs];
        rows_s[tid] = r;
        sl_s[tid] = slen[r];
    }
    __syncthreads();

    float acc[2][6][4];
#pragma unroll
    for (int i = 0; i < 2; i++)
#pragma unroll
        for (int j = 0; j < 6; j++)
#pragma unroll
            for (int e = 0; e < 4; e++) acc[i][j][e] = 0.f;

    if (t > 0) {
        for (int kt = 0; kt < 4; kt++) {
            if (kt) __syncthreads();
            // stage A: h rows, fp32 -> bf16 hi/lo split
#pragma unroll
            for (int i = 0; i < 4; i++) {
                const int id = i * 256 + tid;
                const int sl = id >> 4, c4 = id & 15;
                const int row = rows_s[sl];
                float4 v = *(const float4*)(h_in + (size_t)row * 256 + kt * 64 + c4 * 4);
                __nv_bfloat16 h0 = __float2bfloat16(v.x);
                __nv_bfloat16 h1 = __float2bfloat16(v.y);
                __nv_bfloat16 h2 = __float2bfloat16(v.z);
                __nv_bfloat16 h3 = __float2bfloat16(v.w);
                const int so = sl * STRIDE_ + c4 * 4;
                *(__nv_bfloat162*)(sAh + so)     = __nv_bfloat162(h0, h1);
                *(__nv_bfloat162*)(sAh + so + 2) = __nv_bfloat162(h2, h3);
                *(__nv_bfloat162*)(sAl + so) =
                    __nv_bfloat162(__float2bfloat16(v.x - __bfloat162float(h0)),
                                   __float2bfloat16(v.y - __bfloat162float(h1)));
                *(__nv_bfloat162*)(sAl + so + 2) =
                    __nv_bfloat162(__float2bfloat16(v.z - __bfloat162float(h2)),
                                   __float2bfloat16(v.w - __bfloat162float(h3)));
            }
            // stage B: Whh gate rows (pre-split bf16), tile row = g*64 + j
#pragma unroll
            for (int i = 0; i < 6; i++) {
                const int id = i * 256 + tid;
                const int row = id >> 3, ch = id & 7;       // row 0..191
                const int g = row >> 6, j = row & 63;
                const int grow = g * 256 + bj + j;
                const int col = kt * 64 + ch * 8;
                const int so = row * STRIDE_ + ch * 8;
                *(uint4*)(sBh + so) = *(const uint4*)(Whi + (size_t)grow * 256 + col);
                *(uint4*)(sBl + so) = *(const uint4*)(Wlo + (size_t)grow * 256 + col);
            }
            __syncthreads();

#pragma unroll
            for (int kk = 0; kk < 4; kk++) {
                const int col = kk * 16 + fc;
                uint32_t bh[3][4], bl[3][4], avh[2][4], avl[2][4];
#pragma unroll
                for (int g = 0; g < 3; g++) {
                    const uint32_t o = 2u * ((g * 64 + warp_n * 16 + fr) * STRIDE_ + col);
                    ldsm4(bh[g][0], bh[g][1], bh[g][2], bh[g][3], uBh + o);
                    ldsm4(bl[g][0], bl[g][1], bl[g][2], bl[g][3], uBl + o);
                }
#pragma unroll
                for (int tm = 0; tm < 2; tm++) {
                    const uint32_t o = 2u * ((warp_m * 32 + tm * 16 + fr) * STRIDE_ + col);
                    ldsm4(avh[tm][0], avh[tm][1], avh[tm][2], avh[tm][3], uAh + o);
                    ldsm4(avl[tm][0], avl[tm][1], avl[tm][2], avl[tm][3], uAl + o);
                }
#pragma unroll
                for (int tm = 0; tm < 2; tm++)
#pragma unroll
                    for (int g = 0; g < 3; g++)
#pragma unroll
                        for (int o = 0; o < 2; o++) {
                            mma16816(acc[tm][g * 2 + o], avh[tm], bh[g][o], bh[g][o + 2]);
                            mma16816(acc[tm][g * 2 + o], avh[tm], bl[g][o], bl[g][o + 2]);
                            mma16816(acc[tm][g * 2 + o], avl[tm], bh[g][o], bh[g][o + 2]);
                        }
            }
        }
    }

    // register-resident epilogue: thread owns r,z,n for its (m, j) pairs
#pragma unroll
    for (int tm = 0; tm < 2; tm++)
#pragma unroll
        for (int o = 0; o < 2; o++)
#pragma unroll
            for (int e = 0; e < 4; e++) {
                const int m_local = warp_m * 32 + tm * 16 + (lane >> 2) + 8 * (e >> 1);
                const int slot = bm + m_local;
                if (slot >= active) continue;
                const int b = rows_s[m_local];
                const int j = warp_n * 16 + o * 8 + (lane & 3) * 2 + (e & 1);
                const int jj = bj + j;
                const size_t gbase = ((size_t)(off[b] + t)) * H3_ + jj;
                const float gr = gi[gbase];
                const float gz = gi[gbase + H_];
                const float gn = gi[gbase + 2 * H_];
                const float ar = acc[tm][0 + o][e];
                const float az = acc[tm][2 + o][e];
                const float an = acc[tm][4 + o][e];
                const float hold = (t > 0) ? h_in[(size_t)b * H_ + jj] : 0.f;
                const float r = fast_sigmoid(gr + ar + bhh[jj]);
                const float z = fast_sigmoid(gz + az + bhh[H_ + jj]);
                const float n = fast_tanh(gn + r * (an + bhh[2 * H_ + jj]));
                const float hnew = (1.f - z) * n + z * hold;
                h_out[(size_t)b * H_ + jj] = hnew;
                if (sl_s[m_local] == t)
                    gathered[(size_t)b * H_ + jj] =
                        hnew * mask[(size_t)b * maskT + t];
            }
}

__global__ void __launch_bounds__(256) gru_dual_step(
    const __nv_bfloat16* Whi_c, const __nv_bfloat16* Wlo_c, const float* bhh_c,
    const float* gi_c, const float* h_in_c, float* h_out_c,
    const float* mask_c, float* gath_c, const int* slen_c,
    const __nv_bfloat16* Whi_s, const __nv_bfloat16* Wlo_s, const float* bhh_s,
    const float* gi_s, const float* h_in_s, float* h_out_s,
    const float* mask_s, float* gath_s, const int* slen_s, int t)
{
    if ((int)blockIdx.x < CATBX) {
        const int active = g_cnt_c[t];
        if (blockIdx.x * 64 >= (unsigned)active) return;
        gru_tile_mma(Whi_c, Wlo_c, bhh_c, gi_c, g_off_c, g_order_c, slen_c,
                     mask_c, TC_, h_in_c, h_out_c, gath_c, t, active, blockIdx.x);
    } else {
        const int bx = blockIdx.x - CATBX;
        const int active = g_cnt_s[t];
        if (bx * 64 >= active) return;
        gru_tile_mma(Whi_s, Wlo_s, bhh_s, gi_s, g_off_s, g_order_s, slen_s,
                     mask_s, TS_, h_in_s, h_out_s, gath_s, t, active, bx);
    }
}

// ---------------- attention ----------------------------------------------------
__global__ void attention_kernel(const float* __restrict__ seq_cate,
                                 const float* __restrict__ out_short,
                                 const float* __restrict__ mask_seq,
                                 float* __restrict__ sum_cate)
{
    const int b = blockIdx.x;
    const int j = threadIdx.x;
    __shared__ float red[8];
    __shared__ float w[S_];
    const float os = out_short[(size_t)b * H_ + j];
    float sc[S_];
#pragma unroll
    for (int s = 0; s < S_; s++)
        sc[s] = seq_cate[(size_t)(b * S_ + s) * H_ + j];

    for (int s = 0; s < S_; s++) {
        float v = sc[s] * os;
#pragma unroll
        for (int off = 16; off; off >>= 1) v += __shfl_xor_sync(0xffffffffu, v, off);
        if ((j & 31) == 0) red[j >> 5] = v;
        __syncthreads();
        if (j == 0) {
            float x = 0.f;
#pragma unroll
            for (int q = 0; q < 8; q++) x += red[q];
            w[s] = x;
        }
        __syncthreads();
    }
    if (j == 0) {
        float mx = w[0];
        for (int s = 1; s < S_; s++) mx = fmaxf(mx, w[s]);
        float e[S_];
        float sum = 0.f;
        for (int s = 0; s < S_; s++) { e[s] = expf(w[s] - mx); sum += e[s]; }
        float s2 = 0.f;
        for (int s = 0; s < S_; s++) {
            e[s] = (e[s] / sum) * mask_seq[(size_t)b * S_ + s];
            s2 += e[s];
        }
        for (int s = 0; s < S_; s++) w[s] = e[s] / s2;
    }
    __syncthreads();
    float acc = 0.f;
#pragma unroll
    for (int s = 0; s < S_; s++) acc += w[s] * sc[s];
    sum_cate[(size_t)b * H_ + j] = acc;
}

// ---------------- FC -----------------------------------------------------------
__global__ void fc_kernel(const float* __restrict__ sum_cate,
                          const float* __restrict__ out_short,
                          const float* __restrict__ fcW,
                          const float* __restrict__ fcb,
                          float* __restrict__ fc_out)
{
    __shared__ float mix[16][2 * H_];
    const int b0 = blockIdx.x * 16;
    for (int idx = threadIdx.x; idx < 16 * 2 * H_; idx += 256) {
        const int bb = idx >> 9, k = idx & 511;
        mix[bb][k] = (k < H_) ? sum_cate[(size_t)(b0 + bb) * H_ + k]
                              : out_short[(size_t)(b0 + bb) * H_ + (k - H_)];
    }
    __syncthreads();
    const int i = threadIdx.x;
    const float* wrow = fcW + (size_t)i * (2 * H_);
    float acc[16];
#pragma unroll
    for (int bb = 0; bb < 16; bb++) acc[bb] = 0.f;
    for (int k = 0; k < 2 * H_; k++) {
        const float wv = wrow[k];
#pragma unroll
        for (int bb = 0; bb < 16; bb++) acc[bb] += wv * mix[bb][k];
    }
    const float bias = fcb[i];
#pragma unroll
    for (int bb = 0; bb < 16; bb++)
        fc_out[(size_t)(b0 + bb) * H_ + i] = acc[bb] + bias;
}

__global__ void write_targets(const int* __restrict__ tgt, float* __restrict__ out)
{
    out[threadIdx.x] = (float)tgt[threadIdx.x];
}

// ---------------- launcher ----------------------------------------------------
extern "C" void kernel_launch(void* const* d_in, const int* in_sizes, int n_in,
                              void* d_out, int out_size)
{
    const int*   in_cate       = (const int*)d_in[0];
    const float* mask_cate     = (const float*)d_in[1];
    const float* mask_cate_seq = (const float*)d_in[2];
    const int*   subseqLen     = (const int*)d_in[5];
    const int*   in_batch      = (const int*)d_in[7];
    const float* mask_b        = (const float*)d_in[8];
    const int*   seqLen        = (const int*)d_in[9];
    const int*   target        = (const int*)d_in[10];
    const float* emb           = (const float*)d_in[12];
    const float* Wih_c         = (const float*)d_in[13];
    const float* Whh_c         = (const float*)d_in[14];
    const float* bih_c         = (const float*)d_in[15];
    const float* bhh_c         = (const float*)d_in[16];
    const float* Wih_s         = (const float*)d_in[17];
    const float* Whh_s         = (const float*)d_in[18];
    const float* bih_s         = (const float*)d_in[19];
    const float* bhh_s         = (const float*)d_in[20];
    const float* fc_W          = (const float*)d_in[21];
    const float* fc_b          = (const float*)d_in[22];
    float* out = (float*)d_out;

    float *gi_c, *gi_s, *hA, *hB, *hsA, *hsB, *seqc, *osht, *sumc, *fco;
    int *tok_c, *tok_s, *Mc, *Ms;
    __nv_bfloat16 *whc_hi, *whc_lo, *whs_hi, *whs_lo;
    cudaGetSymbolAddress((void**)&gi_c, g_gi_c);
    cudaGetSymbolAddress((void**)&gi_s, g_gi_s);
    cudaGetSymbolAddress((void**)&hA,  g_hA);
    cudaGetSymbolAddress((void**)&hB,  g_hB);
    cudaGetSymbolAddress((void**)&hsA, g_hsA);
    cudaGetSymbolAddress((void**)&hsB, g_hsB);
    cudaGetSymbolAddress((void**)&seqc, g_seq_cate);
    cudaGetSymbolAddress((void**)&osht, g_out_short);
    cudaGetSymbolAddress((void**)&sumc, g_sum_cate);
    cudaGetSymbolAddress((void**)&fco,  g_fc_out);
    cudaGetSymbolAddress((void**)&tok_c, g_tok_c);
    cudaGetSymbolAddress((void**)&tok_s, g_tok_s);
    cudaGetSymbolAddress((void**)&Mc, g_Mc);
    cudaGetSymbolAddress((void**)&Ms, g_Ms);
    cudaGetSymbolAddress((void**)&whc_hi, g_whc_hi);
    cudaGetSymbolAddress((void**)&whc_lo, g_whc_lo);
    cudaGetSymbolAddress((void**)&whs_hi, g_whs_hi);
    cudaGetSymbolAddress((void**)&whs_lo, g_whs_lo);

    cudaFuncSetAttribute(gemm_mma, cudaFuncAttributeMaxDynamicSharedMemorySize,
                         GEMM_SMEM);
    cudaFuncSetAttribute(gru_dual_step,
                         cudaFuncAttributeMaxDynamicSharedMemorySize, GRU_SMEM);

    // 0) prep + Whh bf16 splits (only weights read repeatedly get pre-split)
    prep_kernel<<<1, 256>>>(subseqLen, in_cate, seqLen, in_batch);
    split_kernel<<<192, 256>>>(Whh_c, whc_hi, whc_lo, H3_ * H_);
    split_kernel<<<192, 256>>>(Whh_s, whs_hi, whs_lo, H3_ * H_);

    // 1) input-gate GEMMs over compacted tokens (split-on-stage HMMA)
    gemm_mma<<<dim3((BC_ * TC_ + 127) / 128, H3_ / 128), 256, GEMM_SMEM>>>(
        emb, tok_c, Mc, Wih_c, bih_c, gi_c, BC_ * TC_, H3_);
    gemm_mma<<<dim3((B_ * TS_ + 127) / 128, H3_ / 128), 256, GEMM_SMEM>>>(
        emb, tok_s, Ms, Wih_s, bih_s, gi_s, B_ * TS_, H3_);

    // 2+3) fused HMMA GRU scans: 50 dual-step launches (cat active for t<20)
    {
        float *hc_in = hA, *hc_out = hB, *hs_in = hsA, *hs_out = hsB;
        for (int t = 0; t < TS_; t++) {
            gru_dual_step<<<dim3(CATBX + B_ / 64, H_ / 64), 256, GRU_SMEM>>>(
                whc_hi, whc_lo, bhh_c, gi_c, hc_in, hc_out, mask_cate, seqc,
                subseqLen,
                whs_hi, whs_lo, bhh_s, gi_s, hs_in, hs_out, mask_b, osht,
                seqLen, t);
            float* tmp;
            tmp = hc_in; hc_in = hc_out; hc_out = tmp;
            tmp = hs_in; hs_in = hs_out; hs_out = tmp;
        }
    }

    // 4) attention + 5) FC
    attention_kernel<<<B_, 256>>>(seqc, osht, mask_cate_seq, sumc);
    fc_kernel<<<B_ / 16, 256>>>(sumc, osht, fc_W, fc_b, fco);

    // 6) logits = fc_out @ emb^T (split-on-stage HMMA)
    gemm_mma<<<dim3(B_ / 128, (V_ + 127) / 128), 256, GEMM_SMEM>>>(
        fco, nullptr, nullptr, emb, nullptr, out, B_, V_);

    // 7) targets appended as float, if the output carries them
    if (out_size >= B_ * V_ + B_)
        write_targets<<<1, B_>>>(target, out + (size_t)B_ * V_);
}

// round 11
// speedup vs baseline: 4.1749x; 1.3360x over previous
#include <cuda_runtime.h>
#include <cuda_bf16.h>
#include <math.h>
#include <stdint.h>

// Problem constants (fixed by setup_inputs)
#define V_  100000
#define E_  256
#define H_  256
#define B_  256
#define S_  10
#define TC_ 20
#define TS_ 50
#define BC_ (B_ * S_)   // 2560
#define H3_ (3 * H_)    // 768

// ---------------- scratch (static device globals; no allocation) --------------
__device__ float g_gi_c[(size_t)BC_ * TC_ * H3_];
__device__ float g_gi_s[(size_t)B_ * TS_ * H3_];
__device__ float g_hA[BC_ * H_];
__device__ float g_hB[BC_ * H_];
__device__ float g_hsA[B_ * H_];
__device__ float g_hsB[B_ * H_];
__device__ float g_seq_cate[BC_ * H_];
__device__ float g_out_short[B_ * H_];
__device__ float g_sum_cate[B_ * H_];
__device__ float g_fc_out[B_ * H_];
__device__ int   g_order_c[BC_];
__device__ int   g_order_s[B_];
__device__ int   g_off_c[BC_ + 1];
__device__ int   g_off_s[B_ + 1];
__device__ int   g_tok_c[BC_ * TC_];
__device__ int   g_tok_s[B_ * TS_];
__device__ int   g_cnt_c[TS_ + 1];
__device__ int   g_cnt_s[TS_ + 1];
__device__ int   g_Mc[1];
__device__ int   g_Ms[1];
// pre-split Whh
__device__ __nv_bfloat16 g_whc_hi[H3_ * H_];
__device__ __nv_bfloat16 g_whc_lo[H3_ * H_];
__device__ __nv_bfloat16 g_whs_hi[H3_ * H_];
__device__ __nv_bfloat16 g_whs_lo[H3_ * H_];
// grid barrier state
__device__ unsigned g_bar_cnt = 0;
__device__ volatile unsigned g_bar_gen = 0;

// ---------------- helpers ------------------------------------------------------
__device__ __forceinline__ float fast_sigmoid(float x) {
    return 1.f / (1.f + __expf(-x));
}
__device__ __forceinline__ float fast_tanh(float x) {
    float ax = fabsf(x);
    float e = __expf(-2.f * ax);
    float t = __fdividef(1.f - e, 1.f + e);
    return copysignf(t, x);
}
__device__ __forceinline__ uint32_t smem_u32(const void* p) {
    uint32_t a;
    asm("{ .reg .u64 t; cvta.to.shared.u64 t, %1; cvt.u32.u64 %0, t; }"
        : "=r"(a) : "l"(p));
    return a;
}
__device__ __forceinline__ void ldsm4(uint32_t& r0, uint32_t& r1, uint32_t& r2,
                                      uint32_t& r3, uint32_t addr) {
    asm volatile("ldmatrix.sync.aligned.m8n8.x4.shared.b16 {%0,%1,%2,%3}, [%4];"
                 : "=r"(r0), "=r"(r1), "=r"(r2), "=r"(r3) : "r"(addr));
}
__device__ __forceinline__ void mma16816(float* d, const uint32_t* a,
                                         uint32_t b0, uint32_t b1) {
    asm volatile(
        "mma.sync.aligned.m16n8k16.row.col.f32.bf16.bf16.f32 "
        "{%0,%1,%2,%3}, {%4,%5,%6,%7}, {%8,%9}, {%0,%1,%2,%3};"
        : "+f"(d[0]), "+f"(d[1]), "+f"(d[2]), "+f"(d[3])
        : "r"(a[0]), "r"(a[1]), "r"(a[2]), "r"(a[3]), "r"(b0), "r"(b1));
}
__device__ __forceinline__ void split_store8(float4 a0, float4 a1,
                                             __nv_bfloat16* hi,
                                             __nv_bfloat16* lo) {
    float f[8] = {a0.x, a0.y, a0.z, a0.w, a1.x, a1.y, a1.z, a1.w};
    __nv_bfloat16 h[8], l[8];
#pragma unroll
    for (int e = 0; e < 8; e++) h[e] = __float2bfloat16(f[e]);
#pragma unroll
    for (int e = 0; e < 8; e++)
        l[e] = __float2bfloat16(f[e] - __bfloat162float(h[e]));
    __nv_bfloat162 hp[4] = {{h[0], h[1]}, {h[2], h[3]}, {h[4], h[5]}, {h[6], h[7]}};
    __nv_bfloat162 lp[4] = {{l[0], l[1]}, {l[2], l[3]}, {l[4], l[5]}, {l[6], l[7]}};
    *(uint4*)hi = *(uint4*)hp;
    *(uint4*)lo = *(uint4*)lp;
}
__device__ __forceinline__ void grid_barrier(unsigned nb) {
    __threadfence();
    __syncthreads();
    if (threadIdx.x == 0) {
        unsigned my = g_bar_gen;
        if (atomicAdd(&g_bar_cnt, 1u) == nb - 1u) {
            g_bar_cnt = 0u;
            __threadfence();
            g_bar_gen = my + 1u;
        } else {
            while (g_bar_gen == my) __nanosleep(64);
        }
    }
    __syncthreads();
}

// ---------------- fp32 -> bf16 hi/lo split (Whh only) -------------------------
__global__ void split_kernel(const float* __restrict__ src,
                             __nv_bfloat16* __restrict__ hi,
                             __nv_bfloat16* __restrict__ lo, int n)
{
    int i = (blockIdx.x * 256 + threadIdx.x) * 4;
    const int stride = gridDim.x * 256 * 4;
    for (; i < n; i += stride) {
        float4 v = *(const float4*)(src + i);
        __nv_bfloat16 h0 = __float2bfloat16(v.x);
        __nv_bfloat16 h1 = __float2bfloat16(v.y);
        __nv_bfloat16 h2 = __float2bfloat16(v.z);
        __nv_bfloat16 h3 = __float2bfloat16(v.w);
        __nv_bfloat16 l0 = __float2bfloat16(v.x - __bfloat162float(h0));
        __nv_bfloat16 l1 = __float2bfloat16(v.y - __bfloat162float(h1));
        __nv_bfloat16 l2 = __float2bfloat16(v.z - __bfloat162float(h2));
        __nv_bfloat16 l3 = __float2bfloat16(v.w - __bfloat162float(h3));
        ((__nv_bfloat162*)(hi + i))[0] = __nv_bfloat162(h0, h1);
        ((__nv_bfloat162*)(hi + i))[1] = __nv_bfloat162(h2, h3);
        ((__nv_bfloat162*)(lo + i))[0] = __nv_bfloat162(l0, l1);
        ((__nv_bfloat162*)(lo + i))[1] = __nv_bfloat162(l2, l3);
    }
}

// ---------------- prep: counting sort desc, prefix offsets, token compaction --
__global__ void prep_kernel(const int* __restrict__ slen_c, const int* __restrict__ tokens_c,
                            const int* __restrict__ slen_s, const int* __restrict__ tokens_s)
{
    __shared__ int hist[64];
    __shared__ int base[64];
    __shared__ int ssum[256];
    const int tid = threadIdx.x;

    if (tid < 64) hist[tid] = 0;
    __syncthreads();
    for (int i = tid; i < BC_; i += 256) atomicAdd(&hist[slen_c[i]], 1);
    __syncthreads();
    if (tid <= TS_) {
        int c = 0;
        if (tid < 64) for (int k = tid; k < 64; k++) c += hist[k];
        g_cnt_c[tid] = (tid < TC_) ? c : 0;
    }
    if (tid == 0) {
        int run = 0;
        for (int k = 63; k >= 0; k--) { base[k] = run; run += hist[k]; }
    }
    __syncthreads();
    for (int i = tid; i < BC_; i += 256) {
        int pos = atomicAdd(&base[slen_c[i]], 1);
        g_order_c[pos] = i;
    }
    {
        const int chunk = BC_ / 256;
        int s = 0;
        for (int i = 0; i < chunk; i++) s += slen_c[tid * chunk + i] + 1;
        ssum[tid] = s;
        __syncthreads();
        for (int d = 1; d < 256; d <<= 1) {
            int v = (tid >= d) ? ssum[tid - d] : 0;
            __syncthreads();
            ssum[tid] += v;
            __syncthreads();
        }
        int run = (tid > 0) ? ssum[tid - 1] : 0;
        for (int i = 0; i < chunk; i++) {
            int b = tid * chunk + i;
            g_off_c[b] = run;
            run += slen_c[b] + 1;
        }
        if (tid == 255) { g_off_c[BC_] = ssum[255]; g_Mc[0] = ssum[255]; }
    }
    __syncthreads();
    for (int i = tid; i < BC_ * TC_; i += 256) {
        int b = i / TC_, t = i % TC_;
        if (t <= slen_c[b]) g_tok_c[g_off_c[b] + t] = tokens_c[i];
    }
    __syncthreads();

    if (tid < 64) hist[tid] = 0;
    __syncthreads();
    for (int i = tid; i < B_; i += 256) atomicAdd(&hist[slen_s[i]], 1);
    __syncthreads();
    if (tid <= TS_) {
        int c = 0;
        if (tid < 64) for (int k = tid; k < 64; k++) c += hist[k];
        g_cnt_s[tid] = (tid < TS_) ? c : 0;
    }
    if (tid == 0) {
        int run = 0;
        for (int k = 63; k >= 0; k--) { base[k] = run; run += hist[k]; }
    }
    __syncthreads();
    for (int i = tid; i < B_; i += 256) {
        int pos = atomicAdd(&base[slen_s[i]], 1);
        g_order_s[pos] = i;
    }
    {
        int s = (tid < B_) ? slen_s[tid] + 1 : 0;
        ssum[tid] = s;
        __syncthreads();
        for (int d = 1; d < 256; d <<= 1) {
            int v = (tid >= d) ? ssum[tid - d] : 0;
            __syncthreads();
            ssum[tid] += v;
            __syncthreads();
        }
        if (tid < B_) g_off_s[tid] = ssum[tid] - (slen_s[tid] + 1);
        if (tid == 255) { g_off_s[B_] = ssum[255]; g_Ms[0] = ssum[255]; }
    }
    __syncthreads();
    for (int i = tid; i < B_ * TS_; i += 256) {
        int b = i / TS_, t = i % TS_;
        if (t <= slen_s[b]) g_tok_s[g_off_s[b] + t] = tokens_s[i];
    }
}

// ---------------- bf16-split HMMA GEMM, fp32 in, split-on-stage ---------------
#define STRIDE_ 72
#define GTILE_  (128 * STRIDE_)
#define GEMM_SMEM (4 * GTILE_ * 2)

__global__ void __launch_bounds__(256, 2) gemm_mma(
    const float* __restrict__ A, const int* __restrict__ idx,
    const int* __restrict__ Mdev,
    const float* __restrict__ B, const float* __restrict__ bias,
    float* __restrict__ C, int M, int N)
{
    extern __shared__ __align__(16) __nv_bfloat16 smem[];
    const int Mq = Mdev ? *Mdev : M;
    const int bm = blockIdx.x * 128, bn = blockIdx.y * 128;
    if (bm >= Mq) return;
    const int tid = threadIdx.x, wid = tid >> 5, lane = tid & 31;
    const int warp_m = wid & 1, warp_n = wid >> 1;

    __nv_bfloat16* sAh = smem;
    __nv_bfloat16* sAl = smem + GTILE_;
    __nv_bfloat16* sBh = smem + 2 * GTILE_;
    __nv_bfloat16* sBl = smem + 3 * GTILE_;
    const uint32_t uAh = smem_u32(sAh), uAl = smem_u32(sAl);
    const uint32_t uBh = smem_u32(sBh), uBl = smem_u32(sBl);

    const int fr = lane & 15;
    const int fc = (lane >> 4) * 8;
    const int arow_f = warp_m * 64 + fr;
    const int brow_f = warp_n * 32 + fr;

    float acc[4][4][4];
#pragma unroll
    for (int i = 0; i < 4; i++)
#pragma unroll
        for (int j = 0; j < 4; j++)
#pragma unroll
            for (int e = 0; e < 4; e++) acc[i][j][e] = 0.f;

    for (int kt = 0; kt < 4; kt++) {
        if (kt) __syncthreads();
#pragma unroll
        for (int i = 0; i < 4; i++) {
            const int id = i * 256 + tid;
            const int row = id >> 3, ch = id & 7;
            const int col = kt * 64 + ch * 8;
            int am = bm + row; if (am > Mq - 1) am = Mq - 1;
            const int ar = idx ? idx[am] : am;
            int br = bn + row; if (br > N - 1) br = N - 1;
            const int so = row * STRIDE_ + ch * 8;
            const float* ap = A + (size_t)ar * 256 + col;
            const float* bp = B + (size_t)br * 256 + col;
            split_store8(*(const float4*)ap, *(const float4*)(ap + 4),
                         sAh + so, sAl + so);
            split_store8(*(const float4*)bp, *(const float4*)(bp + 4),
                         sBh + so, sBl + so);
        }
        __syncthreads();

#pragma unroll
        for (int kk = 0; kk < 4; kk++) {
            const int col = kk * 16 + fc;
            uint32_t bh[2][4], bl[2][4], av[4][4];
#pragma unroll
            for (int p = 0; p < 2; p++) {
                const uint32_t off = 2u * ((brow_f + p * 16) * STRIDE_ + col);
                ldsm4(bh[p][0], bh[p][1], bh[p][2], bh[p][3], uBh + off);
                ldsm4(bl[p][0], bl[p][1], bl[p][2], bl[p][3], uBl + off);
            }
#pragma unroll
            for (int tm = 0; tm < 4; tm++) {
                const uint32_t off = 2u * ((arow_f + tm * 16) * STRIDE_ + col);
                ldsm4(av[tm][0], av[tm][1], av[tm][2], av[tm][3], uAh + off);
            }
#pragma unroll
            for (int tm = 0; tm < 4; tm++)
#pragma unroll
                for (int tn = 0; tn < 4; tn++) {
                    const int p = tn >> 1, o = tn & 1;
                    mma16816(acc[tm][tn], av[tm], bh[p][o], bh[p][o + 2]);
                    mma16816(acc[tm][tn], av[tm], bl[p][o], bl[p][o + 2]);
                }
#pragma unroll
            for (int tm = 0; tm < 4; tm++) {
                const uint32_t off = 2u * ((arow_f + tm * 16) * STRIDE_ + col);
                ldsm4(av[tm][0], av[tm][1], av[tm][2], av[tm][3], uAl + off);
            }
#pragma unroll
            for (int tm = 0; tm < 4; tm++)
#pragma unroll
                for (int tn = 0; tn < 4; tn++) {
                    const int p = tn >> 1, o = tn & 1;
                    mma16816(acc[tm][tn], av[tm], bh[p][o], bh[p][o + 2]);
                }
        }
    }

    const int mrow = bm + warp_m * 64 + (lane >> 2);
    const int ncol = bn + warp_n * 32 + (lane & 3) * 2;
#pragma unroll
    for (int tm = 0; tm < 4; tm++) {
#pragma unroll
        for (int half = 0; half < 2; half++) {
            const int m = mrow + tm * 16 + half * 8;
            if (m >= Mq) continue;
            float* crow = C + (size_t)m * N;
#pragma unroll
            for (int tn = 0; tn < 4; tn++) {
                const int n0 = ncol + tn * 8;
                const float v0 = acc[tm][tn][half * 2 + 0]
                               + (bias ? bias[n0] : 0.f);
                if (n0 + 1 < N) {
                    const float v1 = acc[tm][tn][half * 2 + 1]
                                   + (bias ? bias[n0 + 1] : 0.f);
                    *(float2*)(crow + n0) = make_float2(v0, v1);
                } else if (n0 < N) {
                    crow[n0] = v0;
                }
            }
        }
    }
}

// ---------------- persistent HMMA GRU (resident weights + grid barrier) -------
// 144 blocks (all resident: 148 SMs, 1 CTA/SM at 180 KB smem). Block owns a
// j-slice of 32 (8 slices) and a rowset. Whh hi/lo slice (96 gate-rows x 256 k)
// staged to smem ONCE; 50 steps in-kernel, grid barrier between steps.
// Warps: 4m (16 rows) x 2n (16 j); each warp holds all 3 gates for its j-slice.
#define NBLK 144
#define WKT 6912              // 96*72 elems per kt
#define AKT 4608              // 64*72 elems per kt
#define GRUP_ELEMS (4 * WKT * 2 + 4 * AKT * 2)
#define GRUP_SMEM (GRUP_ELEMS * 2)   // 184320 bytes

__global__ void __launch_bounds__(256, 1) gru_persist(
    const __nv_bfloat16* __restrict__ Whi_c, const __nv_bfloat16* __restrict__ Wlo_c,
    const float* __restrict__ bhh_c, const float* __restrict__ gi_c,
    const float* __restrict__ mask_c, float* __restrict__ gath_c,
    const int* __restrict__ slen_c,
    const __nv_bfloat16* __restrict__ Whi_s, const __nv_bfloat16* __restrict__ Wlo_s,
    const float* __restrict__ bhh_s, const float* __restrict__ gi_s,
    const float* __restrict__ mask_s, float* __restrict__ gath_s,
    const int* __restrict__ slen_s)
{
    extern __shared__ __align__(16) __nv_bfloat16 psm[];
    __nv_bfloat16* sWh = psm;                 // [4][96][72]
    __nv_bfloat16* sWl = psm + 4 * WKT;
    __nv_bfloat16* sAh = psm + 8 * WKT;       // [4][64][72]
    __nv_bfloat16* sAl = psm + 8 * WKT + 4 * AKT;
    const uint32_t uWh = smem_u32(sWh), uWl = smem_u32(sWl);
    const uint32_t uAh = smem_u32(sAh), uAl = smem_u32(sAl);

    const int blk = blockIdx.x;
    const int tid = threadIdx.x, wid = tid >> 5, lane = tid & 31;
    const int warp_m = wid & 3, warp_n = wid >> 2;   // 4m x 2n
    const int fr = lane & 15;
    const int fc = (lane >> 4) * 8;

    const bool isCat = blk < 128;
    const int local = isCat ? blk : (blk - 128);
    const int jsl = local & 7;            // 8 j-slices of 32
    const int rowset = local >> 3;        // cat 0..15, short 0..1
    const int rstride = isCat ? 16 : 2;
    const int maxchunk = isCat ? 40 : 4;
    const int j0 = jsl * 32;

    const __nv_bfloat16* Whi = isCat ? Whi_c : Whi_s;
    const __nv_bfloat16* Wlo = isCat ? Wlo_c : Wlo_s;
    const float* bhh = isCat ? bhh_c : bhh_s;
    const float* gi = isCat ? gi_c : gi_s;
    const float* mask = isCat ? mask_c : mask_s;
    float* gath = isCat ? gath_c : gath_s;
    const int* slen = isCat ? slen_c : slen_s;
    const int* order = isCat ? g_order_c : g_order_s;
    const int* off = isCat ? g_off_c : g_off_s;
    const int* cnt = isCat ? g_cnt_c : g_cnt_s;
    const int maskT = isCat ? TC_ : TS_;
    float* hbufA = isCat ? g_hA : g_hsA;
    float* hbufB = isCat ? g_hB : g_hsB;

    // stage Whh slice ONCE: rows r = g*32 + j (96), all 4 kt chunks
#pragma unroll
    for (int i = 0; i < 12; i++) {
        const int id = i * 256 + tid;       // 0..3071
        const int ch = id & 7;
        const int kt = (id >> 3) & 3;
        const int r = id >> 5;              // 0..95
        const int grow = (r >> 5) * 256 + j0 + (r & 31);
        const int col = kt * 64 + ch * 8;
        const int so = kt * WKT + r * STRIDE_ + ch * 8;
        *(uint4*)(sWh + so) = *(const uint4*)(Whi + (size_t)grow * 256 + col);
        *(uint4*)(sWl + so) = *(const uint4*)(Wlo + (size_t)grow * 256 + col);
    }
    __syncthreads();

    for (int t = 0; t < TS_; t++) {
        const int active = cnt[t];
        const float* h_in = (t & 1) ? hbufB : hbufA;
        float* h_out = (t & 1) ? hbufA : hbufB;

        for (int c = rowset; c < maxchunk && c * 64 < active; c += rstride) {
            const int bm = c * 64;
            __syncthreads();   // protect A smem from previous chunk's readers
            float acc[6][4];
#pragma unroll
            for (int j = 0; j < 6; j++)
#pragma unroll
                for (int e = 0; e < 4; e++) acc[j][e] = 0.f;

            if (t > 0) {
                // stage A: 64 rows x 256 k, fp32 -> bf16 hi/lo
#pragma unroll
                for (int i = 0; i < 16; i++) {
                    const int id = i * 256 + tid;   // 0..4095
                    const int sl = id >> 6;          // 0..63
                    const int q = id & 63;
                    const int kt = q >> 4, c4 = q & 15;
                    int gs = bm + sl; if (gs > active - 1) gs = active - 1;
                    const int row = order[gs];
                    float4 v = *(const float4*)(h_in + (size_t)row * 256 + kt * 64 + c4 * 4);
                    __nv_bfloat16 h0 = __float2bfloat16(v.x);
                    __nv_bfloat16 h1 = __float2bfloat16(v.y);
                    __nv_bfloat16 h2 = __float2bfloat16(v.z);
                    __nv_bfloat16 h3 = __float2bfloat16(v.w);
                    const int so = kt * AKT + sl * STRIDE_ + c4 * 4;
                    *(__nv_bfloat162*)(sAh + so)     = __nv_bfloat162(h0, h1);
                    *(__nv_bfloat162*)(sAh + so + 2) = __nv_bfloat162(h2, h3);
                    *(__nv_bfloat162*)(sAl + so) =
                        __nv_bfloat162(__float2bfloat16(v.x - __bfloat162float(h0)),
                                       __float2bfloat16(v.y - __bfloat162float(h1)));
                    *(__nv_bfloat162*)(sAl + so + 2) =
                        __nv_bfloat162(__float2bfloat16(v.z - __bfloat162float(h2)),
                                       __float2bfloat16(v.w - __bfloat162float(h3)));
                }
                __syncthreads();

#pragma unroll
                for (int kt = 0; kt < 4; kt++) {
#pragma unroll
                    for (int kk = 0; kk < 4; kk++) {
                        const int col = kk * 16 + fc;
                        uint32_t bh[3][4], bl[3][4], avh[4], avl[4];
#pragma unroll
                        for (int g = 0; g < 3; g++) {
                            const uint32_t o = 2u * (kt * WKT +
                                (g * 32 + warp_n * 16 + fr) * STRIDE_ + col);
                            ldsm4(bh[g][0], bh[g][1], bh[g][2], bh[g][3], uWh + o);
                            ldsm4(bl[g][0], bl[g][1], bl[g][2], bl[g][3], uWl + o);
                        }
                        {
                            const uint32_t o = 2u * (kt * AKT +
                                (warp_m * 16 + fr) * STRIDE_ + col);
                            ldsm4(avh[0], avh[1], avh[2], avh[3], uAh + o);
                            ldsm4(avl[0], avl[1], avl[2], avl[3], uAl + o);
                        }
#pragma unroll
                        for (int g = 0; g < 3; g++)
#pragma unroll
                            for (int o = 0; o < 2; o++) {
                                mma16816(acc[g * 2 + o], avh, bh[g][o], bh[g][o + 2]);
                                mma16816(acc[g * 2 + o], avh, bl[g][o], bl[g][o + 2]);
                                mma16816(acc[g * 2 + o], avl, bh[g][o], bh[g][o + 2]);
                            }
                    }
                }
            }

            // register epilogue
#pragma unroll
            for (int o = 0; o < 2; o++)
#pragma unroll
                for (int e = 0; e < 4; e++) {
                    const int m_local = warp_m * 16 + (lane >> 2) + 8 * (e >> 1);
                    const int slot = bm + m_local;
                    if (slot >= active) continue;
                    const int b = order[slot];
                    const int j = warp_n * 16 + o * 8 + (lane & 3) * 2 + (e & 1);
                    const int jj = j0 + j;
                    const size_t gbase = ((size_t)(off[b] + t)) * H3_ + jj;
                    const float gr = gi[gbase];
                    const float gz = gi[gbase + H_];
                    const float gn = gi[gbase + 2 * H_];
                    const float hold = (t > 0) ? h_in[(size_t)b * H_ + jj] : 0.f;
                    const float r = fast_sigmoid(gr + acc[0 + o][e] + bhh[jj]);
                    const float z = fast_sigmoid(gz + acc[2 + o][e] + bhh[H_ + jj]);
                    const float n = fast_tanh(gn + r * (acc[4 + o][e] + bhh[2 * H_ + jj]));
                    const float hnew = (1.f - z) * n + z * hold;
                    h_out[(size_t)b * H_ + jj] = hnew;
                    if (slen[b] == t)
                        gath[(size_t)b * H_ + jj] =
                            hnew * mask[(size_t)b * maskT + t];
                }
        }

        if (t + 1 < TS_) grid_barrier(NBLK);
    }
}

// ---------------- attention ----------------------------------------------------
__global__ void attention_kernel(const float* __restrict__ seq_cate,
                                 const float* __restrict__ out_short,
                                 const float* __restrict__ mask_seq,
                                 float* __restrict__ sum_cate)
{
    const int b = blockIdx.x;
    const int j = threadIdx.x;
    __shared__ float red[8];
    __shared__ float w[S_];
    const float os = out_short[(size_t)b * H_ + j];
    float sc[S_];
#pragma unroll
    for (int s = 0; s < S_; s++)
        sc[s] = seq_cate[(size_t)(b * S_ + s) * H_ + j];

    for (int s = 0; s < S_; s++) {
        float v = sc[s] * os;
#pragma unroll
        for (int off = 16; off; off >>= 1) v += __shfl_xor_sync(0xffffffffu, v, off);
        if ((j & 31) == 0) red[j >> 5] = v;
        __syncthreads();
        if (j == 0) {
            float x = 0.f;
#pragma unroll
            for (int q = 0; q < 8; q++) x += red[q];
            w[s] = x;
        }
        __syncthreads();
    }
    if (j == 0) {
        float mx = w[0];
        for (int s = 1; s < S_; s++) mx = fmaxf(mx, w[s]);
        float e[S_];
        float sum = 0.f;
        for (int s = 0; s < S_; s++) { e[s] = expf(w[s] - mx); sum += e[s]; }
        float s2 = 0.f;
        for (int s = 0; s < S_; s++) {
            e[s] = (e[s] / sum) * mask_seq[(size_t)b * S_ + s];
            s2 += e[s];
        }
        for (int s = 0; s < S_; s++) w[s] = e[s] / s2;
    }
    __syncthreads();
    float acc = 0.f;
#pragma unroll
    for (int s = 0; s < S_; s++) acc += w[s] * sc[s];
    sum_cate[(size_t)b * H_ + j] = acc;
}

// ---------------- FC -----------------------------------------------------------
__global__ void fc_kernel(const float* __restrict__ sum_cate,
                          const float* __restrict__ out_short,
                          const float* __restrict__ fcW,
                          const float* __restrict__ fcb,
                          float* __restrict__ fc_out)
{
    __shared__ float mix[16][2 * H_];
    const int b0 = blockIdx.x * 16;
    for (int idx = threadIdx.x; idx < 16 * 2 * H_; idx += 256) {
        const int bb = idx >> 9, k = idx & 511;
        mix[bb][k] = (k < H_) ? sum_cate[(size_t)(b0 + bb) * H_ + k]
                              : out_short[(size_t)(b0 + bb) * H_ + (k - H_)];
    }
    __syncthreads();
    const int i = threadIdx.x;
    const float* wrow = fcW + (size_t)i * (2 * H_);
    float acc[16];
#pragma unroll
    for (int bb = 0; bb < 16; bb++) acc[bb] = 0.f;
    for (int k = 0; k < 2 * H_; k++) {
        const float wv = wrow[k];
#pragma unroll
        for (int bb = 0; bb < 16; bb++) acc[bb] += wv * mix[bb][k];
    }
    const float bias = fcb[i];
#pragma unroll
    for (int bb = 0; bb < 16; bb++)
        fc_out[(size_t)(b0 + bb) * H_ + i] = acc[bb] + bias;
}

__global__ void write_targets(const int* __restrict__ tgt, float* __restrict__ out)
{
    out[threadIdx.x] = (float)tgt[threadIdx.x];
}

// ---------------- launcher ----------------------------------------------------
extern "C" void kernel_launch(void* const* d_in, const int* in_sizes, int n_in,
                              void* d_out, int out_size)
{
    const int*   in_cate       = (const int*)d_in[0];
    const float* mask_cate     = (const float*)d_in[1];
    const float* mask_cate_seq = (const float*)d_in[2];
    const int*   subseqLen     = (const int*)d_in[5];
    const int*   in_batch      = (const int*)d_in[7];
    const float* mask_b        = (const float*)d_in[8];
    const int*   seqLen        = (const int*)d_in[9];
    const int*   target        = (const int*)d_in[10];
    const float* emb           = (const float*)d_in[12];
    const float* Wih_c         = (const float*)d_in[13];
    const float* Whh_c         = (const float*)d_in[14];
    const float* bih_c         = (const float*)d_in[15];
    const float* bhh_c         = (const float*)d_in[16];
    const float* Wih_s         = (const float*)d_in[17];
    const float* Whh_s         = (const float*)d_in[18];
    const float* bih_s         = (const float*)d_in[19];
    const float* bhh_s         = (const float*)d_in[20];
    const float* fc_W          = (const float*)d_in[21];
    const float* fc_b          = (const float*)d_in[22];
    float* out = (float*)d_out;

    float *gi_c, *gi_s, *seqc, *osht, *sumc, *fco;
    int *tok_c, *tok_s, *Mc, *Ms;
    __nv_bfloat16 *whc_hi, *whc_lo, *whs_hi, *whs_lo;
    cudaGetSymbolAddress((void**)&gi_c, g_gi_c);
    cudaGetSymbolAddress((void**)&gi_s, g_gi_s);
    cudaGetSymbolAddress((void**)&seqc, g_seq_cate);
    cudaGetSymbolAddress((void**)&osht, g_out_short);
    cudaGetSymbolAddress((void**)&sumc, g_sum_cate);
    cudaGetSymbolAddress((void**)&fco,  g_fc_out);
    cudaGetSymbolAddress((void**)&tok_c, g_tok_c);
    cudaGetSymbolAddress((void**)&tok_s, g_tok_s);
    cudaGetSymbolAddress((void**)&Mc, g_Mc);
    cudaGetSymbolAddress((void**)&Ms, g_Ms);
    cudaGetSymbolAddress((void**)&whc_hi, g_whc_hi);
    cudaGetSymbolAddress((void**)&whc_lo, g_whc_lo);
    cudaGetSymbolAddress((void**)&whs_hi, g_whs_hi);
    cudaGetSymbolAddress((void**)&whs_lo, g_whs_lo);

    cudaFuncSetAttribute(gemm_mma, cudaFuncAttributeMaxDynamicSharedMemorySize,
                         GEMM_SMEM);
    cudaFuncSetAttribute(gru_persist,
                         cudaFuncAttributeMaxDynamicSharedMemorySize, GRUP_SMEM);

    // 0) prep + Whh bf16 splits
    prep_kernel<<<1, 256>>>(subseqLen, in_cate, seqLen, in_batch);
    split_kernel<<<192, 256>>>(Whh_c, whc_hi, whc_lo, H3_ * H_);
    split_kernel<<<192, 256>>>(Whh_s, whs_hi, whs_lo, H3_ * H_);

    // 1) input-gate GEMMs over compacted tokens (split-on-stage HMMA)
    gemm_mma<<<dim3((BC_ * TC_ + 127) / 128, H3_ / 128), 256, GEMM_SMEM>>>(
        emb, tok_c, Mc, Wih_c, bih_c, gi_c, BC_ * TC_, H3_);
    gemm_mma<<<dim3((B_ * TS_ + 127) / 128, H3_ / 128), 256, GEMM_SMEM>>>(
        emb, tok_s, Ms, Wih_s, bih_s, gi_s, B_ * TS_, H3_);

    // 2+3) persistent HMMA GRU: ONE launch, 50 steps in-kernel
    gru_persist<<<NBLK, 256, GRUP_SMEM>>>(
        whc_hi, whc_lo, bhh_c, gi_c, mask_cate, seqc, subseqLen,
        whs_hi, whs_lo, bhh_s, gi_s, mask_b, osht, seqLen);

    // 4) attention + 5) FC
    attention_kernel<<<B_, 256>>>(seqc, osht, mask_cate_seq, sumc);
    fc_kernel<<<B_ / 16, 256>>>(sumc, osht, fc_W, fc_b, fco);

    // 6) logits = fc_out @ emb^T (split-on-stage HMMA)
    gemm_mma<<<dim3(B_ / 128, (V_ + 127) / 128), 256, GEMM_SMEM>>>(
        fco, nullptr, nullptr, emb, nullptr, out, B_, V_);

    // 7) targets appended as float, if the output carries them
    if (out_size >= B_ * V_ + B_)
        write_targets<<<1, B_>>>(target, out + (size_t)B_ * V_);
}

// round 12
// speedup vs baseline: 5.2767x; 1.2639x over previous
#include <cuda_runtime.h>
#include <cuda_bf16.h>
#include <math.h>
#include <stdint.h>

// Problem constants (fixed by setup_inputs)
#define V_  100000
#define E_  256
#define H_  256
#define B_  256
#define S_  10
#define TC_ 20
#define TS_ 50
#define BC_ (B_ * S_)   // 2560
#define H3_ (3 * H_)    // 768

// ---------------- scratch (static device globals; no allocation) --------------
__device__ float g_gi_c[(size_t)BC_ * TC_ * H3_];
__device__ float g_gi_s[(size_t)B_ * TS_ * H3_];
__device__ float g_hA[BC_ * H_];
__device__ float g_hB[BC_ * H_];
__device__ float g_hsA[B_ * H_];
__device__ float g_hsB[B_ * H_];
__device__ float g_seq_cate[BC_ * H_];
__device__ float g_out_short[B_ * H_];
__device__ float g_sum_cate[B_ * H_];
__device__ float g_fc_out[B_ * H_];
__device__ int   g_order_c[BC_];
__device__ int   g_order_s[B_];
__device__ int   g_off_c[BC_ + 1];
__device__ int   g_off_s[B_ + 1];
__device__ int   g_tok_c[BC_ * TC_];
__device__ int   g_tok_s[B_ * TS_];
__device__ int   g_cnt_c[TS_ + 1];
__device__ int   g_cnt_s[TS_ + 1];
__device__ int   g_Mc[1];
__device__ int   g_Ms[1];
// pre-split Whh
__device__ __nv_bfloat16 g_whc_hi[H3_ * H_];
__device__ __nv_bfloat16 g_whc_lo[H3_ * H_];
__device__ __nv_bfloat16 g_whs_hi[H3_ * H_];
__device__ __nv_bfloat16 g_whs_lo[H3_ * H_];
// per-group barrier state (18 groups of 8 blocks)
#define NGRP 18
__device__ unsigned g_bar_cnt[NGRP];
__device__ volatile unsigned g_bar_gen[NGRP];

// ---------------- helpers ------------------------------------------------------
__device__ __forceinline__ float fast_sigmoid(float x) {
    return 1.f / (1.f + __expf(-x));
}
__device__ __forceinline__ float fast_tanh(float x) {
    float ax = fabsf(x);
    float e = __expf(-2.f * ax);
    float t = __fdividef(1.f - e, 1.f + e);
    return copysignf(t, x);
}
__device__ __forceinline__ uint32_t smem_u32(const void* p) {
    uint32_t a;
    asm("{ .reg .u64 t; cvta.to.shared.u64 t, %1; cvt.u32.u64 %0, t; }"
        : "=r"(a) : "l"(p));
    return a;
}
__device__ __forceinline__ void ldsm4(uint32_t& r0, uint32_t& r1, uint32_t& r2,
                                      uint32_t& r3, uint32_t addr) {
    asm volatile("ldmatrix.sync.aligned.m8n8.x4.shared.b16 {%0,%1,%2,%3}, [%4];"
                 : "=r"(r0), "=r"(r1), "=r"(r2), "=r"(r3) : "r"(addr));
}
__device__ __forceinline__ void mma16816(float* d, const uint32_t* a,
                                         uint32_t b0, uint32_t b1) {
    asm volatile(
        "mma.sync.aligned.m16n8k16.row.col.f32.bf16.bf16.f32 "
        "{%0,%1,%2,%3}, {%4,%5,%6,%7}, {%8,%9}, {%0,%1,%2,%3};"
        : "+f"(d[0]), "+f"(d[1]), "+f"(d[2]), "+f"(d[3])
        : "r"(a[0]), "r"(a[1]), "r"(a[2]), "r"(a[3]), "r"(b0), "r"(b1));
}
__device__ __forceinline__ void split_store8(float4 a0, float4 a1,
                                             __nv_bfloat16* hi,
                                             __nv_bfloat16* lo) {
    float f[8] = {a0.x, a0.y, a0.z, a0.w, a1.x, a1.y, a1.z, a1.w};
    __nv_bfloat16 h[8], l[8];
#pragma unroll
    for (int e = 0; e < 8; e++) h[e] = __float2bfloat16(f[e]);
#pragma unroll
    for (int e = 0; e < 8; e++)
        l[e] = __float2bfloat16(f[e] - __bfloat162float(h[e]));
    __nv_bfloat162 hp[4] = {{h[0], h[1]}, {h[2], h[3]}, {h[4], h[5]}, {h[6], h[7]}};
    __nv_bfloat162 lp[4] = {{l[0], l[1]}, {l[2], l[3]}, {l[4], l[5]}, {l[6], l[7]}};
    *(uint4*)hi = *(uint4*)hp;
    *(uint4*)lo = *(uint4*)lp;
}
__device__ __forceinline__ void group_barrier(int gid, unsigned nb) {
    __threadfence();
    __syncthreads();
    if (threadIdx.x == 0) {
        unsigned my = g_bar_gen[gid];
        if (atomicAdd(&g_bar_cnt[gid], 1u) == nb - 1u) {
            g_bar_cnt[gid] = 0u;
            __threadfence();
            g_bar_gen[gid] = my + 1u;
        } else {
            while (g_bar_gen[gid] == my) __nanosleep(32);
        }
    }
    __syncthreads();
}

// ---------------- fp32 -> bf16 hi/lo split (Whh only) -------------------------
__global__ void split_kernel(const float* __restrict__ src,
                             __nv_bfloat16* __restrict__ hi,
                             __nv_bfloat16* __restrict__ lo, int n)
{
    int i = (blockIdx.x * 256 + threadIdx.x) * 4;
    const int stride = gridDim.x * 256 * 4;
    for (; i < n; i += stride) {
        float4 v = *(const float4*)(src + i);
        __nv_bfloat16 h0 = __float2bfloat16(v.x);
        __nv_bfloat16 h1 = __float2bfloat16(v.y);
        __nv_bfloat16 h2 = __float2bfloat16(v.z);
        __nv_bfloat16 h3 = __float2bfloat16(v.w);
        __nv_bfloat16 l0 = __float2bfloat16(v.x - __bfloat162float(h0));
        __nv_bfloat16 l1 = __float2bfloat16(v.y - __bfloat162float(h1));
        __nv_bfloat16 l2 = __float2bfloat16(v.z - __bfloat162float(h2));
        __nv_bfloat16 l3 = __float2bfloat16(v.w - __bfloat162float(h3));
        ((__nv_bfloat162*)(hi + i))[0] = __nv_bfloat162(h0, h1);
        ((__nv_bfloat162*)(hi + i))[1] = __nv_bfloat162(h2, h3);
        ((__nv_bfloat162*)(lo + i))[0] = __nv_bfloat162(l0, l1);
        ((__nv_bfloat162*)(lo + i))[1] = __nv_bfloat162(l2, l3);
    }
}

// ---------------- prep: counting sort desc, prefix offsets, token compaction --
__global__ void prep_kernel(const int* __restrict__ slen_c, const int* __restrict__ tokens_c,
                            const int* __restrict__ slen_s, const int* __restrict__ tokens_s)
{
    __shared__ int hist[64];
    __shared__ int base[64];
    __shared__ int ssum[256];
    const int tid = threadIdx.x;

    if (tid < NGRP) { g_bar_cnt[tid] = 0u; }   // barrier state reset (idempotent)

    if (tid < 64) hist[tid] = 0;
    __syncthreads();
    for (int i = tid; i < BC_; i += 256) atomicAdd(&hist[slen_c[i]], 1);
    __syncthreads();
    if (tid <= TS_) {
        int c = 0;
        if (tid < 64) for (int k = tid; k < 64; k++) c += hist[k];
        g_cnt_c[tid] = (tid < TC_) ? c : 0;
    }
    if (tid == 0) {
        int run = 0;
        for (int k = 63; k >= 0; k--) { base[k] = run; run += hist[k]; }
    }
    __syncthreads();
    for (int i = tid; i < BC_; i += 256) {
        int pos = atomicAdd(&base[slen_c[i]], 1);
        g_order_c[pos] = i;
    }
    {
        const int chunk = BC_ / 256;
        int s = 0;
        for (int i = 0; i < chunk; i++) s += slen_c[tid * chunk + i] + 1;
        ssum[tid] = s;
        __syncthreads();
        for (int d = 1; d < 256; d <<= 1) {
            int v = (tid >= d) ? ssum[tid - d] : 0;
            __syncthreads();
            ssum[tid] += v;
            __syncthreads();
        }
        int run = (tid > 0) ? ssum[tid - 1] : 0;
        for (int i = 0; i < chunk; i++) {
            int b = tid * chunk + i;
            g_off_c[b] = run;
            run += slen_c[b] + 1;
        }
        if (tid == 255) { g_off_c[BC_] = ssum[255]; g_Mc[0] = ssum[255]; }
    }
    __syncthreads();
    for (int i = tid; i < BC_ * TC_; i += 256) {
        int b = i / TC_, t = i % TC_;
        if (t <= slen_c[b]) g_tok_c[g_off_c[b] + t] = tokens_c[i];
    }
    __syncthreads();

    if (tid < 64) hist[tid] = 0;
    __syncthreads();
    for (int i = tid; i < B_; i += 256) atomicAdd(&hist[slen_s[i]], 1);
    __syncthreads();
    if (tid <= TS_) {
        int c = 0;
        if (tid < 64) for (int k = tid; k < 64; k++) c += hist[k];
        g_cnt_s[tid] = (tid < TS_) ? c : 0;
    }
    if (tid == 0) {
        int run = 0;
        for (int k = 63; k >= 0; k--) { base[k] = run; run += hist[k]; }
    }
    __syncthreads();
    for (int i = tid; i < B_; i += 256) {
        int pos = atomicAdd(&base[slen_s[i]], 1);
        g_order_s[pos] = i;
    }
    {
        int s = (tid < B_) ? slen_s[tid] + 1 : 0;
        ssum[tid] = s;
        __syncthreads();
        for (int d = 1; d < 256; d <<= 1) {
            int v = (tid >= d) ? ssum[tid - d] : 0;
            __syncthreads();
            ssum[tid] += v;
            __syncthreads();
        }
        if (tid < B_) g_off_s[tid] = ssum[tid] - (slen_s[tid] + 1);
        if (tid == 255) { g_off_s[B_] = ssum[255]; g_Ms[0] = ssum[255]; }
    }
    __syncthreads();
    for (int i = tid; i < B_ * TS_; i += 256) {
        int b = i / TS_, t = i % TS_;
        if (t <= slen_s[b]) g_tok_s[g_off_s[b] + t] = tokens_s[i];
    }
}

// ---------------- bf16-split HMMA GEMM, fp32 in, split-on-stage ---------------
#define STRIDE_ 72
#define GTILE_  (128 * STRIDE_)
#define GEMM_SMEM (4 * GTILE_ * 2)

__global__ void __launch_bounds__(256, 2) gemm_mma(
    const float* __restrict__ A, const int* __restrict__ idx,
    const int* __restrict__ Mdev,
    const float* __restrict__ B, const float* __restrict__ bias,
    float* __restrict__ C, int M, int N)
{
    extern __shared__ __align__(16) __nv_bfloat16 smem[];
    const int Mq = Mdev ? *Mdev : M;
    const int bm = blockIdx.x * 128, bn = blockIdx.y * 128;
    if (bm >= Mq) return;
    const int tid = threadIdx.x, wid = tid >> 5, lane = tid & 31;
    const int warp_m = wid & 1, warp_n = wid >> 1;

    __nv_bfloat16* sAh = smem;
    __nv_bfloat16* sAl = smem + GTILE_;
    __nv_bfloat16* sBh = smem + 2 * GTILE_;
    __nv_bfloat16* sBl = smem + 3 * GTILE_;
    const uint32_t uAh = smem_u32(sAh), uAl = smem_u32(sAl);
    const uint32_t uBh = smem_u32(sBh), uBl = smem_u32(sBl);

    const int fr = lane & 15;
    const int fc = (lane >> 4) * 8;
    const int arow_f = warp_m * 64 + fr;
    const int brow_f = warp_n * 32 + fr;

    float acc[4][4][4];
#pragma unroll
    for (int i = 0; i < 4; i++)
#pragma unroll
        for (int j = 0; j < 4; j++)
#pragma unroll
            for (int e = 0; e < 4; e++) acc[i][j][e] = 0.f;

    for (int kt = 0; kt < 4; kt++) {
        if (kt) __syncthreads();
#pragma unroll
        for (int i = 0; i < 4; i++) {
            const int id = i * 256 + tid;
            const int row = id >> 3, ch = id & 7;
            const int col = kt * 64 + ch * 8;
            int am = bm + row; if (am > Mq - 1) am = Mq - 1;
            const int ar = idx ? idx[am] : am;
            int br = bn + row; if (br > N - 1) br = N - 1;
            const int so = row * STRIDE_ + ch * 8;
            const float* ap = A + (size_t)ar * 256 + col;
            const float* bp = B + (size_t)br * 256 + col;
            split_store8(*(const float4*)ap, *(const float4*)(ap + 4),
                         sAh + so, sAl + so);
            split_store8(*(const float4*)bp, *(const float4*)(bp + 4),
                         sBh + so, sBl + so);
        }
        __syncthreads();

#pragma unroll
        for (int kk = 0; kk < 4; kk++) {
            const int col = kk * 16 + fc;
            uint32_t bh[2][4], bl[2][4], av[4][4];
#pragma unroll
            for (int p = 0; p < 2; p++) {
                const uint32_t off = 2u * ((brow_f + p * 16) * STRIDE_ + col);
                ldsm4(bh[p][0], bh[p][1], bh[p][2], bh[p][3], uBh + off);
                ldsm4(bl[p][0], bl[p][1], bl[p][2], bl[p][3], uBl + off);
            }
#pragma unroll
            for (int tm = 0; tm < 4; tm++) {
                const uint32_t off = 2u * ((arow_f + tm * 16) * STRIDE_ + col);
                ldsm4(av[tm][0], av[tm][1], av[tm][2], av[tm][3], uAh + off);
            }
#pragma unroll
            for (int tm = 0; tm < 4; tm++)
#pragma unroll
                for (int tn = 0; tn < 4; tn++) {
                    const int p = tn >> 1, o = tn & 1;
                    mma16816(acc[tm][tn], av[tm], bh[p][o], bh[p][o + 2]);
                    mma16816(acc[tm][tn], av[tm], bl[p][o], bl[p][o + 2]);
                }
#pragma unroll
            for (int tm = 0; tm < 4; tm++) {
                const uint32_t off = 2u * ((arow_f + tm * 16) * STRIDE_ + col);
                ldsm4(av[tm][0], av[tm][1], av[tm][2], av[tm][3], uAl + off);
            }
#pragma unroll
            for (int tm = 0; tm < 4; tm++)
#pragma unroll
                for (int tn = 0; tn < 4; tn++) {
                    const int p = tn >> 1, o = tn & 1;
                    mma16816(acc[tm][tn], av[tm], bh[p][o], bh[p][o + 2]);
                }
        }
    }

    const int mrow = bm + warp_m * 64 + (lane >> 2);
    const int ncol = bn + warp_n * 32 + (lane & 3) * 2;
#pragma unroll
    for (int tm = 0; tm < 4; tm++) {
#pragma unroll
        for (int half = 0; half < 2; half++) {
            const int m = mrow + tm * 16 + half * 8;
            if (m >= Mq) continue;
            float* crow = C + (size_t)m * N;
#pragma unroll
            for (int tn = 0; tn < 4; tn++) {
                const int n0 = ncol + tn * 8;
                const float v0 = acc[tm][tn][half * 2 + 0]
                               + (bias ? bias[n0] : 0.f);
                if (n0 + 1 < N) {
                    const float v1 = acc[tm][tn][half * 2 + 1]
                                   + (bias ? bias[n0 + 1] : 0.f);
                    *(float2*)(crow + n0) = make_float2(v0, v1);
                } else if (n0 < N) {
                    crow[n0] = v0;
                }
            }
        }
    }
}

// ---------------- persistent HMMA GRU (per-group barriers) --------------------
// 144 blocks: 112 cat (14 rowset groups x 8 j-slices) + 32 short (4 groups x 8).
// Each group of 8 blocks is an independent pipeline: its rows' h vectors are
// written and re-read only within the group -> 8-way barrier, no global sync.
// Cat groups run 20 steps then exit; short groups run 50 (1 chunk/block/step).
#define NBLK 144
#define CAT_RS 14
#define SHT_RS 4
#define WKT 6912              // 96*72 elems per kt
#define AKT 4608              // 64*72 elems per kt
#define GRUP_ELEMS (4 * WKT * 2 + 4 * AKT * 2)
#define GRUP_SMEM (GRUP_ELEMS * 2)   // 184320 bytes

__global__ void __launch_bounds__(256, 1) gru_persist(
    const __nv_bfloat16* __restrict__ Whi_c, const __nv_bfloat16* __restrict__ Wlo_c,
    const float* __restrict__ bhh_c, const float* __restrict__ gi_c,
    const float* __restrict__ mask_c, float* __restrict__ gath_c,
    const int* __restrict__ slen_c,
    const __nv_bfloat16* __restrict__ Whi_s, const __nv_bfloat16* __restrict__ Wlo_s,
    const float* __restrict__ bhh_s, const float* __restrict__ gi_s,
    const float* __restrict__ mask_s, float* __restrict__ gath_s,
    const int* __restrict__ slen_s)
{
    extern __shared__ __align__(16) __nv_bfloat16 psm[];
    __nv_bfloat16* sWh = psm;                 // [4][96][72]
    __nv_bfloat16* sWl = psm + 4 * WKT;
    __nv_bfloat16* sAh = psm + 8 * WKT;       // [4][64][72]
    __nv_bfloat16* sAl = psm + 8 * WKT + 4 * AKT;
    const uint32_t uWh = smem_u32(sWh), uWl = smem_u32(sWl);
    const uint32_t uAh = smem_u32(sAh), uAl = smem_u32(sAl);

    const int blk = blockIdx.x;
    const int tid = threadIdx.x, wid = tid >> 5, lane = tid & 31;
    const int warp_m = wid & 3, warp_n = wid >> 2;   // 4m x 2n
    const int fr = lane & 15;
    const int fc = (lane >> 4) * 8;

    const bool isCat = blk < 112;
    const int local = isCat ? blk : (blk - 112);
    const int jsl = local & 7;            // 8 j-slices of 32
    const int rowset = local >> 3;        // cat 0..13, short 0..3
    const int rstride = isCat ? CAT_RS : SHT_RS;
    const int maxchunk = isCat ? 40 : 4;
    const int tmax = isCat ? TC_ : TS_;
    const int gid = isCat ? rowset : (CAT_RS + rowset);
    const int j0 = jsl * 32;

    const __nv_bfloat16* Whi = isCat ? Whi_c : Whi_s;
    const __nv_bfloat16* Wlo = isCat ? Wlo_c : Wlo_s;
    const float* bhh = isCat ? bhh_c : bhh_s;
    const float* gi = isCat ? gi_c : gi_s;
    const float* mask = isCat ? mask_c : mask_s;
    float* gath = isCat ? gath_c : gath_s;
    const int* slen = isCat ? slen_c : slen_s;
    const int* order = isCat ? g_order_c : g_order_s;
    const int* off = isCat ? g_off_c : g_off_s;
    const int* cnt = isCat ? g_cnt_c : g_cnt_s;
    const int maskT = isCat ? TC_ : TS_;
    float* hbufA = isCat ? g_hA : g_hsA;
    float* hbufB = isCat ? g_hB : g_hsB;

    // stage Whh slice ONCE: rows r = g*32 + j (96), all 4 kt chunks
#pragma unroll
    for (int i = 0; i < 12; i++) {
        const int id = i * 256 + tid;       // 0..3071
        const int ch = id & 7;
        const int kt = (id >> 3) & 3;
        const int r = id >> 5;              // 0..95
        const int grow = (r >> 5) * 256 + j0 + (r & 31);
        const int col = kt * 64 + ch * 8;
        const int so = kt * WKT + r * STRIDE_ + ch * 8;
        *(uint4*)(sWh + so) = *(const uint4*)(Whi + (size_t)grow * 256 + col);
        *(uint4*)(sWl + so) = *(const uint4*)(Wlo + (size_t)grow * 256 + col);
    }
    __syncthreads();

    for (int t = 0; t < tmax; t++) {
        const int active = cnt[t];
        const float* h_in = (t & 1) ? hbufB : hbufA;
        float* h_out = (t & 1) ? hbufA : hbufB;

        for (int c = rowset; c < maxchunk && c * 64 < active; c += rstride) {
            const int bm = c * 64;
            __syncthreads();   // protect A smem from previous chunk's readers
            float acc[6][4];
#pragma unroll
            for (int j = 0; j < 6; j++)
#pragma unroll
                for (int e = 0; e < 4; e++) acc[j][e] = 0.f;

            if (t > 0) {
                // stage A: 64 rows x 256 k, fp32 -> bf16 hi/lo (L2-coherent loads)
#pragma unroll
                for (int i = 0; i < 16; i++) {
                    const int id = i * 256 + tid;   // 0..4095
                    const int sl = id >> 6;          // 0..63
                    const int q = id & 63;
                    const int kt = q >> 4, c4 = q & 15;
                    int gs = bm + sl; if (gs > active - 1) gs = active - 1;
                    const int row = order[gs];
                    float4 v = __ldcg((const float4*)(h_in + (size_t)row * 256 + kt * 64 + c4 * 4));
                    __nv_bfloat16 h0 = __float2bfloat16(v.x);
                    __nv_bfloat16 h1 = __float2bfloat16(v.y);
                    __nv_bfloat16 h2 = __float2bfloat16(v.z);
                    __nv_bfloat16 h3 = __float2bfloat16(v.w);
                    const int so = kt * AKT + sl * STRIDE_ + c4 * 4;
                    *(__nv_bfloat162*)(sAh + so)     = __nv_bfloat162(h0, h1);
                    *(__nv_bfloat162*)(sAh + so + 2) = __nv_bfloat162(h2, h3);
                    *(__nv_bfloat162*)(sAl + so) =
                        __nv_bfloat162(__float2bfloat16(v.x - __bfloat162float(h0)),
                                       __float2bfloat16(v.y - __bfloat162float(h1)));
                    *(__nv_bfloat162*)(sAl + so + 2) =
                        __nv_bfloat162(__float2bfloat16(v.z - __bfloat162float(h2)),
                                       __float2bfloat16(v.w - __bfloat162float(h3)));
                }
                __syncthreads();

#pragma unroll
                for (int kt = 0; kt < 4; kt++) {
#pragma unroll
                    for (int kk = 0; kk < 4; kk++) {
                        const int col = kk * 16 + fc;
                        uint32_t bh[3][4], bl[3][4], avh[4], avl[4];
#pragma unroll
                        for (int g = 0; g < 3; g++) {
                            const uint32_t o = 2u * (kt * WKT +
                                (g * 32 + warp_n * 16 + fr) * STRIDE_ + col);
                            ldsm4(bh[g][0], bh[g][1], bh[g][2], bh[g][3], uWh + o);
                            ldsm4(bl[g][0], bl[g][1], bl[g][2], bl[g][3], uWl + o);
                        }
                        {
                            const uint32_t o = 2u * (kt * AKT +
                                (warp_m * 16 + fr) * STRIDE_ + col);
                            ldsm4(avh[0], avh[1], avh[2], avh[3], uAh + o);
                            ldsm4(avl[0], avl[1], avl[2], avl[3], uAl + o);
                        }
#pragma unroll
                        for (int g = 0; g < 3; g++)
#pragma unroll
                            for (int o = 0; o < 2; o++) {
                                mma16816(acc[g * 2 + o], avh, bh[g][o], bh[g][o + 2]);
                                mma16816(acc[g * 2 + o], avh, bl[g][o], bl[g][o + 2]);
                                mma16816(acc[g * 2 + o], avl, bh[g][o], bh[g][o + 2]);
                            }
                    }
                }
            }

            // register epilogue
#pragma unroll
            for (int o = 0; o < 2; o++)
#pragma unroll
                for (int e = 0; e < 4; e++) {
                    const int m_local = warp_m * 16 + (lane >> 2) + 8 * (e >> 1);
                    const int slot = bm + m_local;
                    if (slot >= active) continue;
                    const int b = order[slot];
                    const int j = warp_n * 16 + o * 8 + (lane & 3) * 2 + (e & 1);
                    const int jj = j0 + j;
                    const size_t gbase = ((size_t)(off[b] + t)) * H3_ + jj;
                    const float gr = gi[gbase];
                    const float gz = gi[gbase + H_];
                    const float gn = gi[gbase + 2 * H_];
                    const float hold = (t > 0)
                        ? __ldcg(h_in + (size_t)b * H_ + jj) : 0.f;
                    const float r = fast_sigmoid(gr + acc[0 + o][e] + bhh[jj]);
                    const float z = fast_sigmoid(gz + acc[2 + o][e] + bhh[H_ + jj]);
                    const float n = fast_tanh(gn + r * (acc[4 + o][e] + bhh[2 * H_ + jj]));
                    const float hnew = (1.f - z) * n + z * hold;
                    h_out[(size_t)b * H_ + jj] = hnew;
                    if (slen[b] == t)
                        gath[(size_t)b * H_ + jj] =
                            hnew * mask[(size_t)b * maskT + t];
                }
        }

        if (t + 1 < tmax) group_barrier(gid, 8u);
    }
}

// ---------------- attention ----------------------------------------------------
__global__ void attention_kernel(const float* __restrict__ seq_cate,
                                 const float* __restrict__ out_short,
                                 const float* __restrict__ mask_seq,
                                 float* __restrict__ sum_cate)
{
    const int b = blockIdx.x;
    const int j = threadIdx.x;
    __shared__ float red[8];
    __shared__ float w[S_];
    const float os = out_short[(size_t)b * H_ + j];
    float sc[S_];
#pragma unroll
    for (int s = 0; s < S_; s++)
        sc[s] = seq_cate[(size_t)(b * S_ + s) * H_ + j];

    for (int s = 0; s < S_; s++) {
        float v = sc[s] * os;
#pragma unroll
        for (int off = 16; off; off >>= 1) v += __shfl_xor_sync(0xffffffffu, v, off);
        if ((j & 31) == 0) red[j >> 5] = v;
        __syncthreads();
        if (j == 0) {
            float x = 0.f;
#pragma unroll
            for (int q = 0; q < 8; q++) x += red[q];
            w[s] = x;
        }
        __syncthreads();
    }
    if (j == 0) {
        float mx = w[0];
        for (int s = 1; s < S_; s++) mx = fmaxf(mx, w[s]);
        float e[S_];
        float sum = 0.f;
        for (int s = 0; s < S_; s++) { e[s] = expf(w[s] - mx); sum += e[s]; }
        float s2 = 0.f;
        for (int s = 0; s < S_; s++) {
            e[s] = (e[s] / sum) * mask_seq[(size_t)b * S_ + s];
            s2 += e[s];
        }
        for (int s = 0; s < S_; s++) w[s] = e[s] / s2;
    }
    __syncthreads();
    float acc = 0.f;
#pragma unroll
    for (int s = 0; s < S_; s++) acc += w[s] * sc[s];
    sum_cate[(size_t)b * H_ + j] = acc;
}

// ---------------- FC -----------------------------------------------------------
__global__ void fc_kernel(const float* __restrict__ sum_cate,
                          const float* __restrict__ out_short,
                          const float* __restrict__ fcW,
                          const float* __restrict__ fcb,
                          float* __restrict__ fc_out)
{
    __shared__ float mix[16][2 * H_];
    const int b0 = blockIdx.x * 16;
    for (int idx = threadIdx.x; idx < 16 * 2 * H_; idx += 256) {
        const int bb = idx >> 9, k = idx & 511;
        mix[bb][k] = (k < H_) ? sum_cate[(size_t)(b0 + bb) * H_ + k]
                              : out_short[(size_t)(b0 + bb) * H_ + (k - H_)];
    }
    __syncthreads();
    const int i = threadIdx.x;
    const float* wrow = fcW + (size_t)i * (2 * H_);
    float acc[16];
#pragma unroll
    for (int bb = 0; bb < 16; bb++) acc[bb] = 0.f;
    for (int k = 0; k < 2 * H_; k++) {
        const float wv = wrow[k];
#pragma unroll
        for (int bb = 0; bb < 16; bb++) acc[bb] += wv * mix[bb][k];
    }
    const float bias = fcb[i];
#pragma unroll
    for (int bb = 0; bb < 16; bb++)
        fc_out[(size_t)(b0 + bb) * H_ + i] = acc[bb] + bias;
}

__global__ void write_targets(const int* __restrict__ tgt, float* __restrict__ out)
{
    out[threadIdx.x] = (float)tgt[threadIdx.x];
}

// ---------------- launcher ----------------------------------------------------
extern "C" void kernel_launch(void* const* d_in, const int* in_sizes, int n_in,
                              void* d_out, int out_size)
{
    const int*   in_cate       = (const int*)d_in[0];
    const float* mask_cate     = (const float*)d_in[1];
    const float* mask_cate_seq = (const float*)d_in[2];
    const int*   subseqLen     = (const int*)d_in[5];
    const int*   in_batch      = (const int*)d_in[7];
    const float* mask_b        = (const float*)d_in[8];
    const int*   seqLen        = (const int*)d_in[9];
    const int*   target        = (const int*)d_in[10];
    const float* emb           = (const float*)d_in[12];
    const float* Wih_c         = (const float*)d_in[13];
    const float* Whh_c         = (const float*)d_in[14];
    const float* bih_c         = (const float*)d_in[15];
    const float* bhh_c         = (const float*)d_in[16];
    const float* Wih_s         = (const float*)d_in[17];
    const float* Whh_s         = (const float*)d_in[18];
    const float* bih_s         = (const float*)d_in[19];
    const float* bhh_s         = (const float*)d_in[20];
    const float* fc_W          = (const float*)d_in[21];
    const float* fc_b          = (const float*)d_in[22];
    float* out = (float*)d_out;

    float *gi_c, *gi_s, *seqc, *osht, *sumc, *fco;
    int *tok_c, *tok_s, *Mc, *Ms;
    __nv_bfloat16 *whc_hi, *whc_lo, *whs_hi, *whs_lo;
    cudaGetSymbolAddress((void**)&gi_c, g_gi_c);
    cudaGetSymbolAddress((void**)&gi_s, g_gi_s);
    cudaGetSymbolAddress((void**)&seqc, g_seq_cate);
    cudaGetSymbolAddress((void**)&osht, g_out_short);
    cudaGetSymbolAddress((void**)&sumc, g_sum_cate);
    cudaGetSymbolAddress((void**)&fco,  g_fc_out);
    cudaGetSymbolAddress((void**)&tok_c, g_tok_c);
    cudaGetSymbolAddress((void**)&tok_s, g_tok_s);
    cudaGetSymbolAddress((void**)&Mc, g_Mc);
    cudaGetSymbolAddress((void**)&Ms, g_Ms);
    cudaGetSymbolAddress((void**)&whc_hi, g_whc_hi);
    cudaGetSymbolAddress((void**)&whc_lo, g_whc_lo);
    cudaGetSymbolAddress((void**)&whs_hi, g_whs_hi);
    cudaGetSymbolAddress((void**)&whs_lo, g_whs_lo);

    cudaFuncSetAttribute(gemm_mma, cudaFuncAttributeMaxDynamicSharedMemorySize,
                         GEMM_SMEM);
    cudaFuncSetAttribute(gru_persist,
                         cudaFuncAttributeMaxDynamicSharedMemorySize, GRUP_SMEM);

    // 0) prep + Whh bf16 splits
    prep_kernel<<<1, 256>>>(subseqLen, in_cate, seqLen, in_batch);
    split_kernel<<<192, 256>>>(Whh_c, whc_hi, whc_lo, H3_ * H_);
    split_kernel<<<192, 256>>>(Whh_s, whs_hi, whs_lo, H3_ * H_);

    // 1) input-gate GEMMs over compacted tokens (split-on-stage HMMA)
    gemm_mma<<<dim3((BC_ * TC_ + 127) / 128, H3_ / 128), 256, GEMM_SMEM>>>(
        emb, tok_c, Mc, Wih_c, bih_c, gi_c, BC_ * TC_, H3_);
    gemm_mma<<<dim3((B_ * TS_ + 127) / 128, H3_ / 128), 256, GEMM_SMEM>>>(
        emb, tok_s, Ms, Wih_s, bih_s, gi_s, B_ * TS_, H3_);

    // 2+3) persistent HMMA GRU: ONE launch, per-group barriers
    gru_persist<<<NBLK, 256, GRUP_SMEM>>>(
        whc_hi, whc_lo, bhh_c, gi_c, mask_cate, seqc, subseqLen,
        whs_hi, whs_lo, bhh_s, gi_s, mask_b, osht, seqLen);

    // 4) attention + 5) FC
    attention_kernel<<<B_, 256>>>(seqc, osht, mask_cate_seq, sumc);
    fc_kernel<<<B_ / 16, 256>>>(sumc, osht, fc_W, fc_b, fco);

    // 6) logits = fc_out @ emb^T (split-on-stage HMMA)
    gemm_mma<<<dim3(B_ / 128, (V_ + 127) / 128), 256, GEMM_SMEM>>>(
        fco, nullptr, nullptr, emb, nullptr, out, B_, V_);

    // 7) targets appended as float, if the output carries them
    if (out_size >= B_ * V_ + B_)
        write_targets<<<1, B_>>>(target, out + (size_t)B_ * V_);
}

// round 14
// speedup vs baseline: 5.6261x; 1.0662x over previous
#include <cuda_runtime.h>
#include <cuda_bf16.h>
#include <math.h>
#include <stdint.h>

// Problem constants (fixed by setup_inputs)
#define V_  100000
#define E_  256
#define H_  256
#define B_  256
#define S_  10
#define TC_ 20
#define TS_ 50
#define BC_ (B_ * S_)   // 2560
#define H3_ (3 * H_)    // 768

// ---------------- scratch (static device globals; no allocation) --------------
__device__ float g_gi_c[(size_t)BC_ * TC_ * H3_];
__device__ float g_gi_s[(size_t)B_ * TS_ * H3_];
__device__ float g_hA[BC_ * H_];
__device__ float g_hB[BC_ * H_];
__device__ float g_hsA[B_ * H_];
__device__ float g_hsB[B_ * H_];
__device__ float g_seq_cate[BC_ * H_];
__device__ float g_out_short[B_ * H_];
__device__ float g_sum_cate[B_ * H_];
__device__ float g_fc_out[B_ * H_];
__device__ int   g_order_c[BC_];
__device__ int   g_order_s[B_];
__device__ int   g_off_c[BC_ + 1];
__device__ int   g_off_s[B_ + 1];
__device__ int   g_tok_c[BC_ * TC_];
__device__ int   g_tok_s[B_ * TS_];
__device__ int   g_cnt_c[TS_ + 1];
__device__ int   g_cnt_s[TS_ + 1];
__device__ int   g_Mc[1];
__device__ int   g_Ms[1];
// pre-split Whh
__device__ __nv_bfloat16 g_whc_hi[H3_ * H_];
__device__ __nv_bfloat16 g_whc_lo[H3_ * H_];
__device__ __nv_bfloat16 g_whs_hi[H3_ * H_];
__device__ __nv_bfloat16 g_whs_lo[H3_ * H_];
// per-group barrier state (18 groups of 8 blocks), monotonic counters
#define NGRP 18
__device__ unsigned g_bar_cnt[NGRP];

// ---------------- helpers ------------------------------------------------------
__device__ __forceinline__ float fast_sigmoid(float x) {
    return 1.f / (1.f + __expf(-x));
}
__device__ __forceinline__ float fast_tanh(float x) {
    float ax = fabsf(x);
    float e = __expf(-2.f * ax);
    float t = __fdividef(1.f - e, 1.f + e);
    return copysignf(t, x);
}
__device__ __forceinline__ uint32_t smem_u32(const void* p) {
    uint32_t a;
    asm("{ .reg .u64 t; cvta.to.shared.u64 t, %1; cvt.u32.u64 %0, t; }"
        : "=r"(a) : "l"(p));
    return a;
}
__device__ __forceinline__ void ldsm4(uint32_t& r0, uint32_t& r1, uint32_t& r2,
                                      uint32_t& r3, uint32_t addr) {
    asm volatile("ldmatrix.sync.aligned.m8n8.x4.shared.b16 {%0,%1,%2,%3}, [%4];"
                 : "=r"(r0), "=r"(r1), "=r"(r2), "=r"(r3) : "r"(addr));
}
__device__ __forceinline__ void mma16816(float* d, const uint32_t* a,
                                         uint32_t b0, uint32_t b1) {
    asm volatile(
        "mma.sync.aligned.m16n8k16.row.col.f32.bf16.bf16.f32 "
        "{%0,%1,%2,%3}, {%4,%5,%6,%7}, {%8,%9}, {%0,%1,%2,%3};"
        : "+f"(d[0]), "+f"(d[1]), "+f"(d[2]), "+f"(d[3])
        : "r"(a[0]), "r"(a[1]), "r"(a[2]), "r"(a[3]), "r"(b0), "r"(b1));
}
__device__ __forceinline__ void split_store8(float4 a0, float4 a1,
                                             __nv_bfloat16* hi,
                                             __nv_bfloat16* lo) {
    float f[8] = {a0.x, a0.y, a0.z, a0.w, a1.x, a1.y, a1.z, a1.w};
    __nv_bfloat16 h[8], l[8];
#pragma unroll
    for (int e = 0; e < 8; e++) h[e] = __float2bfloat16(f[e]);
#pragma unroll
    for (int e = 0; e < 8; e++)
        l[e] = __float2bfloat16(f[e] - __bfloat162float(h[e]));
    __nv_bfloat162 hp[4] = {{h[0], h[1]}, {h[2], h[3]}, {h[4], h[5]}, {h[6], h[7]}};
    __nv_bfloat162 lp[4] = {{l[0], l[1]}, {l[2], l[3]}, {l[4], l[5]}, {l[6], l[7]}};
    *(uint4*)hi = *(uint4*)hp;
    *(uint4*)lo = *(uint4*)lp;
}
// monotonic-counter group barrier: step t has target nb*(t+1).
// VOLATILE poll — a non-volatile __ldcg empty loop is side-effect-free and the
// compiler may delete it (R13 failure root cause).
__device__ __forceinline__ void group_barrier(int gid, unsigned tgt) {
    __threadfence();
    __syncthreads();
    if (threadIdx.x == 0) {
        atomicAdd(&g_bar_cnt[gid], 1u);
        volatile unsigned* p = &g_bar_cnt[gid];
        while (*p < tgt) { }
        __threadfence();
    }
    __syncthreads();
}

// ---------------- fp32 -> bf16 hi/lo split (Whh only) -------------------------
__global__ void split_kernel(const float* __restrict__ src,
                             __nv_bfloat16* __restrict__ hi,
                             __nv_bfloat16* __restrict__ lo, int n)
{
    int i = (blockIdx.x * 256 + threadIdx.x) * 4;
    const int stride = gridDim.x * 256 * 4;
    for (; i < n; i += stride) {
        float4 v = *(const float4*)(src + i);
        __nv_bfloat16 h0 = __float2bfloat16(v.x);
        __nv_bfloat16 h1 = __float2bfloat16(v.y);
        __nv_bfloat16 h2 = __float2bfloat16(v.z);
        __nv_bfloat16 h3 = __float2bfloat16(v.w);
        __nv_bfloat16 l0 = __float2bfloat16(v.x - __bfloat162float(h0));
        __nv_bfloat16 l1 = __float2bfloat16(v.y - __bfloat162float(h1));
        __nv_bfloat16 l2 = __float2bfloat16(v.z - __bfloat162float(h2));
        __nv_bfloat16 l3 = __float2bfloat16(v.w - __bfloat162float(h3));
        ((__nv_bfloat162*)(hi + i))[0] = __nv_bfloat162(h0, h1);
        ((__nv_bfloat162*)(hi + i))[1] = __nv_bfloat162(h2, h3);
        ((__nv_bfloat162*)(lo + i))[0] = __nv_bfloat162(l0, l1);
        ((__nv_bfloat162*)(lo + i))[1] = __nv_bfloat162(l2, l3);
    }
}

// ---------------- prep: counting sort desc, prefix offsets, token compaction --
__global__ void prep_kernel(const int* __restrict__ slen_c, const int* __restrict__ tokens_c,
                            const int* __restrict__ slen_s, const int* __restrict__ tokens_s)
{
    __shared__ int hist[64];
    __shared__ int base[64];
    __shared__ int ssum[256];
    const int tid = threadIdx.x;

    if (tid < NGRP) { g_bar_cnt[tid] = 0u; }   // barrier reset (graph-replay safe)

    if (tid < 64) hist[tid] = 0;
    __syncthreads();
    for (int i = tid; i < BC_; i += 256) atomicAdd(&hist[slen_c[i]], 1);
    __syncthreads();
    if (tid <= TS_) {
        int c = 0;
        if (tid < 64) for (int k = tid; k < 64; k++) c += hist[k];
        g_cnt_c[tid] = (tid < TC_) ? c : 0;
    }
    if (tid == 0) {
        int run = 0;
        for (int k = 63; k >= 0; k--) { base[k] = run; run += hist[k]; }
    }
    __syncthreads();
    for (int i = tid; i < BC_; i += 256) {
        int pos = atomicAdd(&base[slen_c[i]], 1);
        g_order_c[pos] = i;
    }
    {
        const int chunk = BC_ / 256;
        int s = 0;
        for (int i = 0; i < chunk; i++) s += slen_c[tid * chunk + i] + 1;
        ssum[tid] = s;
        __syncthreads();
        for (int d = 1; d < 256; d <<= 1) {
            int v = (tid >= d) ? ssum[tid - d] : 0;
            __syncthreads();
            ssum[tid] += v;
            __syncthreads();
        }
        int run = (tid > 0) ? ssum[tid - 1] : 0;
        for (int i = 0; i < chunk; i++) {
            int b = tid * chunk + i;
            g_off_c[b] = run;
            run += slen_c[b] + 1;
        }
        if (tid == 255) { g_off_c[BC_] = ssum[255]; g_Mc[0] = ssum[255]; }
    }
    __syncthreads();
    for (int i = tid; i < BC_ * TC_; i += 256) {
        int b = i / TC_, t = i % TC_;
        if (t <= slen_c[b]) g_tok_c[g_off_c[b] + t] = tokens_c[i];
    }
    __syncthreads();

    if (tid < 64) hist[tid] = 0;
    __syncthreads();
    for (int i = tid; i < B_; i += 256) atomicAdd(&hist[slen_s[i]], 1);
    __syncthreads();
    if (tid <= TS_) {
        int c = 0;
        if (tid < 64) for (int k = tid; k < 64; k++) c += hist[k];
        g_cnt_s[tid] = (tid < TS_) ? c : 0;
    }
    if (tid == 0) {
        int run = 0;
        for (int k = 63; k >= 0; k--) { base[k] = run; run += hist[k]; }
    }
    __syncthreads();
    for (int i = tid; i < B_; i += 256) {
        int pos = atomicAdd(&base[slen_s[i]], 1);
        g_order_s[pos] = i;
    }
    {
        int s = (tid < B_) ? slen_s[tid] + 1 : 0;
        ssum[tid] = s;
        __syncthreads();
        for (int d = 1; d < 256; d <<= 1) {
            int v = (tid >= d) ? ssum[tid - d] : 0;
            __syncthreads();
            ssum[tid] += v;
            __syncthreads();
        }
        if (tid < B_) g_off_s[tid] = ssum[tid] - (slen_s[tid] + 1);
        if (tid == 255) { g_off_s[B_] = ssum[255]; g_Ms[0] = ssum[255]; }
    }
    __syncthreads();
    for (int i = tid; i < B_ * TS_; i += 256) {
        int b = i / TS_, t = i % TS_;
        if (t <= slen_s[b]) g_tok_s[g_off_s[b] + t] = tokens_s[i];
    }
}

// ---------------- bf16-split HMMA GEMM, fp32 in, split-on-stage ---------------
#define STRIDE_ 72
#define GTILE_  (128 * STRIDE_)
#define GEMM_SMEM (4 * GTILE_ * 2)

__global__ void __launch_bounds__(256, 2) gemm_mma(
    const float* __restrict__ A, const int* __restrict__ idx,
    const int* __restrict__ Mdev,
    const float* __restrict__ B, const float* __restrict__ bias,
    float* __restrict__ C, int M, int N)
{
    extern __shared__ __align__(16) __nv_bfloat16 smem[];
    const int Mq = Mdev ? *Mdev : M;
    const int bm = blockIdx.x * 128, bn = blockIdx.y * 128;
    if (bm >= Mq) return;
    const int tid = threadIdx.x, wid = tid >> 5, lane = tid & 31;
    const int warp_m = wid & 1, warp_n = wid >> 1;

    __nv_bfloat16* sAh = smem;
    __nv_bfloat16* sAl = smem + GTILE_;
    __nv_bfloat16* sBh = smem + 2 * GTILE_;
    __nv_bfloat16* sBl = smem + 3 * GTILE_;
    const uint32_t uAh = smem_u32(sAh), uAl = smem_u32(sAl);
    const uint32_t uBh = smem_u32(sBh), uBl = smem_u32(sBl);

    const int fr = lane & 15;
    const int fc = (lane >> 4) * 8;
    const int arow_f = warp_m * 64 + fr;
    const int brow_f = warp_n * 32 + fr;

    float acc[4][4][4];
#pragma unroll
    for (int i = 0; i < 4; i++)
#pragma unroll
        for (int j = 0; j < 4; j++)
#pragma unroll
            for (int e = 0; e < 4; e++) acc[i][j][e] = 0.f;

    for (int kt = 0; kt < 4; kt++) {
        if (kt) __syncthreads();
#pragma unroll
        for (int i = 0; i < 4; i++) {
            const int id = i * 256 + tid;
            const int row = id >> 3, ch = id & 7;
            const int col = kt * 64 + ch * 8;
            int am = bm + row; if (am > Mq - 1) am = Mq - 1;
            const int ar = idx ? idx[am] : am;
            int br = bn + row; if (br > N - 1) br = N - 1;
            const int so = row * STRIDE_ + ch * 8;
            const float* ap = A + (size_t)ar * 256 + col;
            const float* bp = B + (size_t)br * 256 + col;
            split_store8(*(const float4*)ap, *(const float4*)(ap + 4),
                         sAh + so, sAl + so);
            split_store8(*(const float4*)bp, *(const float4*)(bp + 4),
                         sBh + so, sBl + so);
        }
        __syncthreads();

#pragma unroll
        for (int kk = 0; kk < 4; kk++) {
            const int col = kk * 16 + fc;
            uint32_t bh[2][4], bl[2][4], av[4][4];
#pragma unroll
            for (int p = 0; p < 2; p++) {
                const uint32_t off = 2u * ((brow_f + p * 16) * STRIDE_ + col);
                ldsm4(bh[p][0], bh[p][1], bh[p][2], bh[p][3], uBh + off);
                ldsm4(bl[p][0], bl[p][1], bl[p][2], bl[p][3], uBl + off);
            }
#pragma unroll
            for (int tm = 0; tm < 4; tm++) {
                const uint32_t off = 2u * ((arow_f + tm * 16) * STRIDE_ + col);
                ldsm4(av[tm][0], av[tm][1], av[tm][2], av[tm][3], uAh + off);
            }
#pragma unroll
            for (int tm = 0; tm < 4; tm++)
#pragma unroll
                for (int tn = 0; tn < 4; tn++) {
                    const int p = tn >> 1, o = tn & 1;
                    mma16816(acc[tm][tn], av[tm], bh[p][o], bh[p][o + 2]);
                    mma16816(acc[tm][tn], av[tm], bl[p][o], bl[p][o + 2]);
                }
#pragma unroll
            for (int tm = 0; tm < 4; tm++) {
                const uint32_t off = 2u * ((arow_f + tm * 16) * STRIDE_ + col);
                ldsm4(av[tm][0], av[tm][1], av[tm][2], av[tm][3], uAl + off);
            }
#pragma unroll
            for (int tm = 0; tm < 4; tm++)
#pragma unroll
                for (int tn = 0; tn < 4; tn++) {
                    const int p = tn >> 1, o = tn & 1;
                    mma16816(acc[tm][tn], av[tm], bh[p][o], bh[p][o + 2]);
                }
        }
    }

    const int mrow = bm + warp_m * 64 + (lane >> 2);
    const int ncol = bn + warp_n * 32 + (lane & 3) * 2;
#pragma unroll
    for (int tm = 0; tm < 4; tm++) {
#pragma unroll
        for (int half = 0; half < 2; half++) {
            const int m = mrow + tm * 16 + half * 8;
            if (m >= Mq) continue;
            float* crow = C + (size_t)m * N;
#pragma unroll
            for (int tn = 0; tn < 4; tn++) {
                const int n0 = ncol + tn * 8;
                const float v0 = acc[tm][tn][half * 2 + 0]
                               + (bias ? bias[n0] : 0.f);
                if (n0 + 1 < N) {
                    const float v1 = acc[tm][tn][half * 2 + 1]
                                   + (bias ? bias[n0 + 1] : 0.f);
                    *(float2*)(crow + n0) = make_float2(v0, v1);
                } else if (n0 < N) {
                    crow[n0] = v0;
                }
            }
        }
    }
}

// ---------------- persistent HMMA GRU (per-group barriers, smem gi/hold) ------
// 144 blocks: 112 cat (14 rowset groups x 8 j-slices) + 32 short (4 groups x 8).
// gi + hold staged into smem during the staging phase (overlaps MMA-independent
// DRAM latency with compute); epilogue is pure smem + math.
#define NBLK 144
#define CAT_RS 14
#define SHT_RS 4
#define WKT 6912              // 96*72 elems per kt
#define AKT 4608              // 64*72 elems per kt
#define HOLD_STR 36
#define GRUP_SMEM (184320 + 64 * 96 * 4 + 64 * HOLD_STR * 4)   // 218112 bytes

__global__ void __launch_bounds__(256, 1) gru_persist(
    const __nv_bfloat16* __restrict__ Whi_c, const __nv_bfloat16* __restrict__ Wlo_c,
    const float* __restrict__ bhh_c, const float* __restrict__ gi_c,
    const float* __restrict__ mask_c, float* __restrict__ gath_c,
    const int* __restrict__ slen_c,
    const __nv_bfloat16* __restrict__ Whi_s, const __nv_bfloat16* __restrict__ Wlo_s,
    const float* __restrict__ bhh_s, const float* __restrict__ gi_s,
    const float* __restrict__ mask_s, float* __restrict__ gath_s,
    const int* __restrict__ slen_s)
{
    extern __shared__ __align__(16) __nv_bfloat16 psm[];
    __nv_bfloat16* sWh = psm;                 // [4][96][72]
    __nv_bfloat16* sWl = psm + 4 * WKT;
    __nv_bfloat16* sAh = psm + 8 * WKT;       // [4][64][72]
    __nv_bfloat16* sAl = psm + 8 * WKT + 4 * AKT;
    float* sGi = (float*)(psm + 8 * WKT + 8 * AKT);   // [64][96]
    float* sHold = sGi + 64 * 96;                     // [64][36]
    const uint32_t uWh = smem_u32(sWh), uWl = smem_u32(sWl);
    const uint32_t uAh = smem_u32(sAh), uAl = smem_u32(sAl);

    const int blk = blockIdx.x;
    const int tid = threadIdx.x, wid = tid >> 5, lane = tid & 31;
    const int warp_m = wid & 3, warp_n = wid >> 2;   // 4m x 2n
    const int fr = lane & 15;
    const int fc = (lane >> 4) * 8;

    const bool isCat = blk < 112;
    const int local = isCat ? blk : (blk - 112);
    const int jsl = local & 7;            // 8 j-slices of 32
    const int rowset = local >> 3;        // cat 0..13, short 0..3
    const int rstride = isCat ? CAT_RS : SHT_RS;
    const int maxchunk = isCat ? 40 : 4;
    const int tmax = isCat ? TC_ : TS_;
    const int gid = isCat ? rowset : (CAT_RS + rowset);
    const int j0 = jsl * 32;

    const __nv_bfloat16* Whi = isCat ? Whi_c : Whi_s;
    const __nv_bfloat16* Wlo = isCat ? Wlo_c : Wlo_s;
    const float* bhh = isCat ? bhh_c : bhh_s;
    const float* gi = isCat ? gi_c : gi_s;
    const float* mask = isCat ? mask_c : mask_s;
    float* gath = isCat ? gath_c : gath_s;
    const int* slen = isCat ? slen_c : slen_s;
    const int* order = isCat ? g_order_c : g_order_s;
    const int* off = isCat ? g_off_c : g_off_s;
    const int* cnt = isCat ? g_cnt_c : g_cnt_s;
    const int maskT = isCat ? TC_ : TS_;
    float* hbufA = isCat ? g_hA : g_hsA;
    float* hbufB = isCat ? g_hB : g_hsB;

    // stage Whh slice ONCE: rows r = g*32 + j (96), all 4 kt chunks
#pragma unroll
    for (int i = 0; i < 12; i++) {
        const int id = i * 256 + tid;       // 0..3071
        const int ch = id & 7;
        const int kt = (id >> 3) & 3;
        const int r = id >> 5;              // 0..95
        const int grow = (r >> 5) * 256 + j0 + (r & 31);
        const int col = kt * 64 + ch * 8;
        const int so = kt * WKT + r * STRIDE_ + ch * 8;
        *(uint4*)(sWh + so) = *(const uint4*)(Whi + (size_t)grow * 256 + col);
        *(uint4*)(sWl + so) = *(const uint4*)(Wlo + (size_t)grow * 256 + col);
    }
    __syncthreads();

    for (int t = 0; t < tmax; t++) {
        const int active = cnt[t];
        const float* h_in = (t & 1) ? hbufB : hbufA;
        float* h_out = (t & 1) ? hbufA : hbufB;

        for (int c = rowset; c < maxchunk && c * 64 < active; c += rstride) {
            const int bm = c * 64;
            __syncthreads();   // protect smem from previous chunk's readers
            float acc[6][4];
#pragma unroll
            for (int j = 0; j < 6; j++)
#pragma unroll
                for (int e = 0; e < 4; e++) acc[j][e] = 0.f;

            // stage gi chunk into smem (always; h-independent, deep MLP)
#pragma unroll
            for (int i = 0; i < 24; i++) {
                const int id = i * 256 + tid;      // 0..6143
                const int sl = id / 96;
                const int q = id - sl * 96;        // 0..95: g*32 + jo
                const int g = q >> 5, jo = q & 31;
                int gs = bm + sl; if (gs > active - 1) gs = active - 1;
                const int b = order[gs];
                sGi[sl * 96 + q] =
                    __ldcg(gi + ((size_t)(off[b] + t)) * H3_ + g * 256 + j0 + jo);
            }

            if (t > 0) {
                // stage A: 64 rows x 256 k, fp32 -> bf16 hi/lo (+hold capture)
#pragma unroll
                for (int i = 0; i < 16; i++) {
                    const int id = i * 256 + tid;   // 0..4095
                    const int sl = id >> 6;          // 0..63
                    const int q = id & 63;
                    const int kt = q >> 4, c4 = q & 15;
                    int gs = bm + sl; if (gs > active - 1) gs = active - 1;
                    const int row = order[gs];
                    float4 v = __ldcg((const float4*)(h_in + (size_t)row * 256 + kt * 64 + c4 * 4));
                    const int k = kt * 64 + c4 * 4;
                    const int hk = k - j0;
                    if (hk >= 0 && hk < 32)
                        *(float4*)(sHold + sl * HOLD_STR + hk) = v;
                    __nv_bfloat16 h0 = __float2bfloat16(v.x);
                    __nv_bfloat16 h1 = __float2bfloat16(v.y);
                    __nv_bfloat16 h2 = __float2bfloat16(v.z);
                    __nv_bfloat16 h3 = __float2bfloat16(v.w);
                    const int so = kt * AKT + sl * STRIDE_ + c4 * 4;
                    *(__nv_bfloat162*)(sAh + so)     = __nv_bfloat162(h0, h1);
                    *(__nv_bfloat162*)(sAh + so + 2) = __nv_bfloat162(h2, h3);
                    *(__nv_bfloat162*)(sAl + so) =
                        __nv_bfloat162(__float2bfloat16(v.x - __bfloat162float(h0)),
                                       __float2bfloat16(v.y - __bfloat162float(h1)));
                    *(__nv_bfloat162*)(sAl + so + 2) =
                        __nv_bfloat162(__float2bfloat16(v.z - __bfloat162float(h2)),
                                       __float2bfloat16(v.w - __bfloat162float(h3)));
                }
            }
            __syncthreads();

            if (t > 0) {
#pragma unroll
                for (int kt = 0; kt < 4; kt++) {
#pragma unroll
                    for (int kk = 0; kk < 4; kk++) {
                        const int col = kk * 16 + fc;
                        uint32_t bh[3][4], bl[3][4], avh[4], avl[4];
#pragma unroll
                        for (int g = 0; g < 3; g++) {
                            const uint32_t o = 2u * (kt * WKT +
                                (g * 32 + warp_n * 16 + fr) * STRIDE_ + col);
                            ldsm4(bh[g][0], bh[g][1], bh[g][2], bh[g][3], uWh + o);
                            ldsm4(bl[g][0], bl[g][1], bl[g][2], bl[g][3], uWl + o);
                        }
                        {
                            const uint32_t o = 2u * (kt * AKT +
                                (warp_m * 16 + fr) * STRIDE_ + col);
                            ldsm4(avh[0], avh[1], avh[2], avh[3], uAh + o);
                            ldsm4(avl[0], avl[1], avl[2], avl[3], uAl + o);
                        }
#pragma unroll
                        for (int g = 0; g < 3; g++)
#pragma unroll
                            for (int o = 0; o < 2; o++) {
                                mma16816(acc[g * 2 + o], avh, bh[g][o], bh[g][o + 2]);
                                mma16816(acc[g * 2 + o], avh, bl[g][o], bl[g][o + 2]);
                                mma16816(acc[g * 2 + o], avl, bh[g][o], bh[g][o + 2]);
                            }
                    }
                }
            }

            // register/smem epilogue (no global reads)
#pragma unroll
            for (int o = 0; o < 2; o++)
#pragma unroll
                for (int e = 0; e < 4; e++) {
                    const int m_local = warp_m * 16 + (lane >> 2) + 8 * (e >> 1);
                    const int slot = bm + m_local;
                    if (slot >= active) continue;
                    const int b = order[slot];
                    const int j = warp_n * 16 + o * 8 + (lane & 3) * 2 + (e & 1);
                    const int jj = j0 + j;
                    const float gr = sGi[m_local * 96 + j];
                    const float gz = sGi[m_local * 96 + 32 + j];
                    const float gn = sGi[m_local * 96 + 64 + j];
                    const float hold = (t > 0) ? sHold[m_local * HOLD_STR + j] : 0.f;
                    const float r = fast_sigmoid(gr + acc[0 + o][e] + bhh[jj]);
                    const float z = fast_sigmoid(gz + acc[2 + o][e] + bhh[H_ + jj]);
                    const float n = fast_tanh(gn + r * (acc[4 + o][e] + bhh[2 * H_ + jj]));
                    const float hnew = (1.f - z) * n + z * hold;
                    h_out[(size_t)b * H_ + jj] = hnew;
                    if (slen[b] == t)
                        gath[(size_t)b * H_ + jj] =
                            hnew * mask[(size_t)b * maskT + t];
                }
        }

        if (t + 1 < tmax) group_barrier(gid, 8u * (unsigned)(t + 1));
    }
}

// ---------------- attention ----------------------------------------------------
__global__ void attention_kernel(const float* __restrict__ seq_cate,
                                 const float* __restrict__ out_short,
                                 const float* __restrict__ mask_seq,
                                 float* __restrict__ sum_cate)
{
    const int b = blockIdx.x;
    const int j = threadIdx.x;
    __shared__ float red[8];
    __shared__ float w[S_];
    const float os = out_short[(size_t)b * H_ + j];
    float sc[S_];
#pragma unroll
    for (int s = 0; s < S_; s++)
        sc[s] = seq_cate[(size_t)(b * S_ + s) * H_ + j];

    for (int s = 0; s < S_; s++) {
        float v = sc[s] * os;
#pragma unroll
        for (int off = 16; off; off >>= 1) v += __shfl_xor_sync(0xffffffffu, v, off);
        if ((j & 31) == 0) red[j >> 5] = v;
        __syncthreads();
        if (j == 0) {
            float x = 0.f;
#pragma unroll
            for (int q = 0; q < 8; q++) x += red[q];
            w[s] = x;
        }
        __syncthreads();
    }
    if (j == 0) {
        float mx = w[0];
        for (int s = 1; s < S_; s++) mx = fmaxf(mx, w[s]);
        float e[S_];
        float sum = 0.f;
        for (int s = 0; s < S_; s++) { e[s] = expf(w[s] - mx); sum += e[s]; }
        float s2 = 0.f;
        for (int s = 0; s < S_; s++) {
            e[s] = (e[s] / sum) * mask_seq[(size_t)b * S_ + s];
            s2 += e[s];
        }
        for (int s = 0; s < S_; s++) w[s] = e[s] / s2;
    }
    __syncthreads();
    float acc = 0.f;
#pragma unroll
    for (int s = 0; s < S_; s++) acc += w[s] * sc[s];
    sum_cate[(size_t)b * H_ + j] = acc;
}

// ---------------- FC -----------------------------------------------------------
__global__ void fc_kernel(const float* __restrict__ sum_cate,
                          const float* __restrict__ out_short,
                          const float* __restrict__ fcW,
                          const float* __restrict__ fcb,
                          float* __restrict__ fc_out)
{
    __shared__ float mix[16][2 * H_];
    const int b0 = blockIdx.x * 16;
    for (int idx = threadIdx.x; idx < 16 * 2 * H_; idx += 256) {
        const int bb = idx >> 9, k = idx & 511;
        mix[bb][k] = (k < H_) ? sum_cate[(size_t)(b0 + bb) * H_ + k]
                              : out_short[(size_t)(b0 + bb) * H_ + (k - H_)];
    }
    __syncthreads();
    const int i = threadIdx.x;
    const float* wrow = fcW + (size_t)i * (2 * H_);
    float acc[16];
#pragma unroll
    for (int bb = 0; bb < 16; bb++) acc[bb] = 0.f;
    for (int k = 0; k < 2 * H_; k++) {
        const float wv = wrow[k];
#pragma unroll
        for (int bb = 0; bb < 16; bb++) acc[bb] += wv * mix[bb][k];
    }
    const float bias = fcb[i];
#pragma unroll
    for (int bb = 0; bb < 16; bb++)
        fc_out[(size_t)(b0 + bb) * H_ + i] = acc[bb] + bias;
}

__global__ void write_targets(const int* __restrict__ tgt, float* __restrict__ out)
{
    out[threadIdx.x] = (float)tgt[threadIdx.x];
}

// ---------------- launcher ----------------------------------------------------
extern "C" void kernel_launch(void* const* d_in, const int* in_sizes, int n_in,
                              void* d_out, int out_size)
{
    const int*   in_cate       = (const int*)d_in[0];
    const float* mask_cate     = (const float*)d_in[1];
    const float* mask_cate_seq = (const float*)d_in[2];
    const int*   subseqLen     = (const int*)d_in[5];
    const int*   in_batch      = (const int*)d_in[7];
    const float* mask_b        = (const float*)d_in[8];
    const int*   seqLen        = (const int*)d_in[9];
    const int*   target        = (const int*)d_in[10];
    const float* emb           = (const float*)d_in[12];
    const float* Wih_c         = (const float*)d_in[13];
    const float* Whh_c         = (const float*)d_in[14];
    const float* bih_c         = (const float*)d_in[15];
    const float* bhh_c         = (const float*)d_in[16];
    const float* Wih_s         = (const float*)d_in[17];
    const float* Whh_s         = (const float*)d_in[18];
    const float* bih_s         = (const float*)d_in[19];
    const float* bhh_s         = (const float*)d_in[20];
    const float* fc_W          = (const float*)d_in[21];
    const float* fc_b          = (const float*)d_in[22];
    float* out = (float*)d_out;

    float *gi_c, *gi_s, *seqc, *osht, *sumc, *fco;
    int *tok_c, *tok_s, *Mc, *Ms;
    __nv_bfloat16 *whc_hi, *whc_lo, *whs_hi, *whs_lo;
    cudaGetSymbolAddress((void**)&gi_c, g_gi_c);
    cudaGetSymbolAddress((void**)&gi_s, g_gi_s);
    cudaGetSymbolAddress((void**)&seqc, g_seq_cate);
    cudaGetSymbolAddress((void**)&osht, g_out_short);
    cudaGetSymbolAddress((void**)&sumc, g_sum_cate);
    cudaGetSymbolAddress((void**)&fco,  g_fc_out);
    cudaGetSymbolAddress((void**)&tok_c, g_tok_c);
    cudaGetSymbolAddress((void**)&tok_s, g_tok_s);
    cudaGetSymbolAddress((void**)&Mc, g_Mc);
    cudaGetSymbolAddress((void**)&Ms, g_Ms);
    cudaGetSymbolAddress((void**)&whc_hi, g_whc_hi);
    cudaGetSymbolAddress((void**)&whc_lo, g_whc_lo);
    cudaGetSymbolAddress((void**)&whs_hi, g_whs_hi);
    cudaGetSymbolAddress((void**)&whs_lo, g_whs_lo);

    cudaFuncSetAttribute(gemm_mma, cudaFuncAttributeMaxDynamicSharedMemorySize,
                         GEMM_SMEM);
    cudaFuncSetAttribute(gru_persist,
                         cudaFuncAttributeMaxDynamicSharedMemorySize, GRUP_SMEM);

    // 0) prep + Whh bf16 splits
    prep_kernel<<<1, 256>>>(subseqLen, in_cate, seqLen, in_batch);
    split_kernel<<<192, 256>>>(Whh_c, whc_hi, whc_lo, H3_ * H_);
    split_kernel<<<192, 256>>>(Whh_s, whs_hi, whs_lo, H3_ * H_);

    // 1) input-gate GEMMs over compacted tokens (split-on-stage HMMA)
    gemm_mma<<<dim3((BC_ * TC_ + 127) / 128, H3_ / 128), 256, GEMM_SMEM>>>(
        emb, tok_c, Mc, Wih_c, bih_c, gi_c, BC_ * TC_, H3_);
    gemm_mma<<<dim3((B_ * TS_ + 127) / 128, H3_ / 128), 256, GEMM_SMEM>>>(
        emb, tok_s, Ms, Wih_s, bih_s, gi_s, B_ * TS_, H3_);

    // 2+3) persistent HMMA GRU: ONE launch, per-group barriers
    gru_persist<<<NBLK, 256, GRUP_SMEM>>>(
        whc_hi, whc_lo, bhh_c, gi_c, mask_cate, seqc, subseqLen,
        whs_hi, whs_lo, bhh_s, gi_s, mask_b, osht, seqLen);

    // 4) attention + 5) FC
    attention_kernel<<<B_, 256>>>(seqc, osht, mask_cate_seq, sumc);
    fc_kernel<<<B_ / 16, 256>>>(sumc, osht, fc_W, fc_b, fco);

    // 6) logits = fc_out @ emb^T (split-on-stage HMMA)
    gemm_mma<<<dim3(B_ / 128, (V_ + 127) / 128), 256, GEMM_SMEM>>>(
        fco, nullptr, nullptr, emb, nullptr, out, B_, V_);

    // 7) targets appended as float, if the output carries them
    if (out_size >= B_ * V_ + B_)
        write_targets<<<1, B_>>>(target, out + (size_t)B_ * V_);
}

// round 15
// speedup vs baseline: 5.6423x; 1.0029x over previous
#include <cuda_runtime.h>
#include <cuda_bf16.h>
#include <math.h>
#include <stdint.h>

// Problem constants (fixed by setup_inputs)
#define V_  100000
#define E_  256
#define H_  256
#define B_  256
#define S_  10
#define TC_ 20
#define TS_ 50
#define BC_ (B_ * S_)   // 2560
#define H3_ (3 * H_)    // 768

// ---------------- scratch (static device globals; no allocation) --------------
__device__ float g_gi_c[(size_t)BC_ * TC_ * H3_];
__device__ float g_gi_s[(size_t)B_ * TS_ * H3_];
__device__ float g_hA[BC_ * H_];
__device__ float g_hB[BC_ * H_];
__device__ float g_hsA[B_ * H_];
__device__ float g_hsB[B_ * H_];
__device__ float g_seq_cate[BC_ * H_];
__device__ float g_out_short[B_ * H_];
__device__ float g_sum_cate[B_ * H_];
__device__ float g_fc_out[B_ * H_];
__device__ int   g_order_c[BC_];
__device__ int   g_order_s[B_];
__device__ int   g_off_c[BC_ + 1];
__device__ int   g_off_s[B_ + 1];
__device__ int   g_tok_c[BC_ * TC_];
__device__ int   g_tok_s[B_ * TS_];
__device__ int   g_cnt_c[TS_ + 1];
__device__ int   g_cnt_s[TS_ + 1];
__device__ int   g_Mc[1];
__device__ int   g_Ms[1];
// pre-split Whh
__device__ __nv_bfloat16 g_whc_hi[H3_ * H_];
__device__ __nv_bfloat16 g_whc_lo[H3_ * H_];
__device__ __nv_bfloat16 g_whs_hi[H3_ * H_];
__device__ __nv_bfloat16 g_whs_lo[H3_ * H_];
// per-group barrier state (18 groups of 8 blocks), monotonic counters
#define NGRP 18
__device__ unsigned g_bar_cnt[NGRP];

// ---------------- helpers ------------------------------------------------------
__device__ __forceinline__ float fast_sigmoid(float x) {
    return 1.f / (1.f + __expf(-x));
}
__device__ __forceinline__ float fast_tanh(float x) {
    float ax = fabsf(x);
    float e = __expf(-2.f * ax);
    float t = __fdividef(1.f - e, 1.f + e);
    return copysignf(t, x);
}
__device__ __forceinline__ uint32_t smem_u32(const void* p) {
    uint32_t a;
    asm("{ .reg .u64 t; cvta.to.shared.u64 t, %1; cvt.u32.u64 %0, t; }"
        : "=r"(a) : "l"(p));
    return a;
}
__device__ __forceinline__ void ldsm4(uint32_t& r0, uint32_t& r1, uint32_t& r2,
                                      uint32_t& r3, uint32_t addr) {
    asm volatile("ldmatrix.sync.aligned.m8n8.x4.shared.b16 {%0,%1,%2,%3}, [%4];"
                 : "=r"(r0), "=r"(r1), "=r"(r2), "=r"(r3) : "r"(addr));
}
__device__ __forceinline__ void mma16816(float* d, const uint32_t* a,
                                         uint32_t b0, uint32_t b1) {
    asm volatile(
        "mma.sync.aligned.m16n8k16.row.col.f32.bf16.bf16.f32 "
        "{%0,%1,%2,%3}, {%4,%5,%6,%7}, {%8,%9}, {%0,%1,%2,%3};"
        : "+f"(d[0]), "+f"(d[1]), "+f"(d[2]), "+f"(d[3])
        : "r"(a[0]), "r"(a[1]), "r"(a[2]), "r"(a[3]), "r"(b0), "r"(b1));
}
__device__ __forceinline__ void split_store8(float4 a0, float4 a1,
                                             __nv_bfloat16* hi,
                                             __nv_bfloat16* lo) {
    float f[8] = {a0.x, a0.y, a0.z, a0.w, a1.x, a1.y, a1.z, a1.w};
    __nv_bfloat16 h[8], l[8];
#pragma unroll
    for (int e = 0; e < 8; e++) h[e] = __float2bfloat16(f[e]);
#pragma unroll
    for (int e = 0; e < 8; e++)
        l[e] = __float2bfloat16(f[e] - __bfloat162float(h[e]));
    __nv_bfloat162 hp[4] = {{h[0], h[1]}, {h[2], h[3]}, {h[4], h[5]}, {h[6], h[7]}};
    __nv_bfloat162 lp[4] = {{l[0], l[1]}, {l[2], l[3]}, {l[4], l[5]}, {l[6], l[7]}};
    *(uint4*)hi = *(uint4*)hp;
    *(uint4*)lo = *(uint4*)lp;
}
// monotonic-counter group barrier: step t has target nb*(t+1). VOLATILE poll.
__device__ __forceinline__ void group_barrier(int gid, unsigned tgt) {
    __threadfence();
    __syncthreads();
    if (threadIdx.x == 0) {
        atomicAdd(&g_bar_cnt[gid], 1u);
        volatile unsigned* p = &g_bar_cnt[gid];
        while (*p < tgt) { }
        __threadfence();
    }
    __syncthreads();
}

// ---------------- fp32 -> bf16 hi/lo split (Whh only) -------------------------
__global__ void split_kernel(const float* __restrict__ src,
                             __nv_bfloat16* __restrict__ hi,
                             __nv_bfloat16* __restrict__ lo, int n)
{
    int i = (blockIdx.x * 256 + threadIdx.x) * 4;
    const int stride = gridDim.x * 256 * 4;
    for (; i < n; i += stride) {
        float4 v = *(const float4*)(src + i);
        __nv_bfloat16 h0 = __float2bfloat16(v.x);
        __nv_bfloat16 h1 = __float2bfloat16(v.y);
        __nv_bfloat16 h2 = __float2bfloat16(v.z);
        __nv_bfloat16 h3 = __float2bfloat16(v.w);
        __nv_bfloat16 l0 = __float2bfloat16(v.x - __bfloat162float(h0));
        __nv_bfloat16 l1 = __float2bfloat16(v.y - __bfloat162float(h1));
        __nv_bfloat16 l2 = __float2bfloat16(v.z - __bfloat162float(h2));
        __nv_bfloat16 l3 = __float2bfloat16(v.w - __bfloat162float(h3));
        ((__nv_bfloat162*)(hi + i))[0] = __nv_bfloat162(h0, h1);
        ((__nv_bfloat162*)(hi + i))[1] = __nv_bfloat162(h2, h3);
        ((__nv_bfloat162*)(lo + i))[0] = __nv_bfloat162(l0, l1);
        ((__nv_bfloat162*)(lo + i))[1] = __nv_bfloat162(l2, l3);
    }
}

// ---------------- prep: counting sort desc, prefix offsets, token compaction --
__global__ void prep_kernel(const int* __restrict__ slen_c, const int* __restrict__ tokens_c,
                            const int* __restrict__ slen_s, const int* __restrict__ tokens_s)
{
    __shared__ int hist[64];
    __shared__ int base[64];
    __shared__ int ssum[256];
    const int tid = threadIdx.x;

    if (tid < NGRP) { g_bar_cnt[tid] = 0u; }   // barrier reset (graph-replay safe)

    if (tid < 64) hist[tid] = 0;
    __syncthreads();
    for (int i = tid; i < BC_; i += 256) atomicAdd(&hist[slen_c[i]], 1);
    __syncthreads();
    if (tid <= TS_) {
        int c = 0;
        if (tid < 64) for (int k = tid; k < 64; k++) c += hist[k];
        g_cnt_c[tid] = (tid < TC_) ? c : 0;
    }
    if (tid == 0) {
        int run = 0;
        for (int k = 63; k >= 0; k--) { base[k] = run; run += hist[k]; }
    }
    __syncthreads();
    for (int i = tid; i < BC_; i += 256) {
        int pos = atomicAdd(&base[slen_c[i]], 1);
        g_order_c[pos] = i;
    }
    {
        const int chunk = BC_ / 256;
        int s = 0;
        for (int i = 0; i < chunk; i++) s += slen_c[tid * chunk + i] + 1;
        ssum[tid] = s;
        __syncthreads();
        for (int d = 1; d < 256; d <<= 1) {
            int v = (tid >= d) ? ssum[tid - d] : 0;
            __syncthreads();
            ssum[tid] += v;
            __syncthreads();
        }
        int run = (tid > 0) ? ssum[tid - 1] : 0;
        for (int i = 0; i < chunk; i++) {
            int b = tid * chunk + i;
            g_off_c[b] = run;
            run += slen_c[b] + 1;
        }
        if (tid == 255) { g_off_c[BC_] = ssum[255]; g_Mc[0] = ssum[255]; }
    }
    __syncthreads();
    for (int i = tid; i < BC_ * TC_; i += 256) {
        int b = i / TC_, t = i % TC_;
        if (t <= slen_c[b]) g_tok_c[g_off_c[b] + t] = tokens_c[i];
    }
    __syncthreads();

    if (tid < 64) hist[tid] = 0;
    __syncthreads();
    for (int i = tid; i < B_; i += 256) atomicAdd(&hist[slen_s[i]], 1);
    __syncthreads();
    if (tid <= TS_) {
        int c = 0;
        if (tid < 64) for (int k = tid; k < 64; k++) c += hist[k];
        g_cnt_s[tid] = (tid < TS_) ? c : 0;
    }
    if (tid == 0) {
        int run = 0;
        for (int k = 63; k >= 0; k--) { base[k] = run; run += hist[k]; }
    }
    __syncthreads();
    for (int i = tid; i < B_; i += 256) {
        int pos = atomicAdd(&base[slen_s[i]], 1);
        g_order_s[pos] = i;
    }
    {
        int s = (tid < B_) ? slen_s[tid] + 1 : 0;
        ssum[tid] = s;
        __syncthreads();
        for (int d = 1; d < 256; d <<= 1) {
            int v = (tid >= d) ? ssum[tid - d] : 0;
            __syncthreads();
            ssum[tid] += v;
            __syncthreads();
        }
        if (tid < B_) g_off_s[tid] = ssum[tid] - (slen_s[tid] + 1);
        if (tid == 255) { g_off_s[B_] = ssum[255]; g_Ms[0] = ssum[255]; }
    }
    __syncthreads();
    for (int i = tid; i < B_ * TS_; i += 256) {
        int b = i / TS_, t = i % TS_;
        if (t <= slen_s[b]) g_tok_s[g_off_s[b] + t] = tokens_s[i];
    }
}

// ---------------- bf16-split HMMA GEMM, fp32 in, split-on-stage ---------------
// Warp tile 32m x 64n (4m x 2n warps): 12 ldsm4 -> 48 mma per 16-k slice (4:1).
#define STRIDE_ 72
#define GTILE_  (128 * STRIDE_)
#define GEMM_SMEM (4 * GTILE_ * 2)

__global__ void __launch_bounds__(256, 2) gemm_mma(
    const float* __restrict__ A, const int* __restrict__ idx,
    const int* __restrict__ Mdev,
    const float* __restrict__ B, const float* __restrict__ bias,
    float* __restrict__ C, int M, int N)
{
    extern __shared__ __align__(16) __nv_bfloat16 smem[];
    const int Mq = Mdev ? *Mdev : M;
    const int bm = blockIdx.x * 128, bn = blockIdx.y * 128;
    if (bm >= Mq) return;
    const int tid = threadIdx.x, wid = tid >> 5, lane = tid & 31;
    const int warp_m = wid & 3, warp_n = wid >> 2;   // 4m x 2n

    __nv_bfloat16* sAh = smem;
    __nv_bfloat16* sAl = smem + GTILE_;
    __nv_bfloat16* sBh = smem + 2 * GTILE_;
    __nv_bfloat16* sBl = smem + 3 * GTILE_;
    const uint32_t uAh = smem_u32(sAh), uAl = smem_u32(sAl);
    const uint32_t uBh = smem_u32(sBh), uBl = smem_u32(sBl);

    const int fr = lane & 15;
    const int fc = (lane >> 4) * 8;
    const int arow_f = warp_m * 32 + fr;
    const int brow_f = warp_n * 64 + fr;

    float acc[2][8][4];
#pragma unroll
    for (int i = 0; i < 2; i++)
#pragma unroll
        for (int j = 0; j < 8; j++)
#pragma unroll
            for (int e = 0; e < 4; e++) acc[i][j][e] = 0.f;

    for (int kt = 0; kt < 4; kt++) {
        if (kt) __syncthreads();
#pragma unroll
        for (int i = 0; i < 4; i++) {
            const int id = i * 256 + tid;
            const int row = id >> 3, ch = id & 7;
            const int col = kt * 64 + ch * 8;
            int am = bm + row; if (am > Mq - 1) am = Mq - 1;
            const int ar = idx ? idx[am] : am;
            int br = bn + row; if (br > N - 1) br = N - 1;
            const int so = row * STRIDE_ + ch * 8;
            const float* ap = A + (size_t)ar * 256 + col;
            const float* bp = B + (size_t)br * 256 + col;
            split_store8(*(const float4*)ap, *(const float4*)(ap + 4),
                         sAh + so, sAl + so);
            split_store8(*(const float4*)bp, *(const float4*)(bp + 4),
                         sBh + so, sBl + so);
        }
        __syncthreads();

#pragma unroll
        for (int kk = 0; kk < 4; kk++) {
            const int col = kk * 16 + fc;
            uint32_t bh[4][4], bl[4][4], av[2][4];
#pragma unroll
            for (int p = 0; p < 4; p++) {
                const uint32_t off = 2u * ((brow_f + p * 16) * STRIDE_ + col);
                ldsm4(bh[p][0], bh[p][1], bh[p][2], bh[p][3], uBh + off);
                ldsm4(bl[p][0], bl[p][1], bl[p][2], bl[p][3], uBl + off);
            }
#pragma unroll
            for (int tm = 0; tm < 2; tm++) {
                const uint32_t off = 2u * ((arow_f + tm * 16) * STRIDE_ + col);
                ldsm4(av[tm][0], av[tm][1], av[tm][2], av[tm][3], uAh + off);
            }
#pragma unroll
            for (int tm = 0; tm < 2; tm++)
#pragma unroll
                for (int tn = 0; tn < 8; tn++) {
                    const int p = tn >> 1, o = tn & 1;
                    mma16816(acc[tm][tn], av[tm], bh[p][o], bh[p][o + 2]);
                    mma16816(acc[tm][tn], av[tm], bl[p][o], bl[p][o + 2]);
                }
#pragma unroll
            for (int tm = 0; tm < 2; tm++) {
                const uint32_t off = 2u * ((arow_f + tm * 16) * STRIDE_ + col);
                ldsm4(av[tm][0], av[tm][1], av[tm][2], av[tm][3], uAl + off);
            }
#pragma unroll
            for (int tm = 0; tm < 2; tm++)
#pragma unroll
                for (int tn = 0; tn < 8; tn++) {
                    const int p = tn >> 1, o = tn & 1;
                    mma16816(acc[tm][tn], av[tm], bh[p][o], bh[p][o + 2]);
                }
        }
    }

    const int mrow = bm + warp_m * 32 + (lane >> 2);
    const int ncol = bn + warp_n * 64 + (lane & 3) * 2;
#pragma unroll
    for (int tm = 0; tm < 2; tm++) {
#pragma unroll
        for (int half = 0; half < 2; half++) {
            const int m = mrow + tm * 16 + half * 8;
            if (m >= Mq) continue;
            float* crow = C + (size_t)m * N;
#pragma unroll
            for (int tn = 0; tn < 8; tn++) {
                const int n0 = ncol + tn * 8;
                const float v0 = acc[tm][tn][half * 2 + 0]
                               + (bias ? bias[n0] : 0.f);
                if (n0 + 1 < N) {
                    const float v1 = acc[tm][tn][half * 2 + 1]
                                   + (bias ? bias[n0 + 1] : 0.f);
                    *(float2*)(crow + n0) = make_float2(v0, v1);
                } else if (n0 < N) {
                    crow[n0] = v0;
                }
            }
        }
    }
}

// ---------------- persistent HMMA GRU (per-group barriers, smem gi/hold) ------
#define NBLK 144
#define CAT_RS 14
#define SHT_RS 4
#define WKT 6912              // 96*72 elems per kt
#define AKT 4608              // 64*72 elems per kt
#define HOLD_STR 36
#define GRUP_SMEM (184320 + 64 * 96 * 4 + 64 * HOLD_STR * 4)   // 218112 bytes

__global__ void __launch_bounds__(256, 1) gru_persist(
    const __nv_bfloat16* __restrict__ Whi_c, const __nv_bfloat16* __restrict__ Wlo_c,
    const float* __restrict__ bhh_c, const float* __restrict__ gi_c,
    const float* __restrict__ mask_c, float* __restrict__ gath_c,
    const int* __restrict__ slen_c,
    const __nv_bfloat16* __restrict__ Whi_s, const __nv_bfloat16* __restrict__ Wlo_s,
    const float* __restrict__ bhh_s, const float* __restrict__ gi_s,
    const float* __restrict__ mask_s, float* __restrict__ gath_s,
    const int* __restrict__ slen_s)
{
    extern __shared__ __align__(16) __nv_bfloat16 psm[];
    __nv_bfloat16* sWh = psm;                 // [4][96][72]
    __nv_bfloat16* sWl = psm + 4 * WKT;
    __nv_bfloat16* sAh = psm + 8 * WKT;       // [4][64][72]
    __nv_bfloat16* sAl = psm + 8 * WKT + 4 * AKT;
    float* sGi = (float*)(psm + 8 * WKT + 8 * AKT);   // [64][96]
    float* sHold = sGi + 64 * 96;                     // [64][36]
    const uint32_t uWh = smem_u32(sWh), uWl = smem_u32(sWl);
    const uint32_t uAh = smem_u32(sAh), uAl = smem_u32(sAl);

    const int blk = blockIdx.x;
    const int tid = threadIdx.x, wid = tid >> 5, lane = tid & 31;
    const int warp_m = wid & 3, warp_n = wid >> 2;   // 4m x 2n
    const int fr = lane & 15;
    const int fc = (lane >> 4) * 8;

    const bool isCat = blk < 112;
    const int local = isCat ? blk : (blk - 112);
    const int jsl = local & 7;            // 8 j-slices of 32
    const int rowset = local >> 3;        // cat 0..13, short 0..3
    const int rstride = isCat ? CAT_RS : SHT_RS;
    const int maxchunk = isCat ? 40 : 4;
    const int tmax = isCat ? TC_ : TS_;
    const int gid = isCat ? rowset : (CAT_RS + rowset);
    const int j0 = jsl * 32;

    const __nv_bfloat16* Whi = isCat ? Whi_c : Whi_s;
    const __nv_bfloat16* Wlo = isCat ? Wlo_c : Wlo_s;
    const float* bhh = isCat ? bhh_c : bhh_s;
    const float* gi = isCat ? gi_c : gi_s;
    const float* mask = isCat ? mask_c : mask_s;
    float* gath = isCat ? gath_c : gath_s;
    const int* slen = isCat ? slen_c : slen_s;
    const int* order = isCat ? g_order_c : g_order_s;
    const int* off = isCat ? g_off_c : g_off_s;
    const int* cnt = isCat ? g_cnt_c : g_cnt_s;
    const int maskT = isCat ? TC_ : TS_;
    float* hbufA = isCat ? g_hA : g_hsA;
    float* hbufB = isCat ? g_hB : g_hsB;

    // stage Whh slice ONCE: rows r = g*32 + j (96), all 4 kt chunks
#pragma unroll
    for (int i = 0; i < 12; i++) {
        const int id = i * 256 + tid;       // 0..3071
        const int ch = id & 7;
        const int kt = (id >> 3) & 3;
        const int r = id >> 5;              // 0..95
        const int grow = (r >> 5) * 256 + j0 + (r & 31);
        const int col = kt * 64 + ch * 8;
        const int so = kt * WKT + r * STRIDE_ + ch * 8;
        *(uint4*)(sWh + so) = *(const uint4*)(Whi + (size_t)grow * 256 + col);
        *(uint4*)(sWl + so) = *(const uint4*)(Wlo + (size_t)grow * 256 + col);
    }
    __syncthreads();

    for (int t = 0; t < tmax; t++) {
        const int active = cnt[t];
        const float* h_in = (t & 1) ? hbufB : hbufA;
        float* h_out = (t & 1) ? hbufA : hbufB;

        for (int c = rowset; c < maxchunk && c * 64 < active; c += rstride) {
            const int bm = c * 64;
            __syncthreads();   // protect smem from previous chunk's readers
            float acc[6][4];
#pragma unroll
            for (int j = 0; j < 6; j++)
#pragma unroll
                for (int e = 0; e < 4; e++) acc[j][e] = 0.f;

            // stage gi chunk into smem (always; h-independent, deep MLP)
#pragma unroll
            for (int i = 0; i < 24; i++) {
                const int id = i * 256 + tid;      // 0..6143
                const int sl = id / 96;
                const int q = id - sl * 96;        // 0..95: g*32 + jo
                const int g = q >> 5, jo = q & 31;
                int gs = bm + sl; if (gs > active - 1) gs = active - 1;
                const int b = order[gs];
                sGi[sl * 96 + q] =
                    __ldcg(gi + ((size_t)(off[b] + t)) * H3_ + g * 256 + j0 + jo);
            }

            if (t > 0) {
                // stage A: 64 rows x 256 k, fp32 -> bf16 hi/lo (+hold capture)
#pragma unroll
                for (int i = 0; i < 16; i++) {
                    const int id = i * 256 + tid;   // 0..4095
                    const int sl = id >> 6;          // 0..63
                    const int q = id & 63;
                    const int kt = q >> 4, c4 = q & 15;
                    int gs = bm + sl; if (gs > active - 1) gs = active - 1;
                    const int row = order[gs];
                    float4 v = __ldcg((const float4*)(h_in + (size_t)row * 256 + kt * 64 + c4 * 4));
                    const int k = kt * 64 + c4 * 4;
                    const int hk = k - j0;
                    if (hk >= 0 && hk < 32)
                        *(float4*)(sHold + sl * HOLD_STR + hk) = v;
                    __nv_bfloat16 h0 = __float2bfloat16(v.x);
                    __nv_bfloat16 h1 = __float2bfloat16(v.y);
                    __nv_bfloat16 h2 = __float2bfloat16(v.z);
                    __nv_bfloat16 h3 = __float2bfloat16(v.w);
                    const int so = kt * AKT + sl * STRIDE_ + c4 * 4;
                    *(__nv_bfloat162*)(sAh + so)     = __nv_bfloat162(h0, h1);
                    *(__nv_bfloat162*)(sAh + so + 2) = __nv_bfloat162(h2, h3);
                    *(__nv_bfloat162*)(sAl + so) =
                        __nv_bfloat162(__float2bfloat16(v.x - __bfloat162float(h0)),
                                       __float2bfloat16(v.y - __bfloat162float(h1)));
                    *(__nv_bfloat162*)(sAl + so + 2) =
                        __nv_bfloat162(__float2bfloat16(v.z - __bfloat162float(h2)),
                                       __float2bfloat16(v.w - __bfloat162float(h3)));
                }
            }
            __syncthreads();

            if (t > 0) {
#pragma unroll
                for (int kt = 0; kt < 4; kt++) {
#pragma unroll
                    for (int kk = 0; kk < 4; kk++) {
                        const int col = kk * 16 + fc;
                        uint32_t bh[3][4], bl[3][4], avh[4], avl[4];
#pragma unroll
                        for (int g = 0; g < 3; g++) {
                            const uint32_t o = 2u * (kt * WKT +
                                (g * 32 + warp_n * 16 + fr) * STRIDE_ + col);
                            ldsm4(bh[g][0], bh[g][1], bh[g][2], bh[g][3], uWh + o);
                            ldsm4(bl[g][0], bl[g][1], bl[g][2], bl[g][3], uWl + o);
                        }
                        {
                            const uint32_t o = 2u * (kt * AKT +
                                (warp_m * 16 + fr) * STRIDE_ + col);
                            ldsm4(avh[0], avh[1], avh[2], avh[3], uAh + o);
                            ldsm4(avl[0], avl[1], avl[2], avl[3], uAl + o);
                        }
#pragma unroll
                        for (int g = 0; g < 3; g++)
#pragma unroll
                            for (int o = 0; o < 2; o++) {
                                mma16816(acc[g * 2 + o], avh, bh[g][o], bh[g][o + 2]);
                                mma16816(acc[g * 2 + o], avh, bl[g][o], bl[g][o + 2]);
                                mma16816(acc[g * 2 + o], avl, bh[g][o], bh[g][o + 2]);
                            }
                    }
                }
            }

            // register/smem epilogue (no global reads)
#pragma unroll
            for (int o = 0; o < 2; o++)
#pragma unroll
                for (int e = 0; e < 4; e++) {
                    const int m_local = warp_m * 16 + (lane >> 2) + 8 * (e >> 1);
                    const int slot = bm + m_local;
                    if (slot >= active) continue;
                    const int b = order[slot];
                    const int j = warp_n * 16 + o * 8 + (lane & 3) * 2 + (e & 1);
                    const int jj = j0 + j;
                    const float gr = sGi[m_local * 96 + j];
                    const float gz = sGi[m_local * 96 + 32 + j];
                    const float gn = sGi[m_local * 96 + 64 + j];
                    const float hold = (t > 0) ? sHold[m_local * HOLD_STR + j] : 0.f;
                    const float r = fast_sigmoid(gr + acc[0 + o][e] + bhh[jj]);
                    const float z = fast_sigmoid(gz + acc[2 + o][e] + bhh[H_ + jj]);
                    const float n = fast_tanh(gn + r * (acc[4 + o][e] + bhh[2 * H_ + jj]));
                    const float hnew = (1.f - z) * n + z * hold;
                    h_out[(size_t)b * H_ + jj] = hnew;
                    if (slen[b] == t)
                        gath[(size_t)b * H_ + jj] =
                            hnew * mask[(size_t)b * maskT + t];
                }
        }

        if (t + 1 < tmax) group_barrier(gid, 8u * (unsigned)(t + 1));
    }
}

// ---------------- attention ----------------------------------------------------
__global__ void attention_kernel(const float* __restrict__ seq_cate,
                                 const float* __restrict__ out_short,
                                 const float* __restrict__ mask_seq,
                                 float* __restrict__ sum_cate)
{
    const int b = blockIdx.x;
    const int j = threadIdx.x;
    __shared__ float red[8];
    __shared__ float w[S_];
    const float os = out_short[(size_t)b * H_ + j];
    float sc[S_];
#pragma unroll
    for (int s = 0; s < S_; s++)
        sc[s] = seq_cate[(size_t)(b * S_ + s) * H_ + j];

    for (int s = 0; s < S_; s++) {
        float v = sc[s] * os;
#pragma unroll
        for (int off = 16; off; off >>= 1) v += __shfl_xor_sync(0xffffffffu, v, off);
        if ((j & 31) == 0) red[j >> 5] = v;
        __syncthreads();
        if (j == 0) {
            float x = 0.f;
#pragma unroll
            for (int q = 0; q < 8; q++) x += red[q];
            w[s] = x;
        }
        __syncthreads();
    }
    if (j == 0) {
        float mx = w[0];
        for (int s = 1; s < S_; s++) mx = fmaxf(mx, w[s]);
        float e[S_];
        float sum = 0.f;
        for (int s = 0; s < S_; s++) { e[s] = expf(w[s] - mx); sum += e[s]; }
        float s2 = 0.f;
        for (int s = 0; s < S_; s++) {
            e[s] = (e[s] / sum) * mask_seq[(size_t)b * S_ + s];
            s2 += e[s];
        }
        for (int s = 0; s < S_; s++) w[s] = e[s] / s2;
    }
    __syncthreads();
    float acc = 0.f;
#pragma unroll
    for (int s = 0; s < S_; s++) acc += w[s] * sc[s];
    sum_cate[(size_t)b * H_ + j] = acc;
}

// ---------------- FC -----------------------------------------------------------
__global__ void fc_kernel(const float* __restrict__ sum_cate,
                          const float* __restrict__ out_short,
                          const float* __restrict__ fcW,
                          const float* __restrict__ fcb,
                          float* __restrict__ fc_out)
{
    __shared__ float mix[16][2 * H_];
    const int b0 = blockIdx.x * 16;
    for (int idx = threadIdx.x; idx < 16 * 2 * H_; idx += 256) {
        const int bb = idx >> 9, k = idx & 511;
        mix[bb][k] = (k < H_) ? sum_cate[(size_t)(b0 + bb) * H_ + k]
                              : out_short[(size_t)(b0 + bb) * H_ + (k - H_)];
    }
    __syncthreads();
    const int i = threadIdx.x;
    const float* wrow = fcW + (size_t)i * (2 * H_);
    float acc[16];
#pragma unroll
    for (int bb = 0; bb < 16; bb++) acc[bb] = 0.f;
    for (int k = 0; k < 2 * H_; k++) {
        const float wv = wrow[k];
#pragma unroll
        for (int bb = 0; bb < 16; bb++) acc[bb] += wv * mix[bb][k];
    }
    const float bias = fcb[i];
#pragma unroll
    for (int bb = 0; bb < 16; bb++)
        fc_out[(size_t)(b0 + bb) * H_ + i] = acc[bb] + bias;
}

__global__ void write_targets(const int* __restrict__ tgt, float* __restrict__ out)
{
    out[threadIdx.x] = (float)tgt[threadIdx.x];
}

// ---------------- launcher ----------------------------------------------------
extern "C" void kernel_launch(void* const* d_in, const int* in_sizes, int n_in,
                              void* d_out, int out_size)
{
    const int*   in_cate       = (const int*)d_in[0];
    const float* mask_cate     = (const float*)d_in[1];
    const float* mask_cate_seq = (const float*)d_in[2];
    const int*   subseqLen     = (const int*)d_in[5];
    const int*   in_batch      = (const int*)d_in[7];
    const float* mask_b        = (const float*)d_in[8];
    const int*   seqLen        = (const int*)d_in[9];
    const int*   target        = (const int*)d_in[10];
    const float* emb           = (const float*)d_in[12];
    const float* Wih_c         = (const float*)d_in[13];
    const float* Whh_c         = (const float*)d_in[14];
    const float* bih_c         = (const float*)d_in[15];
    const float* bhh_c         = (const float*)d_in[16];
    const float* Wih_s         = (const float*)d_in[17];
    const float* Whh_s         = (const float*)d_in[18];
    const float* bih_s         = (const float*)d_in[19];
    const float* bhh_s         = (const float*)d_in[20];
    const float* fc_W          = (const float*)d_in[21];
    const float* fc_b          = (const float*)d_in[22];
    float* out = (float*)d_out;

    float *gi_c, *gi_s, *seqc, *osht, *sumc, *fco;
    int *tok_c, *tok_s, *Mc, *Ms;
    __nv_bfloat16 *whc_hi, *whc_lo, *whs_hi, *whs_lo;
    cudaGetSymbolAddress((void**)&gi_c, g_gi_c);
    cudaGetSymbolAddress((void**)&gi_s, g_gi_s);
    cudaGetSymbolAddress((void**)&seqc, g_seq_cate);
    cudaGetSymbolAddress((void**)&osht, g_out_short);
    cudaGetSymbolAddress((void**)&sumc, g_sum_cate);
    cudaGetSymbolAddress((void**)&fco,  g_fc_out);
    cudaGetSymbolAddress((void**)&tok_c, g_tok_c);
    cudaGetSymbolAddress((void**)&tok_s, g_tok_s);
    cudaGetSymbolAddress((void**)&Mc, g_Mc);
    cudaGetSymbolAddress((void**)&Ms, g_Ms);
    cudaGetSymbolAddress((void**)&whc_hi, g_whc_hi);
    cudaGetSymbolAddress((void**)&whc_lo, g_whc_lo);
    cudaGetSymbolAddress((void**)&whs_hi, g_whs_hi);
    cudaGetSymbolAddress((void**)&whs_lo, g_whs_lo);

    cudaFuncSetAttribute(gemm_mma, cudaFuncAttributeMaxDynamicSharedMemorySize,
                         GEMM_SMEM);
    cudaFuncSetAttribute(gru_persist,
                         cudaFuncAttributeMaxDynamicSharedMemorySize, GRUP_SMEM);

    // 0) prep + Whh bf16 splits
    prep_kernel<<<1, 256>>>(subseqLen, in_cate, seqLen, in_batch);
    split_kernel<<<192, 256>>>(Whh_c, whc_hi, whc_lo, H3_ * H_);
    split_kernel<<<192, 256>>>(Whh_s, whs_hi, whs_lo, H3_ * H_);

    // 1) input-gate GEMMs over compacted tokens (split-on-stage HMMA)
    gemm_mma<<<dim3((BC_ * TC_ + 127) / 128, H3_ / 128), 256, GEMM_SMEM>>>(
        emb, tok_c, Mc, Wih_c, bih_c, gi_c, BC_ * TC_, H3_);
    gemm_mma<<<dim3((B_ * TS_ + 127) / 128, H3_ / 128), 256, GEMM_SMEM>>>(
        emb, tok_s, Ms, Wih_s, bih_s, gi_s, B_ * TS_, H3_);

    // 2+3) persistent HMMA GRU: ONE launch, per-group barriers
    gru_persist<<<NBLK, 256, GRUP_SMEM>>>(
        whc_hi, whc_lo, bhh_c, gi_c, mask_cate, seqc, subseqLen,
        whs_hi, whs_lo, bhh_s, gi_s, mask_b, osht, seqLen);

    // 4) attention + 5) FC
    attention_kernel<<<B_, 256>>>(seqc, osht, mask_cate_seq, sumc);
    fc_kernel<<<B_ / 16, 256>>>(sumc, osht, fc_W, fc_b, fco);

    // 6) logits = fc_out @ emb^T (split-on-stage HMMA)
    gemm_mma<<<dim3(B_ / 128, (V_ + 127) / 128), 256, GEMM_SMEM>>>(
        fco, nullptr, nullptr, emb, nullptr, out, B_, V_);

    // 7) targets appended as float, if the output carries them
    if (out_size >= B_ * V_ + B_)
        write_targets<<<1, B_>>>(target, out + (size_t)B_ * V_);
}

// round 16
// speedup vs baseline: 6.0548x; 1.0731x over previous
#include <cuda_runtime.h>
#include <cuda_bf16.h>
#include <math.h>
#include <stdint.h>

// Problem constants (fixed by setup_inputs)
#define V_  100000
#define E_  256
#define H_  256
#define B_  256
#define S_  10
#define TC_ 20
#define TS_ 50
#define BC_ (B_ * S_)   // 2560
#define H3_ (3 * H_)    // 768

// ---------------- scratch (static device globals; no allocation) --------------
__device__ float g_gi_c[(size_t)BC_ * TC_ * H3_];
__device__ float g_gi_s[(size_t)B_ * TS_ * H3_];
__device__ float g_hA[BC_ * H_];
__device__ float g_hB[BC_ * H_];
__device__ float g_hsA[B_ * H_];
__device__ float g_hsB[B_ * H_];
__device__ float g_seq_cate[BC_ * H_];
__device__ float g_out_short[B_ * H_];
__device__ float g_sum_cate[B_ * H_];
__device__ float g_fc_out[B_ * H_];
__device__ int   g_order_c[BC_];
__device__ int   g_order_s[B_];
__device__ int   g_off_c[BC_ + 1];
__device__ int   g_off_s[B_ + 1];
__device__ int   g_tok_c[BC_ * TC_];
__device__ int   g_tok_s[B_ * TS_];
__device__ int   g_cnt_c[TS_ + 1];
__device__ int   g_cnt_s[TS_ + 1];
__device__ int   g_Mc[1];
__device__ int   g_Ms[1];
// pre-split Whh
__device__ __nv_bfloat16 g_whc_hi[H3_ * H_];
__device__ __nv_bfloat16 g_whc_lo[H3_ * H_];
__device__ __nv_bfloat16 g_whs_hi[H3_ * H_];
__device__ __nv_bfloat16 g_whs_lo[H3_ * H_];
// per-group barrier state (18 groups of 8 blocks), monotonic counters
#define NGRP 18
__device__ unsigned g_bar_cnt[NGRP];

// ---------------- helpers ------------------------------------------------------
__device__ __forceinline__ float fast_sigmoid(float x) {
    return 1.f / (1.f + __expf(-x));
}
__device__ __forceinline__ float fast_tanh(float x) {
    float ax = fabsf(x);
    float e = __expf(-2.f * ax);
    float t = __fdividef(1.f - e, 1.f + e);
    return copysignf(t, x);
}
__device__ __forceinline__ uint32_t smem_u32(const void* p) {
    uint32_t a;
    asm("{ .reg .u64 t; cvta.to.shared.u64 t, %1; cvt.u32.u64 %0, t; }"
        : "=r"(a) : "l"(p));
    return a;
}
__device__ __forceinline__ void ldsm4(uint32_t& r0, uint32_t& r1, uint32_t& r2,
                                      uint32_t& r3, uint32_t addr) {
    asm volatile("ldmatrix.sync.aligned.m8n8.x4.shared.b16 {%0,%1,%2,%3}, [%4];"
                 : "=r"(r0), "=r"(r1), "=r"(r2), "=r"(r3) : "r"(addr));
}
__device__ __forceinline__ void mma16816(float* d, const uint32_t* a,
                                         uint32_t b0, uint32_t b1) {
    asm volatile(
        "mma.sync.aligned.m16n8k16.row.col.f32.bf16.bf16.f32 "
        "{%0,%1,%2,%3}, {%4,%5,%6,%7}, {%8,%9}, {%0,%1,%2,%3};"
        : "+f"(d[0]), "+f"(d[1]), "+f"(d[2]), "+f"(d[3])
        : "r"(a[0]), "r"(a[1]), "r"(a[2]), "r"(a[3]), "r"(b0), "r"(b1));
}
__device__ __forceinline__ void split_store8(float4 a0, float4 a1,
                                             __nv_bfloat16* hi,
                                             __nv_bfloat16* lo) {
    float f[8] = {a0.x, a0.y, a0.z, a0.w, a1.x, a1.y, a1.z, a1.w};
    __nv_bfloat16 h[8], l[8];
#pragma unroll
    for (int e = 0; e < 8; e++) h[e] = __float2bfloat16(f[e]);
#pragma unroll
    for (int e = 0; e < 8; e++)
        l[e] = __float2bfloat16(f[e] - __bfloat162float(h[e]));
    __nv_bfloat162 hp[4] = {{h[0], h[1]}, {h[2], h[3]}, {h[4], h[5]}, {h[6], h[7]}};
    __nv_bfloat162 lp[4] = {{l[0], l[1]}, {l[2], l[3]}, {l[4], l[5]}, {l[6], l[7]}};
    *(uint4*)hi = *(uint4*)hp;
    *(uint4*)lo = *(uint4*)lp;
}
// monotonic-counter group barrier: step t has target nb*(t+1). VOLATILE poll.
__device__ __forceinline__ void group_barrier(int gid, unsigned tgt) {
    __threadfence();
    __syncthreads();
    if (threadIdx.x == 0) {
        atomicAdd(&g_bar_cnt[gid], 1u);
        volatile unsigned* p = &g_bar_cnt[gid];
        while (*p < tgt) { }
        __threadfence();
    }
    __syncthreads();
}

// ---------------- fp32 -> bf16 hi/lo split (Whh only) -------------------------
__global__ void split_kernel(const float* __restrict__ src,
                             __nv_bfloat16* __restrict__ hi,
                             __nv_bfloat16* __restrict__ lo, int n)
{
    int i = (blockIdx.x * 256 + threadIdx.x) * 4;
    const int stride = gridDim.x * 256 * 4;
    for (; i < n; i += stride) {
        float4 v = *(const float4*)(src + i);
        __nv_bfloat16 h0 = __float2bfloat16(v.x);
        __nv_bfloat16 h1 = __float2bfloat16(v.y);
        __nv_bfloat16 h2 = __float2bfloat16(v.z);
        __nv_bfloat16 h3 = __float2bfloat16(v.w);
        __nv_bfloat16 l0 = __float2bfloat16(v.x - __bfloat162float(h0));
        __nv_bfloat16 l1 = __float2bfloat16(v.y - __bfloat162float(h1));
        __nv_bfloat16 l2 = __float2bfloat16(v.z - __bfloat162float(h2));
        __nv_bfloat16 l3 = __float2bfloat16(v.w - __bfloat162float(h3));
        ((__nv_bfloat162*)(hi + i))[0] = __nv_bfloat162(h0, h1);
        ((__nv_bfloat162*)(hi + i))[1] = __nv_bfloat162(h2, h3);
        ((__nv_bfloat162*)(lo + i))[0] = __nv_bfloat162(l0, l1);
        ((__nv_bfloat162*)(lo + i))[1] = __nv_bfloat162(l2, l3);
    }
}

// ---------------- prep: counting sort desc, prefix offsets (1 block) ----------
__global__ void prep_kernel(const int* __restrict__ slen_c,
                            const int* __restrict__ slen_s)
{
    __shared__ int hist[64];
    __shared__ int base[64];
    __shared__ int ssum[256];
    const int tid = threadIdx.x;

    if (tid < NGRP) { g_bar_cnt[tid] = 0u; }   // barrier reset (graph-replay safe)

    if (tid < 64) hist[tid] = 0;
    __syncthreads();
    for (int i = tid; i < BC_; i += 256) atomicAdd(&hist[slen_c[i]], 1);
    __syncthreads();
    if (tid <= TS_) {
        int c = 0;
        if (tid < 64) for (int k = tid; k < 64; k++) c += hist[k];
        g_cnt_c[tid] = (tid < TC_) ? c : 0;
    }
    if (tid == 0) {
        int run = 0;
        for (int k = 63; k >= 0; k--) { base[k] = run; run += hist[k]; }
    }
    __syncthreads();
    for (int i = tid; i < BC_; i += 256) {
        int pos = atomicAdd(&base[slen_c[i]], 1);
        g_order_c[pos] = i;
    }
    {
        const int chunk = BC_ / 256;
        int s = 0;
        for (int i = 0; i < chunk; i++) s += slen_c[tid * chunk + i] + 1;
        ssum[tid] = s;
        __syncthreads();
        for (int d = 1; d < 256; d <<= 1) {
            int v = (tid >= d) ? ssum[tid - d] : 0;
            __syncthreads();
            ssum[tid] += v;
            __syncthreads();
        }
        int run = (tid > 0) ? ssum[tid - 1] : 0;
        for (int i = 0; i < chunk; i++) {
            int b = tid * chunk + i;
            g_off_c[b] = run;
            run += slen_c[b] + 1;
        }
        if (tid == 255) { g_off_c[BC_] = ssum[255]; g_Mc[0] = ssum[255]; }
    }
    __syncthreads();

    if (tid < 64) hist[tid] = 0;
    __syncthreads();
    for (int i = tid; i < B_; i += 256) atomicAdd(&hist[slen_s[i]], 1);
    __syncthreads();
    if (tid <= TS_) {
        int c = 0;
        if (tid < 64) for (int k = tid; k < 64; k++) c += hist[k];
        g_cnt_s[tid] = (tid < TS_) ? c : 0;
    }
    if (tid == 0) {
        int run = 0;
        for (int k = 63; k >= 0; k--) { base[k] = run; run += hist[k]; }
    }
    __syncthreads();
    for (int i = tid; i < B_; i += 256) {
        int pos = atomicAdd(&base[slen_s[i]], 1);
        g_order_s[pos] = i;
    }
    {
        int s = (tid < B_) ? slen_s[tid] + 1 : 0;
        ssum[tid] = s;
        __syncthreads();
        for (int d = 1; d < 256; d <<= 1) {
            int v = (tid >= d) ? ssum[tid - d] : 0;
            __syncthreads();
            ssum[tid] += v;
            __syncthreads();
        }
        if (tid < B_) g_off_s[tid] = ssum[tid] - (slen_s[tid] + 1);
        if (tid == 255) { g_off_s[B_] = ssum[255]; g_Ms[0] = ssum[255]; }
    }
}

// ---------------- token compaction (multi-block, after prep) ------------------
__global__ void compact_kernel(const int* __restrict__ slen_c,
                               const int* __restrict__ tokens_c,
                               const int* __restrict__ slen_s,
                               const int* __restrict__ tokens_s)
{
    const int i0 = blockIdx.x * 256 + threadIdx.x;
    const int stride = gridDim.x * 256;
    for (int i = i0; i < BC_ * TC_; i += stride) {
        const int b = i / TC_, t = i - b * TC_;
        if (t <= slen_c[b]) g_tok_c[g_off_c[b] + t] = tokens_c[i];
    }
    for (int i = i0; i < B_ * TS_; i += stride) {
        const int b = i / TS_, t = i - b * TS_;
        if (t <= slen_s[b]) g_tok_s[g_off_s[b] + t] = tokens_s[i];
    }
}

// ---------------- bf16-split HMMA GEMM, fp32 in, split-on-stage ---------------
// Warp tile 32m x 64n (4m x 2n warps). streamC: use __stcs for C (never re-read).
#define STRIDE_ 72
#define GTILE_  (128 * STRIDE_)
#define GEMM_SMEM (4 * GTILE_ * 2)

__global__ void __launch_bounds__(256, 2) gemm_mma(
    const float* __restrict__ A, const int* __restrict__ idx,
    const int* __restrict__ Mdev,
    const float* __restrict__ B, const float* __restrict__ bias,
    float* __restrict__ C, int M, int N, int streamC)
{
    extern __shared__ __align__(16) __nv_bfloat16 smem[];
    const int Mq = Mdev ? *Mdev : M;
    const int bm = blockIdx.x * 128, bn = blockIdx.y * 128;
    if (bm >= Mq) return;
    const int tid = threadIdx.x, wid = tid >> 5, lane = tid & 31;
    const int warp_m = wid & 3, warp_n = wid >> 2;   // 4m x 2n

    __nv_bfloat16* sAh = smem;
    __nv_bfloat16* sAl = smem + GTILE_;
    __nv_bfloat16* sBh = smem + 2 * GTILE_;
    __nv_bfloat16* sBl = smem + 3 * GTILE_;
    const uint32_t uAh = smem_u32(sAh), uAl = smem_u32(sAl);
    const uint32_t uBh = smem_u32(sBh), uBl = smem_u32(sBl);

    const int fr = lane & 15;
    const int fc = (lane >> 4) * 8;
    const int arow_f = warp_m * 32 + fr;
    const int brow_f = warp_n * 64 + fr;

    float acc[2][8][4];
#pragma unroll
    for (int i = 0; i < 2; i++)
#pragma unroll
        for (int j = 0; j < 8; j++)
#pragma unroll
            for (int e = 0; e < 4; e++) acc[i][j][e] = 0.f;

    for (int kt = 0; kt < 4; kt++) {
        if (kt) __syncthreads();
#pragma unroll
        for (int i = 0; i < 4; i++) {
            const int id = i * 256 + tid;
            const int row = id >> 3, ch = id & 7;
            const int col = kt * 64 + ch * 8;
            int am = bm + row; if (am > Mq - 1) am = Mq - 1;
            const int ar = idx ? idx[am] : am;
            int br = bn + row; if (br > N - 1) br = N - 1;
            const int so = row * STRIDE_ + ch * 8;
            const float* ap = A + (size_t)ar * 256 + col;
            const float* bp = B + (size_t)br * 256 + col;
            split_store8(*(const float4*)ap, *(const float4*)(ap + 4),
                         sAh + so, sAl + so);
            split_store8(*(const float4*)bp, *(const float4*)(bp + 4),
                         sBh + so, sBl + so);
        }
        __syncthreads();

#pragma unroll
        for (int kk = 0; kk < 4; kk++) {
            const int col = kk * 16 + fc;
            uint32_t bh[4][4], bl[4][4], av[2][4];
#pragma unroll
            for (int p = 0; p < 4; p++) {
                const uint32_t off = 2u * ((brow_f + p * 16) * STRIDE_ + col);
                ldsm4(bh[p][0], bh[p][1], bh[p][2], bh[p][3], uBh + off);
                ldsm4(bl[p][0], bl[p][1], bl[p][2], bl[p][3], uBl + off);
            }
#pragma unroll
            for (int tm = 0; tm < 2; tm++) {
                const uint32_t off = 2u * ((arow_f + tm * 16) * STRIDE_ + col);
                ldsm4(av[tm][0], av[tm][1], av[tm][2], av[tm][3], uAh + off);
            }
#pragma unroll
            for (int tm = 0; tm < 2; tm++)
#pragma unroll
                for (int tn = 0; tn < 8; tn++) {
                    const int p = tn >> 1, o = tn & 1;
                    mma16816(acc[tm][tn], av[tm], bh[p][o], bh[p][o + 2]);
                    mma16816(acc[tm][tn], av[tm], bl[p][o], bl[p][o + 2]);
                }
#pragma unroll
            for (int tm = 0; tm < 2; tm++) {
                const uint32_t off = 2u * ((arow_f + tm * 16) * STRIDE_ + col);
                ldsm4(av[tm][0], av[tm][1], av[tm][2], av[tm][3], uAl + off);
            }
#pragma unroll
            for (int tm = 0; tm < 2; tm++)
#pragma unroll
                for (int tn = 0; tn < 8; tn++) {
                    const int p = tn >> 1, o = tn & 1;
                    mma16816(acc[tm][tn], av[tm], bh[p][o], bh[p][o + 2]);
                }
        }
    }

    const int mrow = bm + warp_m * 32 + (lane >> 2);
    const int ncol = bn + warp_n * 64 + (lane & 3) * 2;
#pragma unroll
    for (int tm = 0; tm < 2; tm++) {
#pragma unroll
        for (int half = 0; half < 2; half++) {
            const int m = mrow + tm * 16 + half * 8;
            if (m >= Mq) continue;
            float* crow = C + (size_t)m * N;
#pragma unroll
            for (int tn = 0; tn < 8; tn++) {
                const int n0 = ncol + tn * 8;
                const float v0 = acc[tm][tn][half * 2 + 0]
                               + (bias ? bias[n0] : 0.f);
                if (n0 + 1 < N) {
                    const float v1 = acc[tm][tn][half * 2 + 1]
                                   + (bias ? bias[n0 + 1] : 0.f);
                    if (streamC)
                        __stcs((float2*)(crow + n0), make_float2(v0, v1));
                    else
                        *(float2*)(crow + n0) = make_float2(v0, v1);
                } else if (n0 < N) {
                    if (streamC) __stcs(crow + n0, v0);
                    else         crow[n0] = v0;
                }
            }
        }
    }
}

// ---------------- persistent HMMA GRU (per-group barriers, smem gi/hold) ------
#define NBLK 144
#define CAT_RS 14
#define SHT_RS 4
#define WKT 6912              // 96*72 elems per kt
#define AKT 4608              // 64*72 elems per kt
#define HOLD_STR 36
#define GRUP_SMEM (184320 + 64 * 96 * 4 + 64 * HOLD_STR * 4)   // 218112 bytes

__global__ void __launch_bounds__(256, 1) gru_persist(
    const __nv_bfloat16* __restrict__ Whi_c, const __nv_bfloat16* __restrict__ Wlo_c,
    const float* __restrict__ bhh_c, const float* __restrict__ gi_c,
    const float* __restrict__ mask_c, float* __restrict__ gath_c,
    const int* __restrict__ slen_c,
    const __nv_bfloat16* __restrict__ Whi_s, const __nv_bfloat16* __restrict__ Wlo_s,
    const float* __restrict__ bhh_s, const float* __restrict__ gi_s,
    const float* __restrict__ mask_s, float* __restrict__ gath_s,
    const int* __restrict__ slen_s)
{
    extern __shared__ __align__(16) __nv_bfloat16 psm[];
    __nv_bfloat16* sWh = psm;                 // [4][96][72]
    __nv_bfloat16* sWl = psm + 4 * WKT;
    __nv_bfloat16* sAh = psm + 8 * WKT;       // [4][64][72]
    __nv_bfloat16* sAl = psm + 8 * WKT + 4 * AKT;
    float* sGi = (float*)(psm + 8 * WKT + 8 * AKT);   // [64][96]
    float* sHold = sGi + 64 * 96;                     // [64][36]
    const uint32_t uWh = smem_u32(sWh), uWl = smem_u32(sWl);
    const uint32_t uAh = smem_u32(sAh), uAl = smem_u32(sAl);

    const int blk = blockIdx.x;
    const int tid = threadIdx.x, wid = tid >> 5, lane = tid & 31;
    const int warp_m = wid & 3, warp_n = wid >> 2;   // 4m x 2n
    const int fr = lane & 15;
    const int fc = (lane >> 4) * 8;

    const bool isCat = blk < 112;
    const int local = isCat ? blk : (blk - 112);
    const int jsl = local & 7;            // 8 j-slices of 32
    const int rowset = local >> 3;        // cat 0..13, short 0..3
    const int rstride = isCat ? CAT_RS : SHT_RS;
    const int maxchunk = isCat ? 40 : 4;
    const int tmax = isCat ? TC_ : TS_;
    const int gid = isCat ? rowset : (CAT_RS + rowset);
    const int j0 = jsl * 32;

    const __nv_bfloat16* Whi = isCat ? Whi_c : Whi_s;
    const __nv_bfloat16* Wlo = isCat ? Wlo_c : Wlo_s;
    const float* bhh = isCat ? bhh_c : bhh_s;
    const float* gi = isCat ? gi_c : gi_s;
    const float* mask = isCat ? mask_c : mask_s;
    float* gath = isCat ? gath_c : gath_s;
    const int* slen = isCat ? slen_c : slen_s;
    const int* order = isCat ? g_order_c : g_order_s;
    const int* off = isCat ? g_off_c : g_off_s;
    const int* cnt = isCat ? g_cnt_c : g_cnt_s;
    const int maskT = isCat ? TC_ : TS_;
    float* hbufA = isCat ? g_hA : g_hsA;
    float* hbufB = isCat ? g_hB : g_hsB;

    // stage Whh slice ONCE: rows r = g*32 + j (96), all 4 kt chunks
#pragma unroll
    for (int i = 0; i < 12; i++) {
        const int id = i * 256 + tid;       // 0..3071
        const int ch = id & 7;
        const int kt = (id >> 3) & 3;
        const int r = id >> 5;              // 0..95
        const int grow = (r >> 5) * 256 + j0 + (r & 31);
        const int col = kt * 64 + ch * 8;
        const int so = kt * WKT + r * STRIDE_ + ch * 8;
        *(uint4*)(sWh + so) = *(const uint4*)(Whi + (size_t)grow * 256 + col);
        *(uint4*)(sWl + so) = *(const uint4*)(Wlo + (size_t)grow * 256 + col);
    }
    __syncthreads();

    for (int t = 0; t < tmax; t++) {
        const int active = cnt[t];
        const float* h_in = (t & 1) ? hbufB : hbufA;
        float* h_out = (t & 1) ? hbufA : hbufB;

        for (int c = rowset; c < maxchunk && c * 64 < active; c += rstride) {
            const int bm = c * 64;
            __syncthreads();   // protect smem from previous chunk's readers
            float acc[6][4];
#pragma unroll
            for (int j = 0; j < 6; j++)
#pragma unroll
                for (int e = 0; e < 4; e++) acc[j][e] = 0.f;

            // stage gi chunk into smem (always; h-independent, deep MLP)
#pragma unroll
            for (int i = 0; i < 24; i++) {
                const int id = i * 256 + tid;      // 0..6143
                const int sl = id / 96;
                const int q = id - sl * 96;        // 0..95: g*32 + jo
                const int g = q >> 5, jo = q & 31;
                int gs = bm + sl; if (gs > active - 1) gs = active - 1;
                const int b = order[gs];
                sGi[sl * 96 + q] =
                    __ldcg(gi + ((size_t)(off[b] + t)) * H3_ + g * 256 + j0 + jo);
            }

            if (t > 0) {
                // stage A: 64 rows x 256 k, fp32 -> bf16 hi/lo (+hold capture)
#pragma unroll
                for (int i = 0; i < 16; i++) {
                    const int id = i * 256 + tid;   // 0..4095
                    const int sl = id >> 6;          // 0..63
                    const int q = id & 63;
                    const int kt = q >> 4, c4 = q & 15;
                    int gs = bm + sl; if (gs > active - 1) gs = active - 1;
                    const int row = order[gs];
                    float4 v = __ldcg((const float4*)(h_in + (size_t)row * 256 + kt * 64 + c4 * 4));
                    const int k = kt * 64 + c4 * 4;
                    const int hk = k - j0;
                    if (hk >= 0 && hk < 32)
                        *(float4*)(sHold + sl * HOLD_STR + hk) = v;
                    __nv_bfloat16 h0 = __float2bfloat16(v.x);
                    __nv_bfloat16 h1 = __float2bfloat16(v.y);
                    __nv_bfloat16 h2 = __float2bfloat16(v.z);
                    __nv_bfloat16 h3 = __float2bfloat16(v.w);
                    const int so = kt * AKT + sl * STRIDE_ + c4 * 4;
                    *(__nv_bfloat162*)(sAh + so)     = __nv_bfloat162(h0, h1);
                    *(__nv_bfloat162*)(sAh + so + 2) = __nv_bfloat162(h2, h3);
                    *(__nv_bfloat162*)(sAl + so) =
                        __nv_bfloat162(__float2bfloat16(v.x - __bfloat162float(h0)),
                                       __float2bfloat16(v.y - __bfloat162float(h1)));
                    *(__nv_bfloat162*)(sAl + so + 2) =
                        __nv_bfloat162(__float2bfloat16(v.z - __bfloat162float(h2)),
                                       __float2bfloat16(v.w - __bfloat162float(h3)));
                }
            }
            __syncthreads();

            if (t > 0) {
#pragma unroll
                for (int kt = 0; kt < 4; kt++) {
#pragma unroll
                    for (int kk = 0; kk < 4; kk++) {
                        const int col = kk * 16 + fc;
                        uint32_t bh[3][4], bl[3][4], avh[4], avl[4];
#pragma unroll
                        for (int g = 0; g < 3; g++) {
                            const uint32_t o = 2u * (kt * WKT +
                                (g * 32 + warp_n * 16 + fr) * STRIDE_ + col);
                            ldsm4(bh[g][0], bh[g][1], bh[g][2], bh[g][3], uWh + o);
                            ldsm4(bl[g][0], bl[g][1], bl[g][2], bl[g][3], uWl + o);
                        }
                        {
                            const uint32_t o = 2u * (kt * AKT +
                                (warp_m * 16 + fr) * STRIDE_ + col);
                            ldsm4(avh[0], avh[1], avh[2], avh[3], uAh + o);
                            ldsm4(avl[0], avl[1], avl[2], avl[3], uAl + o);
                        }
#pragma unroll
                        for (int g = 0; g < 3; g++)
#pragma unroll
                            for (int o = 0; o < 2; o++) {
                                mma16816(acc[g * 2 + o], avh, bh[g][o], bh[g][o + 2]);
                                mma16816(acc[g * 2 + o], avh, bl[g][o], bl[g][o + 2]);
                                mma16816(acc[g * 2 + o], avl, bh[g][o], bh[g][o + 2]);
                            }
                    }
                }
            }

            // register/smem epilogue (no global reads)
#pragma unroll
            for (int o = 0; o < 2; o++)
#pragma unroll
                for (int e = 0; e < 4; e++) {
                    const int m_local = warp_m * 16 + (lane >> 2) + 8 * (e >> 1);
                    const int slot = bm + m_local;
                    if (slot >= active) continue;
                    const int b = order[slot];
                    const int j = warp_n * 16 + o * 8 + (lane & 3) * 2 + (e & 1);
                    const int jj = j0 + j;
                    const float gr = sGi[m_local * 96 + j];
                    const float gz = sGi[m_local * 96 + 32 + j];
                    const float gn = sGi[m_local * 96 + 64 + j];
                    const float hold = (t > 0) ? sHold[m_local * HOLD_STR + j] : 0.f;
                    const float r = fast_sigmoid(gr + acc[0 + o][e] + bhh[jj]);
                    const float z = fast_sigmoid(gz + acc[2 + o][e] + bhh[H_ + jj]);
                    const float n = fast_tanh(gn + r * (acc[4 + o][e] + bhh[2 * H_ + jj]));
                    const float hnew = (1.f - z) * n + z * hold;
                    h_out[(size_t)b * H_ + jj] = hnew;
                    if (slen[b] == t)
                        gath[(size_t)b * H_ + jj] =
                            hnew * mask[(size_t)b * maskT + t];
                }
        }

        if (t + 1 < tmax) group_barrier(gid, 8u * (unsigned)(t + 1));
    }
}

// ---------------- attention ----------------------------------------------------
__global__ void attention_kernel(const float* __restrict__ seq_cate,
                                 const float* __restrict__ out_short,
                                 const float* __restrict__ mask_seq,
                                 float* __restrict__ sum_cate)
{
    const int b = blockIdx.x;
    const int j = threadIdx.x;
    __shared__ float red[8];
    __shared__ float w[S_];
    const float os = out_short[(size_t)b * H_ + j];
    float sc[S_];
#pragma unroll
    for (int s = 0; s < S_; s++)
        sc[s] = seq_cate[(size_t)(b * S_ + s) * H_ + j];

    for (int s = 0; s < S_; s++) {
        float v = sc[s] * os;
#pragma unroll
        for (int off = 16; off; off >>= 1) v += __shfl_xor_sync(0xffffffffu, v, off);
        if ((j & 31) == 0) red[j >> 5] = v;
        __syncthreads();
        if (j == 0) {
            float x = 0.f;
#pragma unroll
            for (int q = 0; q < 8; q++) x += red[q];
            w[s] = x;
        }
        __syncthreads();
    }
    if (j == 0) {
        float mx = w[0];
        for (int s = 1; s < S_; s++) mx = fmaxf(mx, w[s]);
        float e[S_];
        float sum = 0.f;
        for (int s = 0; s < S_; s++) { e[s] = expf(w[s] - mx); sum += e[s]; }
        float s2 = 0.f;
        for (int s = 0; s < S_; s++) {
            e[s] = (e[s] / sum) * mask_seq[(size_t)b * S_ + s];
            s2 += e[s];
        }
        for (int s = 0; s < S_; s++) w[s] = e[s] / s2;
    }
    __syncthreads();
    float acc = 0.f;
#pragma unroll
    for (int s = 0; s < S_; s++) acc += w[s] * sc[s];
    sum_cate[(size_t)b * H_ + j] = acc;
}

// ---------------- FC -----------------------------------------------------------
__global__ void fc_kernel(const float* __restrict__ sum_cate,
                          const float* __restrict__ out_short,
                          const float* __restrict__ fcW,
                          const float* __restrict__ fcb,
                          float* __restrict__ fc_out)
{
    __shared__ float mix[16][2 * H_];
    const int b0 = blockIdx.x * 16;
    for (int idx = threadIdx.x; idx < 16 * 2 * H_; idx += 256) {
        const int bb = idx >> 9, k = idx & 511;
        mix[bb][k] = (k < H_) ? sum_cate[(size_t)(b0 + bb) * H_ + k]
                              : out_short[(size_t)(b0 + bb) * H_ + (k - H_)];
    }
    __syncthreads();
    const int i = threadIdx.x;
    const float* wrow = fcW + (size_t)i * (2 * H_);
    float acc[16];
#pragma unroll
    for (int bb = 0; bb < 16; bb++) acc[bb] = 0.f;
    for (int k = 0; k < 2 * H_; k++) {
        const float wv = wrow[k];
#pragma unroll
        for (int bb = 0; bb < 16; bb++) acc[bb] += wv * mix[bb][k];
    }
    const float bias = fcb[i];
#pragma unroll
    for (int bb = 0; bb < 16; bb++)
        fc_out[(size_t)(b0 + bb) * H_ + i] = acc[bb] + bias;
}

__global__ void write_targets(const int* __restrict__ tgt, float* __restrict__ out)
{
    out[threadIdx.x] = (float)tgt[threadIdx.x];
}

// ---------------- launcher ----------------------------------------------------
extern "C" void kernel_launch(void* const* d_in, const int* in_sizes, int n_in,
                              void* d_out, int out_size)
{
    const int*   in_cate       = (const int*)d_in[0];
    const float* mask_cate     = (const float*)d_in[1];
    const float* mask_cate_seq = (const float*)d_in[2];
    const int*   subseqLen     = (const int*)d_in[5];
    const int*   in_batch      = (const int*)d_in[7];
    const float* mask_b        = (const float*)d_in[8];
    const int*   seqLen        = (const int*)d_in[9];
    const int*   target        = (const int*)d_in[10];
    const float* emb           = (const float*)d_in[12];
    const float* Wih_c         = (const float*)d_in[13];
    const float* Whh_c         = (const float*)d_in[14];
    const float* bih_c         = (const float*)d_in[15];
    const float* bhh_c         = (const float*)d_in[16];
    const float* Wih_s         = (const float*)d_in[17];
    const float* Whh_s         = (const float*)d_in[18];
    const float* bih_s         = (const float*)d_in[19];
    const float* bhh_s         = (const float*)d_in[20];
    const float* fc_W          = (const float*)d_in[21];
    const float* fc_b          = (const float*)d_in[22];
    float* out = (float*)d_out;

    float *gi_c, *gi_s, *seqc, *osht, *sumc, *fco;
    int *tok_c, *tok_s, *Mc, *Ms;
    __nv_bfloat16 *whc_hi, *whc_lo, *whs_hi, *whs_lo;
    cudaGetSymbolAddress((void**)&gi_c, g_gi_c);
    cudaGetSymbolAddress((void**)&gi_s, g_gi_s);
    cudaGetSymbolAddress((void**)&seqc, g_seq_cate);
    cudaGetSymbolAddress((void**)&osht, g_out_short);
    cudaGetSymbolAddress((void**)&sumc, g_sum_cate);
    cudaGetSymbolAddress((void**)&fco,  g_fc_out);
    cudaGetSymbolAddress((void**)&tok_c, g_tok_c);
    cudaGetSymbolAddress((void**)&tok_s, g_tok_s);
    cudaGetSymbolAddress((void**)&Mc, g_Mc);
    cudaGetSymbolAddress((void**)&Ms, g_Ms);
    cudaGetSymbolAddress((void**)&whc_hi, g_whc_hi);
    cudaGetSymbolAddress((void**)&whc_lo, g_whc_lo);
    cudaGetSymbolAddress((void**)&whs_hi, g_whs_hi);
    cudaGetSymbolAddress((void**)&whs_lo, g_whs_lo);

    cudaFuncSetAttribute(gemm_mma, cudaFuncAttributeMaxDynamicSharedMemorySize,
                         GEMM_SMEM);
    cudaFuncSetAttribute(gru_persist,
                         cudaFuncAttributeMaxDynamicSharedMemorySize, GRUP_SMEM);

    // 0) prep (sort + offsets) -> token compaction (parallel) + Whh splits
    prep_kernel<<<1, 256>>>(subseqLen, seqLen);
    compact_kernel<<<64, 256>>>(subseqLen, in_cate, seqLen, in_batch);
    split_kernel<<<192, 256>>>(Whh_c, whc_hi, whc_lo, H3_ * H_);
    split_kernel<<<192, 256>>>(Whh_s, whs_hi, whs_lo, H3_ * H_);

    // 1) input-gate GEMMs over compacted tokens (split-on-stage HMMA)
    gemm_mma<<<dim3((BC_ * TC_ + 127) / 128, H3_ / 128), 256, GEMM_SMEM>>>(
        emb, tok_c, Mc, Wih_c, bih_c, gi_c, BC_ * TC_, H3_, 0);
    gemm_mma<<<dim3((B_ * TS_ + 127) / 128, H3_ / 128), 256, GEMM_SMEM>>>(
        emb, tok_s, Ms, Wih_s, bih_s, gi_s, B_ * TS_, H3_, 0);

    // 2+3) persistent HMMA GRU: ONE launch, per-group barriers
    gru_persist<<<NBLK, 256, GRUP_SMEM>>>(
        whc_hi, whc_lo, bhh_c, gi_c, mask_cate, seqc, subseqLen,
        whs_hi, whs_lo, bhh_s, gi_s, mask_b, osht, seqLen);

    // 4) attention + 5) FC
    attention_kernel<<<B_, 256>>>(seqc, osht, mask_cate_seq, sumc);
    fc_kernel<<<B_ / 16, 256>>>(sumc, osht, fc_W, fc_b, fco);

    // 6) logits = fc_out @ emb^T (streaming C stores: out is never re-read)
    gemm_mma<<<dim3(B_ / 128, (V_ + 127) / 128), 256, GEMM_SMEM>>>(
        fco, nullptr, nullptr, emb, nullptr, out, B_, V_, 1);

    // 7) targets appended as float, if the output carries them
    if (out_size >= B_ * V_ + B_)
        write_targets<<<1, B_>>>(target, out + (size_t)B_ * V_);
}